// round 1
// baseline (speedup 1.0000x reference)
#include <cuda_runtime.h>

#define BB   16
#define NPTS 4096
#define MPTS 1024
#define CH   256      // C1 = C2 = H = 256
#define K1   512
#define BN_EPS 1e-5f

// ---------------- scratch (device globals; no allocation allowed) ----------------
__device__ float g_kft[(size_t)BB * MPTS * CH];          // known_feats transposed (b, m, c)
__device__ float g_T  [(size_t)BB * NPTS * CH];          // interpolated feats, (b, i, c) layout
__device__ float g_Y1 [(size_t)BB * CH * NPTS];          // raw conv1 output (pre-BN)
__device__ float g_Y2 [(size_t)BB * CH * NPTS];          // raw conv2 output (pre-BN)
__device__ int   g_idx3[BB * NPTS * 3];
__device__ float g_w3  [BB * NPTS * 3];
__device__ float g_scale1[CH], g_shift1[CH], g_scale2[CH], g_shift2[CH];

// ---------------- packed f32x2 helpers ----------------
__device__ __forceinline__ void fma2(unsigned long long &d, unsigned long long a, unsigned long long b) {
    asm("fma.rn.f32x2 %0, %1, %2, %0;" : "+l"(d) : "l"(a), "l"(b));
}
__device__ __forceinline__ unsigned long long dup2(float x) {
    unsigned long long r;
    asm("mov.b64 %0, {%1, %1};" : "=l"(r) : "f"(x));
    return r;
}
__device__ __forceinline__ float2 unpk(unsigned long long v) {
    float2 f;
    asm("mov.b64 {%0, %1}, %2;" : "=f"(f.x), "=f"(f.y) : "l"(v));
    return f;
}

// ---------------- kernel 1: 3-NN + interpolation weights ----------------
__global__ void nn_kernel(const float* __restrict__ unknown, const float* __restrict__ known) {
    __shared__ float skx[MPTS], sky[MPTS], skz[MPTS];
    int b = blockIdx.y;
    const float* kb = known + (size_t)b * MPTS * 3;
    for (int j = threadIdx.x; j < MPTS; j += blockDim.x) {
        skx[j] = kb[j * 3 + 0];
        sky[j] = kb[j * 3 + 1];
        skz[j] = kb[j * 3 + 2];
    }
    __syncthreads();

    int i = blockIdx.x * blockDim.x + threadIdx.x;
    const float* u = unknown + ((size_t)b * NPTS + i) * 3;
    float ux = u[0], uy = u[1], uz = u[2];

    float b0 = 3.4e38f, b1 = 3.4e38f, b2 = 3.4e38f;
    int i0 = 0, i1 = 0, i2 = 0;
    #pragma unroll 4
    for (int j = 0; j < MPTS; j++) {
        float dx = ux - skx[j], dy = uy - sky[j], dz = uz - skz[j];
        float d = dx * dx + dy * dy + dz * dz;
        if (d < b2) {                 // strict < keeps lower index on ties (matches stable top_k)
            if (d < b1) {
                if (d < b0) { b2 = b1; i2 = i1; b1 = b0; i1 = i0; b0 = d; i0 = j; }
                else        { b2 = b1; i2 = i1; b1 = d;  i1 = j; }
            } else          { b2 = d;  i2 = j; }
        }
    }
    float r0 = 1.0f / (b0 + 1e-8f);
    float r1 = 1.0f / (b1 + 1e-8f);
    float r2 = 1.0f / (b2 + 1e-8f);
    float inv = 1.0f / (r0 + r1 + r2);
    size_t base = ((size_t)b * NPTS + i) * 3;
    g_idx3[base + 0] = i0; g_idx3[base + 1] = i1; g_idx3[base + 2] = i2;
    g_w3[base + 0] = r0 * inv; g_w3[base + 1] = r1 * inv; g_w3[base + 2] = r2 * inv;
}

// ---------------- kernel 2: transpose known_feats (b,c,m) -> (b,m,c) ----------------
__global__ void transpose_kernel(const float* __restrict__ kf) {
    __shared__ float tile[32][33];
    int b = blockIdx.z;
    int c0 = blockIdx.y * 32, j0 = blockIdx.x * 32;
    const float* src = kf + (size_t)b * CH * MPTS;
    for (int r = threadIdx.y; r < 32; r += 8)
        tile[r][threadIdx.x] = src[(size_t)(c0 + r) * MPTS + j0 + threadIdx.x];
    __syncthreads();
    float* dst = g_kft + (size_t)b * MPTS * CH;
    for (int r = threadIdx.y; r < 32; r += 8)
        dst[(size_t)(j0 + r) * CH + c0 + threadIdx.x] = tile[threadIdx.x][r];
}

// ---------------- kernel 3: coalesced 3-NN gather -> T (b, i, c) ----------------
__global__ void gather_kernel() {
    int b = blockIdx.y;
    int i = blockIdx.x * 4 + (threadIdx.x >> 6);
    int c = (threadIdx.x & 63) * 4;
    size_t base = ((size_t)b * NPTS + i) * 3;
    int j0 = g_idx3[base + 0], j1 = g_idx3[base + 1], j2 = g_idx3[base + 2];
    float w0 = g_w3[base + 0], w1 = g_w3[base + 1], w2 = g_w3[base + 2];
    const float* kb = g_kft + (size_t)b * MPTS * CH;
    float4 a = *(const float4*)(kb + (size_t)j0 * CH + c);
    float4 d = *(const float4*)(kb + (size_t)j1 * CH + c);
    float4 e = *(const float4*)(kb + (size_t)j2 * CH + c);
    float4 o;
    o.x = w0 * a.x + w1 * d.x + w2 * e.x;
    o.y = w0 * a.y + w1 * d.y + w2 * e.y;
    o.z = w0 * a.z + w1 * d.z + w2 * e.z;
    o.w = w0 * a.w + w1 * d.w + w2 * e.w;
    *(float4*)(g_T + ((size_t)b * NPTS + i) * CH + c) = o;
}

// ---------------- GEMM1: Y1 = W1 @ [interp ; unknow_feats] ----------------
// tile 128(o) x 128(i) x 16(k); 256 threads, each computes 8x8 via packed f32x2
__global__ __launch_bounds__(256) void gemm1_kernel(const float* __restrict__ W1,
                                                    const float* __restrict__ uf) {
    __shared__ float As[16][128];
    __shared__ float Bs[16][128];
    int b = blockIdx.z, o0 = blockIdx.y * 128, i0 = blockIdx.x * 128;
    int tid = threadIdx.x;
    int tx = tid & 15, ty = tid >> 4;

    unsigned long long acc[8][4];
    #pragma unroll
    for (int p = 0; p < 8; p++)
        #pragma unroll
        for (int q = 0; q < 4; q++) acc[p][q] = 0ull;

    for (int k0 = 0; k0 < K1; k0 += 16) {
        // A tile: W1[o0+row][k0 + q*4 ..], scatter-transpose into As[k][o]
        #pragma unroll
        for (int it = 0; it < 2; it++) {
            int e = tid + it * 256;
            int row = e >> 2, q = e & 3;
            float4 v = *(const float4*)(W1 + (size_t)(o0 + row) * K1 + k0 + q * 4);
            As[q * 4 + 0][row] = v.x; As[q * 4 + 1][row] = v.y;
            As[q * 4 + 2][row] = v.z; As[q * 4 + 3][row] = v.w;
        }
        if (k0 < 256) {
            // interp half: T is (b, i, k) -> k contiguous
            #pragma unroll
            for (int it = 0; it < 2; it++) {
                int e = tid + it * 256;
                int row = e >> 2, q = e & 3;
                float4 v = *(const float4*)(g_T + ((size_t)b * NPTS + i0 + row) * CH + k0 + q * 4);
                Bs[q * 4 + 0][row] = v.x; Bs[q * 4 + 1][row] = v.y;
                Bs[q * 4 + 2][row] = v.z; Bs[q * 4 + 3][row] = v.w;
            }
        } else {
            // unknow_feats half: (b, c, i) -> i contiguous
            #pragma unroll
            for (int it = 0; it < 2; it++) {
                int e = tid + it * 256;
                int kr = e >> 5, iq = e & 31;
                float4 v = *(const float4*)(uf + ((size_t)b * CH + (k0 - 256 + kr)) * NPTS + i0 + iq * 4);
                *(float4*)&Bs[kr][iq * 4] = v;
            }
        }
        __syncthreads();
        #pragma unroll
        for (int kk = 0; kk < 16; kk++) {
            float4 a0 = *(const float4*)&As[kk][ty * 8];
            float4 a1 = *(const float4*)&As[kk][ty * 8 + 4];
            ulonglong2 bv0 = *(const ulonglong2*)&Bs[kk][tx * 8];
            ulonglong2 bv1 = *(const ulonglong2*)&Bs[kk][tx * 8 + 4];
            unsigned long long aa[8];
            aa[0] = dup2(a0.x); aa[1] = dup2(a0.y); aa[2] = dup2(a0.z); aa[3] = dup2(a0.w);
            aa[4] = dup2(a1.x); aa[5] = dup2(a1.y); aa[6] = dup2(a1.z); aa[7] = dup2(a1.w);
            unsigned long long bb[4] = { bv0.x, bv0.y, bv1.x, bv1.y };
            #pragma unroll
            for (int p = 0; p < 8; p++)
                #pragma unroll
                for (int q = 0; q < 4; q++) fma2(acc[p][q], aa[p], bb[q]);
        }
        __syncthreads();
    }
    #pragma unroll
    for (int p = 0; p < 8; p++) {
        float2 v0 = unpk(acc[p][0]), v1 = unpk(acc[p][1]);
        float2 v2 = unpk(acc[p][2]), v3 = unpk(acc[p][3]);
        float* dst = g_Y1 + ((size_t)b * CH + o0 + ty * 8 + p) * NPTS + i0 + tx * 8;
        *(float4*)(dst + 0) = make_float4(v0.x, v0.y, v1.x, v1.y);
        *(float4*)(dst + 4) = make_float4(v2.x, v2.y, v3.x, v3.y);
    }
}

// ---------------- GEMM2: Y2 = W2 @ relu(BN1(Y1)); BN1 fused into operand load ----------------
__global__ __launch_bounds__(256) void gemm2_kernel(const float* __restrict__ W2) {
    __shared__ float As[16][128];
    __shared__ float Bs[16][128];
    int b = blockIdx.z, o0 = blockIdx.y * 128, i0 = blockIdx.x * 128;
    int tid = threadIdx.x;
    int tx = tid & 15, ty = tid >> 4;

    unsigned long long acc[8][4];
    #pragma unroll
    for (int p = 0; p < 8; p++)
        #pragma unroll
        for (int q = 0; q < 4; q++) acc[p][q] = 0ull;

    for (int k0 = 0; k0 < CH; k0 += 16) {
        #pragma unroll
        for (int it = 0; it < 2; it++) {
            int e = tid + it * 256;
            int row = e >> 2, q = e & 3;
            float4 v = *(const float4*)(W2 + (size_t)(o0 + row) * CH + k0 + q * 4);
            As[q * 4 + 0][row] = v.x; As[q * 4 + 1][row] = v.y;
            As[q * 4 + 2][row] = v.z; As[q * 4 + 3][row] = v.w;
        }
        #pragma unroll
        for (int it = 0; it < 2; it++) {
            int e = tid + it * 256;
            int kr = e >> 5, iq = e & 31;
            int c = k0 + kr;
            float s = g_scale1[c], t = g_shift1[c];
            float4 v = *(const float4*)(g_Y1 + ((size_t)b * CH + c) * NPTS + i0 + iq * 4);
            v.x = fmaxf(fmaf(v.x, s, t), 0.f);
            v.y = fmaxf(fmaf(v.y, s, t), 0.f);
            v.z = fmaxf(fmaf(v.z, s, t), 0.f);
            v.w = fmaxf(fmaf(v.w, s, t), 0.f);
            *(float4*)&Bs[kr][iq * 4] = v;
        }
        __syncthreads();
        #pragma unroll
        for (int kk = 0; kk < 16; kk++) {
            float4 a0 = *(const float4*)&As[kk][ty * 8];
            float4 a1 = *(const float4*)&As[kk][ty * 8 + 4];
            ulonglong2 bv0 = *(const ulonglong2*)&Bs[kk][tx * 8];
            ulonglong2 bv1 = *(const ulonglong2*)&Bs[kk][tx * 8 + 4];
            unsigned long long aa[8];
            aa[0] = dup2(a0.x); aa[1] = dup2(a0.y); aa[2] = dup2(a0.z); aa[3] = dup2(a0.w);
            aa[4] = dup2(a1.x); aa[5] = dup2(a1.y); aa[6] = dup2(a1.z); aa[7] = dup2(a1.w);
            unsigned long long bb[4] = { bv0.x, bv0.y, bv1.x, bv1.y };
            #pragma unroll
            for (int p = 0; p < 8; p++)
                #pragma unroll
                for (int q = 0; q < 4; q++) fma2(acc[p][q], aa[p], bb[q]);
        }
        __syncthreads();
    }
    #pragma unroll
    for (int p = 0; p < 8; p++) {
        float2 v0 = unpk(acc[p][0]), v1 = unpk(acc[p][1]);
        float2 v2 = unpk(acc[p][2]), v3 = unpk(acc[p][3]);
        float* dst = g_Y2 + ((size_t)b * CH + o0 + ty * 8 + p) * NPTS + i0 + tx * 8;
        *(float4*)(dst + 0) = make_float4(v0.x, v0.y, v1.x, v1.y);
        *(float4*)(dst + 4) = make_float4(v2.x, v2.y, v3.x, v3.y);
    }
}

// ---------------- batch stats -> scale/shift (one block per channel) ----------------
__global__ void stats_kernel(const float* __restrict__ gamma, const float* __restrict__ beta,
                             int which) {
    const float* Y = (which == 1) ? g_Y1 : g_Y2;
    int o = blockIdx.x;
    int tid = threadIdx.x;
    float s = 0.f, sq = 0.f;
    for (int b = 0; b < BB; b++) {
        const float4* p = (const float4*)(Y + ((size_t)b * CH + o) * NPTS);
        for (int i = tid; i < NPTS / 4; i += blockDim.x) {
            float4 v = p[i];
            s  += v.x + v.y + v.z + v.w;
            sq += v.x * v.x + v.y * v.y + v.z * v.z + v.w * v.w;
        }
    }
    __shared__ float rs[256], rq[256];
    rs[tid] = s; rq[tid] = sq;
    __syncthreads();
    for (int st = 128; st > 0; st >>= 1) {
        if (tid < st) { rs[tid] += rs[tid + st]; rq[tid] += rq[tid + st]; }
        __syncthreads();
    }
    if (tid == 0) {
        float inv  = 1.0f / (float)(BB * NPTS);
        float mean = rs[0] * inv;
        float var  = rq[0] * inv - mean * mean;
        float sc   = gamma[o] * rsqrtf(var + BN_EPS);
        float sh   = beta[o] - mean * sc;
        if (which == 1) { g_scale1[o] = sc; g_shift1[o] = sh; }
        else            { g_scale2[o] = sc; g_shift2[o] = sh; }
    }
}

// ---------------- final BN2 + ReLU ----------------
__global__ void out_kernel(float* __restrict__ out) {
    size_t q = (size_t)blockIdx.x * blockDim.x + threadIdx.x;
    size_t e = q * 4;
    int o = (int)((e >> 12) & (CH - 1));   // (e / 4096) % 256
    float s = g_scale2[o], t = g_shift2[o];
    float4 v = ((const float4*)g_Y2)[q];
    v.x = fmaxf(fmaf(v.x, s, t), 0.f);
    v.y = fmaxf(fmaf(v.y, s, t), 0.f);
    v.z = fmaxf(fmaf(v.z, s, t), 0.f);
    v.w = fmaxf(fmaf(v.w, s, t), 0.f);
    ((float4*)out)[q] = v;
}

// ---------------- launch ----------------
extern "C" void kernel_launch(void* const* d_in, const int* in_sizes, int n_in,
                              void* d_out, int out_size) {
    const float* unknown = (const float*)d_in[0];
    const float* known   = (const float*)d_in[1];
    const float* uf      = (const float*)d_in[2];
    const float* kf      = (const float*)d_in[3];
    const float* W1      = (const float*)d_in[4];
    const float* g1      = (const float*)d_in[5];
    const float* be1     = (const float*)d_in[6];
    const float* W2      = (const float*)d_in[7];
    const float* g2      = (const float*)d_in[8];
    const float* be2     = (const float*)d_in[9];
    float* out = (float*)d_out;

    nn_kernel<<<dim3(NPTS / 256, BB), 256>>>(unknown, known);
    transpose_kernel<<<dim3(MPTS / 32, CH / 32, BB), dim3(32, 8)>>>(kf);
    gather_kernel<<<dim3(NPTS / 4, BB), 256>>>();
    gemm1_kernel<<<dim3(NPTS / 128, CH / 128, BB), 256>>>(W1, uf);
    stats_kernel<<<CH, 256>>>(g1, be1, 1);
    gemm2_kernel<<<dim3(NPTS / 128, CH / 128, BB), 256>>>(W2);
    stats_kernel<<<CH, 256>>>(g2, be2, 2);
    out_kernel<<<(BB * CH * NPTS / 4) / 256, 256>>>(out);
}

// round 3
// speedup vs baseline: 2.8260x; 2.8260x over previous
#include <cuda_runtime.h>
#include <cstdint>

#define BB   16
#define NPTS 4096
#define MPTS 1024
#define CH   256
#define K1   512
#define TK   32
#define BN_EPS 1e-5f

// ---------------- scratch ----------------
__device__ __align__(16) float g_kft[(size_t)BB * MPTS * CH];   // known_feats^T (b,m,c)
__device__ __align__(16) float g_X  [(size_t)BB * NPTS * K1];   // [interp | uf^T] (b,i,k) tf32-rounded
__device__ __align__(16) float g_Y1t[(size_t)BB * NPTS * CH];   // conv1 raw out (b,i,o)
__device__ __align__(16) float g_Y2t[(size_t)BB * NPTS * CH];   // conv2 raw out (b,i,o)
__device__ __align__(16) float g_W1r[CH * K1];
__device__ __align__(16) float g_W2r[CH * CH];
__device__ int   g_idx3[BB * NPTS * 3];
__device__ float g_w3[BB * NPTS * 3];
__device__ float g_sum1[CH], g_sq1[CH], g_sum2[CH], g_sq2[CH];
__device__ float g_scale1[CH], g_shift1[CH], g_scale2[CH], g_shift2[CH];

// ---------------- helpers ----------------
__device__ __forceinline__ float rtf32(float x) {
    float r;
    asm("cvt.rna.tf32.f32 %0, %1;" : "=f"(r) : "f"(x));
    return r;
}
__device__ __forceinline__ void cp16(uint32_t saddr, const void* g) {
    asm volatile("cp.async.ca.shared.global [%0], [%1], 16;" :: "r"(saddr), "l"(g));
}
__device__ __forceinline__ uint32_t smem_u32(const void* p) {
    uint32_t a;
    asm("{ .reg .u64 t; cvta.to.shared.u64 t, %1; cvt.u32.u64 %0, t; }" : "=r"(a) : "l"(p));
    return a;
}
__device__ __forceinline__ void mma_tf32(float* d, const uint32_t* a, const uint32_t* b) {
    asm volatile(
        "mma.sync.aligned.m16n8k8.row.col.f32.tf32.tf32.f32 "
        "{%0,%1,%2,%3}, {%4,%5,%6,%7}, {%8,%9}, {%0,%1,%2,%3};"
        : "+f"(d[0]), "+f"(d[1]), "+f"(d[2]), "+f"(d[3])
        : "r"(a[0]), "r"(a[1]), "r"(a[2]), "r"(a[3]), "r"(b[0]), "r"(b[1]));
}

// ---------------- kernel: 3-NN + weights ----------------
__global__ void nn_kernel(const float* __restrict__ unknown, const float* __restrict__ known) {
    __shared__ float skx[MPTS], sky[MPTS], skz[MPTS];
    int b = blockIdx.y;
    const float* kb = known + (size_t)b * MPTS * 3;
    for (int j = threadIdx.x; j < MPTS; j += blockDim.x) {
        skx[j] = kb[j * 3 + 0]; sky[j] = kb[j * 3 + 1]; skz[j] = kb[j * 3 + 2];
    }
    __syncthreads();
    int i = blockIdx.x * blockDim.x + threadIdx.x;
    const float* u = unknown + ((size_t)b * NPTS + i) * 3;
    float ux = u[0], uy = u[1], uz = u[2];
    float b0 = 3.4e38f, b1 = 3.4e38f, b2 = 3.4e38f;
    int i0 = 0, i1 = 0, i2 = 0;
    #pragma unroll 4
    for (int j = 0; j < MPTS; j++) {
        float dx = ux - skx[j], dy = uy - sky[j], dz = uz - skz[j];
        float d = dx * dx + dy * dy + dz * dz;
        if (d < b2) {
            if (d < b1) {
                if (d < b0) { b2 = b1; i2 = i1; b1 = b0; i1 = i0; b0 = d; i0 = j; }
                else        { b2 = b1; i2 = i1; b1 = d;  i1 = j; }
            } else          { b2 = d;  i2 = j; }
        }
    }
    float r0 = 1.0f / (b0 + 1e-8f), r1 = 1.0f / (b1 + 1e-8f), r2 = 1.0f / (b2 + 1e-8f);
    float inv = 1.0f / (r0 + r1 + r2);
    size_t base = ((size_t)b * NPTS + i) * 3;
    g_idx3[base] = i0; g_idx3[base + 1] = i1; g_idx3[base + 2] = i2;
    g_w3[base] = r0 * inv; g_w3[base + 1] = r1 * inv; g_w3[base + 2] = r2 * inv;
}

// ---------------- transpose known_feats (b,c,m)->(b,m,c) ----------------
__global__ void kft_kernel(const float* __restrict__ kf) {
    __shared__ float tile[32][33];
    int b = blockIdx.z, c0 = blockIdx.y * 32, j0 = blockIdx.x * 32;
    const float* src = kf + (size_t)b * CH * MPTS;
    for (int r = threadIdx.y; r < 32; r += 8)
        tile[r][threadIdx.x] = src[(size_t)(c0 + r) * MPTS + j0 + threadIdx.x];
    __syncthreads();
    float* dst = g_kft + (size_t)b * MPTS * CH;
    for (int r = threadIdx.y; r < 32; r += 8)
        dst[(size_t)(j0 + r) * CH + c0 + threadIdx.x] = tile[threadIdx.x][r];
}

// ---------------- gather -> X[:, :, 0:256] ----------------
__global__ void gather_kernel() {
    int b = blockIdx.y;
    int i = blockIdx.x * 4 + (threadIdx.x >> 6);
    int c = (threadIdx.x & 63) * 4;
    size_t base = ((size_t)b * NPTS + i) * 3;
    int j0 = g_idx3[base], j1 = g_idx3[base + 1], j2 = g_idx3[base + 2];
    float w0 = g_w3[base], w1 = g_w3[base + 1], w2 = g_w3[base + 2];
    const float* kb = g_kft + (size_t)b * MPTS * CH;
    float4 a = *(const float4*)(kb + (size_t)j0 * CH + c);
    float4 d = *(const float4*)(kb + (size_t)j1 * CH + c);
    float4 e = *(const float4*)(kb + (size_t)j2 * CH + c);
    float4 o;
    o.x = rtf32(w0 * a.x + w1 * d.x + w2 * e.x);
    o.y = rtf32(w0 * a.y + w1 * d.y + w2 * e.y);
    o.z = rtf32(w0 * a.z + w1 * d.z + w2 * e.z);
    o.w = rtf32(w0 * a.w + w1 * d.w + w2 * e.w);
    *(float4*)(g_X + ((size_t)b * NPTS + i) * K1 + c) = o;
}

// ---------------- uf transpose -> X[:, :, 256:512] ----------------
__global__ void uft_kernel(const float* __restrict__ uf) {
    __shared__ float tile[32][33];
    int b = blockIdx.z, c0 = blockIdx.y * 32, i0 = blockIdx.x * 32;
    const float* src = uf + (size_t)b * CH * NPTS;
    for (int r = threadIdx.y; r < 32; r += 8)
        tile[r][threadIdx.x] = src[(size_t)(c0 + r) * NPTS + i0 + threadIdx.x];
    __syncthreads();
    float* dst = g_X + (size_t)b * NPTS * K1;
    for (int r = threadIdx.y; r < 32; r += 8)
        dst[(size_t)(i0 + r) * K1 + 256 + c0 + threadIdx.x] = rtf32(tile[threadIdx.x][r]);
}

// ---------------- weight rounding ----------------
__global__ void wround_kernel(const float* __restrict__ w, float* __restrict__ dst) {
    int i = blockIdx.x * 256 + threadIdx.x;
    dst[i] = rtf32(w[i]);
}
__global__ void zero_kernel() {
    int o = threadIdx.x;
    g_sum1[o] = 0.f; g_sq1[o] = 0.f; g_sum2[o] = 0.f; g_sq2[o] = 0.f;
}

// ---------------- mma.sync tf32 GEMM ----------------
// D(b,i,o) = A(b,i,k) @ B(o,k)^T.  128x128 block tile, 8 warps of 64x32.
// smem: per stage As[128][36] + Bs[128][36] floats; 2 stages.
#define AS_STRIDE 36
#define TILE_F (128 * AS_STRIDE)          // 4608 floats
#define STAGE_F (2 * TILE_F)              // A + B
#define GEMM_SMEM (2 * STAGE_F * 4)       // 73728 bytes

template<int KDIM, bool FUSE>
__global__ void __launch_bounds__(256) gemm_mma(const float* __restrict__ Ag,
                                                const float* __restrict__ Bg,
                                                float* __restrict__ Dg) {
    extern __shared__ float sm[];
    const int tid = threadIdx.x;
    const int wid = tid >> 5, l = tid & 31;
    const int wy = wid >> 2, wx = wid & 3;
    const int b = blockIdx.z;
    const int i0 = blockIdx.x * 128, o0 = blockIdx.y * 128;
    const int g = l >> 2, c4 = l & 3;

    const float* Abase = Ag + ((size_t)b * NPTS + i0) * KDIM;
    const float* Bbase = Bg + (size_t)o0 * KDIM;

    float acc[4][4][4];
    #pragma unroll
    for (int mi = 0; mi < 4; mi++)
        #pragma unroll
        for (int ni = 0; ni < 4; ni++)
            #pragma unroll
            for (int t = 0; t < 4; t++) acc[mi][ni][t] = 0.f;

    const int rb = tid >> 3, qq = tid & 7;
    const uint32_t sbase = smem_u32(sm);
    const int NC = KDIM / TK;

    // ---- chunk loader ----
    auto load_chunk = [&](int c, int s) {
        int k0 = c * TK;
        uint32_t offA = s * STAGE_F, offB = offA + TILE_F;
        #pragma unroll
        for (int it = 0; it < 4; it++) {
            int r = rb + it * 32;
            uint32_t so = (r * AS_STRIDE + qq * 4) * 4;
            if (FUSE) {
                float4 v = *(const float4*)(Abase + (size_t)r * KDIM + k0 + qq * 4);
                float4 sc = *(const float4*)(g_scale1 + k0 + qq * 4);
                float4 sh = *(const float4*)(g_shift1 + k0 + qq * 4);
                v.x = rtf32(fmaxf(fmaf(v.x, sc.x, sh.x), 0.f));
                v.y = rtf32(fmaxf(fmaf(v.y, sc.y, sh.y), 0.f));
                v.z = rtf32(fmaxf(fmaf(v.z, sc.z, sh.z), 0.f));
                v.w = rtf32(fmaxf(fmaf(v.w, sc.w, sh.w), 0.f));
                *(float4*)(sm + offA + r * AS_STRIDE + qq * 4) = v;
            } else {
                cp16(sbase + offA * 4 + so, Abase + (size_t)r * KDIM + k0 + qq * 4);
            }
            cp16(sbase + offB * 4 + so, Bbase + (size_t)r * KDIM + k0 + qq * 4);
        }
        asm volatile("cp.async.commit_group;" ::: "memory");
    };

    load_chunk(0, 0);
    for (int c = 0; c < NC; c++) {
        if (c + 1 < NC) {
            load_chunk(c + 1, (c + 1) & 1);
            asm volatile("cp.async.wait_group 1;" ::: "memory");
        } else {
            asm volatile("cp.async.wait_group 0;" ::: "memory");
        }
        __syncthreads();

        const float* As = sm + (c & 1) * STAGE_F;
        const float* Bs = As + TILE_F;
        #pragma unroll
        for (int kk8 = 0; kk8 < 4; kk8++) {
            int kk = kk8 * 8;
            uint32_t af[4][4], bf[4][2];
            #pragma unroll
            for (int mi = 0; mi < 4; mi++) {
                const uint32_t* p = (const uint32_t*)(As + (wy * 64 + mi * 16 + g) * AS_STRIDE + kk + c4);
                af[mi][0] = p[0];
                af[mi][1] = p[8 * AS_STRIDE];
                af[mi][2] = p[4];
                af[mi][3] = p[8 * AS_STRIDE + 4];
            }
            #pragma unroll
            for (int ni = 0; ni < 4; ni++) {
                const uint32_t* p = (const uint32_t*)(Bs + (wx * 32 + ni * 8 + g) * AS_STRIDE + kk + c4);
                bf[ni][0] = p[0];
                bf[ni][1] = p[4];
            }
            #pragma unroll
            for (int mi = 0; mi < 4; mi++)
                #pragma unroll
                for (int ni = 0; ni < 4; ni++)
                    mma_tf32(acc[mi][ni], af[mi], bf[ni]);
        }
        __syncthreads();
    }

    // ---- epilogue: D(b,i,o), float2 per thread ----
    #pragma unroll
    for (int mi = 0; mi < 4; mi++) {
        int row0 = i0 + wy * 64 + mi * 16 + g;
        #pragma unroll
        for (int ni = 0; ni < 4; ni++) {
            int col = o0 + wx * 32 + ni * 8 + 2 * c4;
            *(float2*)(Dg + ((size_t)b * NPTS + row0) * CH + col) =
                make_float2(acc[mi][ni][0], acc[mi][ni][1]);
            *(float2*)(Dg + ((size_t)b * NPTS + row0 + 8) * CH + col) =
                make_float2(acc[mi][ni][2], acc[mi][ni][3]);
        }
    }
}

// ---------------- column stats over (b,i,o) layout ----------------
__global__ void stats_col_kernel(const float* __restrict__ Y, float* __restrict__ sums,
                                 float* __restrict__ sqs) {
    int b = blockIdx.y, i0 = blockIdx.x * 256;
    int o = threadIdx.x;
    const float* p = Y + ((size_t)b * NPTS + i0) * CH + o;
    float s = 0.f, sq = 0.f;
    #pragma unroll 4
    for (int r = 0; r < 256; r++) {
        float v = p[(size_t)r * CH];
        s += v; sq += v * v;
    }
    atomicAdd(&sums[o], s);
    atomicAdd(&sqs[o], sq);
}

__global__ void finalize_kernel(const float* __restrict__ ga, const float* __restrict__ be,
                                const float* __restrict__ sums, const float* __restrict__ sqs,
                                float* __restrict__ scale, float* __restrict__ shift) {
    int o = threadIdx.x;
    float inv = 1.0f / (float)(BB * NPTS);
    float mean = sums[o] * inv;
    float var = sqs[o] * inv - mean * mean;
    float sc = ga[o] * rsqrtf(var + BN_EPS);
    scale[o] = sc;
    shift[o] = be[o] - mean * sc;
}

// ---------------- final: BN2 + ReLU + transpose (b,i,o) -> (b,o,i) ----------------
__global__ void out_kernel(float* __restrict__ out) {
    __shared__ float tile[32][33];
    int b = blockIdx.z, i0 = blockIdx.x * 32, o0 = blockIdx.y * 32;
    const float* src = g_Y2t + (size_t)b * NPTS * CH;
    for (int r = threadIdx.y; r < 32; r += 8)
        tile[r][threadIdx.x] = src[(size_t)(i0 + r) * CH + o0 + threadIdx.x];
    __syncthreads();
    float* dst = out + (size_t)b * CH * NPTS;
    for (int r = threadIdx.y; r < 32; r += 8) {
        int o = o0 + r;
        float v = fmaxf(fmaf(tile[threadIdx.x][r], g_scale2[o], g_shift2[o]), 0.f);
        dst[(size_t)o * NPTS + i0 + threadIdx.x] = v;
    }
}

// ---------------- launch ----------------
extern "C" void kernel_launch(void* const* d_in, const int* in_sizes, int n_in,
                              void* d_out, int out_size) {
    const float* unknown = (const float*)d_in[0];
    const float* known   = (const float*)d_in[1];
    const float* uf      = (const float*)d_in[2];
    const float* kf      = (const float*)d_in[3];
    const float* W1      = (const float*)d_in[4];
    const float* g1      = (const float*)d_in[5];
    const float* be1     = (const float*)d_in[6];
    const float* W2      = (const float*)d_in[7];
    const float* g2      = (const float*)d_in[8];
    const float* be2     = (const float*)d_in[9];
    float* out = (float*)d_out;

    cudaFuncSetAttribute(gemm_mma<K1, false>, cudaFuncAttributeMaxDynamicSharedMemorySize, GEMM_SMEM);
    cudaFuncSetAttribute(gemm_mma<CH, true>,  cudaFuncAttributeMaxDynamicSharedMemorySize, GEMM_SMEM);

    float *pX, *pW1, *pW2, *pY1, *pY2;
    float *ps1, *pq1, *ps2, *pq2, *psc1, *psh1, *psc2, *psh2;
    cudaGetSymbolAddress((void**)&pX, g_X);
    cudaGetSymbolAddress((void**)&pW1, g_W1r);
    cudaGetSymbolAddress((void**)&pW2, g_W2r);
    cudaGetSymbolAddress((void**)&pY1, g_Y1t);
    cudaGetSymbolAddress((void**)&pY2, g_Y2t);
    cudaGetSymbolAddress((void**)&ps1, g_sum1);
    cudaGetSymbolAddress((void**)&pq1, g_sq1);
    cudaGetSymbolAddress((void**)&ps2, g_sum2);
    cudaGetSymbolAddress((void**)&pq2, g_sq2);
    cudaGetSymbolAddress((void**)&psc1, g_scale1);
    cudaGetSymbolAddress((void**)&psh1, g_shift1);
    cudaGetSymbolAddress((void**)&psc2, g_scale2);
    cudaGetSymbolAddress((void**)&psh2, g_shift2);

    zero_kernel<<<1, 256>>>();
    nn_kernel<<<dim3(NPTS / 256, BB), 256>>>(unknown, known);
    kft_kernel<<<dim3(MPTS / 32, CH / 32, BB), dim3(32, 8)>>>(kf);
    gather_kernel<<<dim3(NPTS / 4, BB), 256>>>();
    uft_kernel<<<dim3(NPTS / 32, CH / 32, BB), dim3(32, 8)>>>(uf);
    wround_kernel<<<CH * K1 / 256, 256>>>(W1, pW1);
    wround_kernel<<<CH * CH / 256, 256>>>(W2, pW2);

    gemm_mma<K1, false><<<dim3(NPTS / 128, CH / 128, BB), 256, GEMM_SMEM>>>(pX, pW1, pY1);
    stats_col_kernel<<<dim3(NPTS / 256, BB), 256>>>(pY1, ps1, pq1);
    finalize_kernel<<<1, 256>>>(g1, be1, ps1, pq1, psc1, psh1);

    gemm_mma<CH, true><<<dim3(NPTS / 128, CH / 128, BB), 256, GEMM_SMEM>>>(pY1, pW2, pY2);
    stats_col_kernel<<<dim3(NPTS / 256, BB), 256>>>(pY2, ps2, pq2);
    finalize_kernel<<<1, 256>>>(g2, be2, ps2, pq2, psc2, psh2);

    out_kernel<<<dim3(NPTS / 32, CH / 32, BB), dim3(32, 8)>>>(out);
}

// round 4
// speedup vs baseline: 3.0998x; 1.0969x over previous
#include <cuda_runtime.h>
#include <cuda_fp16.h>
#include <cstdint>

#define BB   16
#define NPTS 4096
#define MPTS 1024
#define CH   256
#define K1   512
#define BN_EPS 1e-5f

// ---------------- scratch ----------------
__device__ __align__(16) float  g_kft[(size_t)BB * MPTS * CH];   // known_feats^T (b,m,c) f32
__device__ __align__(16) __half g_Xh[(size_t)BB * NPTS * K1];    // [interp | uf^T] (b,i,k) half
__device__ __align__(16) float  g_Y1t[(size_t)BB * NPTS * CH];   // conv1 raw out (b,i,o) f32
__device__ __align__(16) __half g_H  [(size_t)BB * NPTS * CH];   // relu(bn1(Y1)) half (b,i,o)
__device__ __align__(16) float  g_Y2t[(size_t)BB * NPTS * CH];   // conv2 raw out (b,i,o) f32
__device__ __align__(16) __half g_W1h[CH * K1];
__device__ __align__(16) __half g_W2h[CH * CH];
__device__ int   g_idx3[BB * NPTS * 3];
__device__ float g_w3[BB * NPTS * 3];
__device__ float g_sum1[CH], g_sq1[CH], g_sum2[CH], g_sq2[CH];
__device__ float g_scale1[CH], g_shift1[CH], g_scale2[CH], g_shift2[CH];

// ---------------- helpers ----------------
__device__ __forceinline__ void cp16(uint32_t saddr, const void* g) {
    asm volatile("cp.async.ca.shared.global [%0], [%1], 16;" :: "r"(saddr), "l"(g));
}
__device__ __forceinline__ uint32_t smem_u32(const void* p) {
    uint32_t a;
    asm("{ .reg .u64 t; cvta.to.shared.u64 t, %1; cvt.u32.u64 %0, t; }" : "=r"(a) : "l"(p));
    return a;
}
__device__ __forceinline__ void ldm_x4(uint32_t* r, uint32_t addr) {
    asm volatile("ldmatrix.sync.aligned.m8n8.x4.shared.b16 {%0,%1,%2,%3}, [%4];"
                 : "=r"(r[0]), "=r"(r[1]), "=r"(r[2]), "=r"(r[3]) : "r"(addr));
}
__device__ __forceinline__ void mma_f16(float* d, const uint32_t* a, const uint32_t* b) {
    asm volatile(
        "mma.sync.aligned.m16n8k16.row.col.f32.f16.f16.f32 "
        "{%0,%1,%2,%3}, {%4,%5,%6,%7}, {%8,%9}, {%0,%1,%2,%3};"
        : "+f"(d[0]), "+f"(d[1]), "+f"(d[2]), "+f"(d[3])
        : "r"(a[0]), "r"(a[1]), "r"(a[2]), "r"(a[3]), "r"(b[0]), "r"(b[1]));
}

// ---------------- kernel: 3-NN + weights ----------------
__global__ void nn_kernel(const float* __restrict__ unknown, const float* __restrict__ known) {
    __shared__ float skx[MPTS], sky[MPTS], skz[MPTS];
    int b = blockIdx.y;
    const float* kb = known + (size_t)b * MPTS * 3;
    for (int j = threadIdx.x; j < MPTS; j += blockDim.x) {
        skx[j] = kb[j * 3 + 0]; sky[j] = kb[j * 3 + 1]; skz[j] = kb[j * 3 + 2];
    }
    __syncthreads();
    int i = blockIdx.x * blockDim.x + threadIdx.x;
    const float* u = unknown + ((size_t)b * NPTS + i) * 3;
    float ux = u[0], uy = u[1], uz = u[2];
    float b0 = 3.4e38f, b1 = 3.4e38f, b2 = 3.4e38f;
    int i0 = 0, i1 = 0, i2 = 0;
    #pragma unroll 4
    for (int j = 0; j < MPTS; j++) {
        float dx = ux - skx[j], dy = uy - sky[j], dz = uz - skz[j];
        float d = dx * dx + dy * dy + dz * dz;
        if (d < b2) {
            if (d < b1) {
                if (d < b0) { b2 = b1; i2 = i1; b1 = b0; i1 = i0; b0 = d; i0 = j; }
                else        { b2 = b1; i2 = i1; b1 = d;  i1 = j; }
            } else          { b2 = d;  i2 = j; }
        }
    }
    float r0 = 1.0f / (b0 + 1e-8f), r1 = 1.0f / (b1 + 1e-8f), r2 = 1.0f / (b2 + 1e-8f);
    float inv = 1.0f / (r0 + r1 + r2);
    size_t base = ((size_t)b * NPTS + i) * 3;
    g_idx3[base] = i0; g_idx3[base + 1] = i1; g_idx3[base + 2] = i2;
    g_w3[base] = r0 * inv; g_w3[base + 1] = r1 * inv; g_w3[base + 2] = r2 * inv;
}

// ---------------- transpose known_feats (b,c,m)->(b,m,c) ----------------
__global__ void kft_kernel(const float* __restrict__ kf) {
    __shared__ float tile[32][33];
    int b = blockIdx.z, c0 = blockIdx.y * 32, j0 = blockIdx.x * 32;
    const float* src = kf + (size_t)b * CH * MPTS;
    for (int r = threadIdx.y; r < 32; r += 8)
        tile[r][threadIdx.x] = src[(size_t)(c0 + r) * MPTS + j0 + threadIdx.x];
    __syncthreads();
    float* dst = g_kft + (size_t)b * MPTS * CH;
    for (int r = threadIdx.y; r < 32; r += 8)
        dst[(size_t)(j0 + r) * CH + c0 + threadIdx.x] = tile[threadIdx.x][r];
}

// ---------------- gather -> Xh[:, :, 0:256] (half) ----------------
__global__ void gather_kernel() {
    int b = blockIdx.y;
    int i = blockIdx.x * 4 + (threadIdx.x >> 6);
    int c = (threadIdx.x & 63) * 4;
    size_t base = ((size_t)b * NPTS + i) * 3;
    int j0 = g_idx3[base], j1 = g_idx3[base + 1], j2 = g_idx3[base + 2];
    float w0 = g_w3[base], w1 = g_w3[base + 1], w2 = g_w3[base + 2];
    const float* kb = g_kft + (size_t)b * MPTS * CH;
    float4 a = *(const float4*)(kb + (size_t)j0 * CH + c);
    float4 d = *(const float4*)(kb + (size_t)j1 * CH + c);
    float4 e = *(const float4*)(kb + (size_t)j2 * CH + c);
    union { __half2 h[2]; uint2 u; } cv;
    cv.h[0] = __floats2half2_rn(w0 * a.x + w1 * d.x + w2 * e.x,
                                w0 * a.y + w1 * d.y + w2 * e.y);
    cv.h[1] = __floats2half2_rn(w0 * a.z + w1 * d.z + w2 * e.z,
                                w0 * a.w + w1 * d.w + w2 * e.w);
    *(uint2*)(g_Xh + ((size_t)b * NPTS + i) * K1 + c) = cv.u;
}

// ---------------- uf transpose -> Xh[:, :, 256:512] (half) ----------------
__global__ void uft_kernel(const float* __restrict__ uf) {
    __shared__ float tile[32][33];
    int b = blockIdx.z, c0 = blockIdx.y * 32, i0 = blockIdx.x * 32;
    const float* src = uf + (size_t)b * CH * NPTS;
    for (int r = threadIdx.y; r < 32; r += 8)
        tile[r][threadIdx.x] = src[(size_t)(c0 + r) * NPTS + i0 + threadIdx.x];
    __syncthreads();
    __half* dst = g_Xh + (size_t)b * NPTS * K1;
    for (int r = threadIdx.y; r < 32; r += 8)
        dst[(size_t)(i0 + r) * K1 + 256 + c0 + threadIdx.x] = __float2half_rn(tile[threadIdx.x][r]);
}

// ---------------- weight -> half ----------------
__global__ void wround_kernel(const float* __restrict__ w, __half* __restrict__ dst) {
    int i = blockIdx.x * 256 + threadIdx.x;
    dst[i] = __float2half_rn(w[i]);
}
__global__ void zero_kernel() {
    int o = threadIdx.x;
    g_sum1[o] = 0.f; g_sq1[o] = 0.f; g_sum2[o] = 0.f; g_sq2[o] = 0.f;
}

// ---------------- fp16 mma GEMM, 128x128 tile, TK=64, 3-stage, fused col-stats ----------------
// D(b,i,o) = A(b,i,k) @ B(o,k)^T
#define HS      72               // smem row stride in halves (64 data + 8 pad)
#define ATILE_B (128 * HS * 2)   // 18432 bytes
#define STAGE_B (2 * ATILE_B)    // 36864 bytes (A + B)
#define GEMM_SMEM (3 * STAGE_B + 1024)

template<int KDIM>
__global__ void __launch_bounds__(256) gemm_h(const __half* __restrict__ Ag,
                                              const __half* __restrict__ Bg,
                                              float* __restrict__ Dg,
                                              float* __restrict__ sums,
                                              float* __restrict__ sqs) {
    extern __shared__ char smc[];
    const uint32_t sbase = smem_u32(smc);
    float* ssum = (float*)(smc + 3 * STAGE_B);
    float* ssq  = ssum + 128;

    const int tid = threadIdx.x;
    const int wid = tid >> 5, l = tid & 31;
    const int wy = wid >> 2, wx = wid & 3;
    const int g = l >> 2, c4 = l & 3;
    const int lr = l & 7, sel = l >> 3;
    const int b = blockIdx.z;
    const int i0 = blockIdx.x * 128, o0 = blockIdx.y * 128;

    if (tid < 128) { ssum[tid] = 0.f; ssq[tid] = 0.f; }

    const __half* Abase = Ag + ((size_t)b * NPTS + i0) * KDIM;
    const __half* Bbase = Bg + (size_t)o0 * KDIM;

    float acc[4][4][4];
    #pragma unroll
    for (int mi = 0; mi < 4; mi++)
        #pragma unroll
        for (int ni = 0; ni < 4; ni++)
            #pragma unroll
            for (int t = 0; t < 4; t++) acc[mi][ni][t] = 0.f;

    const int rb = tid >> 3, qq = tid & 7;
    const int NC = KDIM / 64;

    auto load_chunk = [&](int c, int s) {
        int k0 = c * 64;
        uint32_t offA = sbase + s * STAGE_B;
        uint32_t offB = offA + ATILE_B;
        const __half* Ab = Abase + k0;
        const __half* Bb = Bbase + k0;
        #pragma unroll
        for (int it = 0; it < 4; it++) {
            int r = rb + it * 32;
            cp16(offA + r * (HS * 2) + qq * 16, Ab + (size_t)r * KDIM + qq * 8);
            cp16(offB + r * (HS * 2) + qq * 16, Bb + (size_t)r * KDIM + qq * 8);
        }
        asm volatile("cp.async.commit_group;" ::: "memory");
    };

    // lane-invariant fragment address offsets (halves)
    const uint32_t aLane = ((uint32_t)(wy * 64 + lr + ((sel & 1) << 3)) * HS + ((sel >> 1) << 3)) * 2;
    const uint32_t bLane = ((uint32_t)(wx * 32 + lr + ((sel >> 1) << 3)) * HS + ((sel & 1) << 3)) * 2;

    load_chunk(0, 0);
    load_chunk(1, 1);
    for (int c = 0; c < NC; c++) {
        if (c + 2 < NC) {
            load_chunk(c + 2, (c + 2) % 3);
            asm volatile("cp.async.wait_group 2;" ::: "memory");
        } else if (c + 1 < NC) {
            asm volatile("cp.async.wait_group 1;" ::: "memory");
        } else {
            asm volatile("cp.async.wait_group 0;" ::: "memory");
        }
        __syncthreads();

        uint32_t sA = sbase + (c % 3) * STAGE_B;
        uint32_t sB = sA + ATILE_B;
        #pragma unroll
        for (int kk16 = 0; kk16 < 4; kk16++) {
            uint32_t koff = kk16 * 32;  // 16 halves * 2B
            uint32_t af[4][4], bf[4][2];
            #pragma unroll
            for (int mi = 0; mi < 4; mi++)
                ldm_x4(af[mi], sA + aLane + mi * (16 * HS * 2) + koff);
            #pragma unroll
            for (int nip = 0; nip < 2; nip++) {
                uint32_t r[4];
                ldm_x4(r, sB + bLane + nip * (16 * HS * 2) + koff);
                bf[2 * nip][0] = r[0]; bf[2 * nip][1] = r[1];
                bf[2 * nip + 1][0] = r[2]; bf[2 * nip + 1][1] = r[3];
            }
            #pragma unroll
            for (int mi = 0; mi < 4; mi++)
                #pragma unroll
                for (int ni = 0; ni < 4; ni++)
                    mma_f16(acc[mi][ni], af[mi], bf[ni]);
        }
        __syncthreads();
    }

    // ---- epilogue: store D(b,i,o) + per-column partial stats ----
    #pragma unroll
    for (int mi = 0; mi < 4; mi++) {
        int row0 = i0 + wy * 64 + mi * 16 + g;
        #pragma unroll
        for (int ni = 0; ni < 4; ni++) {
            int col = o0 + wx * 32 + ni * 8 + 2 * c4;
            *(float2*)(Dg + ((size_t)b * NPTS + row0) * CH + col) =
                make_float2(acc[mi][ni][0], acc[mi][ni][1]);
            *(float2*)(Dg + ((size_t)b * NPTS + row0 + 8) * CH + col) =
                make_float2(acc[mi][ni][2], acc[mi][ni][3]);
        }
    }
    #pragma unroll
    for (int ni = 0; ni < 4; ni++) {
        float s0 = 0.f, s1 = 0.f, q0 = 0.f, q1 = 0.f;
        #pragma unroll
        for (int mi = 0; mi < 4; mi++) {
            const float* a = acc[mi][ni];
            s0 += a[0] + a[2]; s1 += a[1] + a[3];
            q0 += a[0] * a[0] + a[2] * a[2];
            q1 += a[1] * a[1] + a[3] * a[3];
        }
        int lc = wx * 32 + ni * 8 + 2 * c4;
        atomicAdd(&ssum[lc], s0); atomicAdd(&ssum[lc + 1], s1);
        atomicAdd(&ssq[lc], q0);  atomicAdd(&ssq[lc + 1], q1);
    }
    __syncthreads();
    if (tid < 128) {
        atomicAdd(&sums[o0 + tid], ssum[tid]);
        atomicAdd(&sqs[o0 + tid], ssq[tid]);
    }
}

// ---------------- finalize BN params ----------------
__global__ void finalize_kernel(const float* __restrict__ ga, const float* __restrict__ be,
                                const float* __restrict__ sums, const float* __restrict__ sqs,
                                float* __restrict__ scale, float* __restrict__ shift) {
    int o = threadIdx.x;
    float inv = 1.0f / (float)(BB * NPTS);
    float mean = sums[o] * inv;
    float var = sqs[o] * inv - mean * mean;
    float sc = ga[o] * rsqrtf(var + BN_EPS);
    scale[o] = sc;
    shift[o] = be[o] - mean * sc;
}

// ---------------- BN1 + ReLU + half convert: Y1t -> H ----------------
__global__ void bn1h_kernel() {
    size_t q = (size_t)blockIdx.x * 256 + threadIdx.x;  // one float4 per thread
    size_t e = q * 4;
    int o = (int)(e & (CH - 1));
    float4 v = ((const float4*)g_Y1t)[q];
    float4 sc = *(const float4*)(g_scale1 + o);
    float4 sh = *(const float4*)(g_shift1 + o);
    v.x = fmaxf(fmaf(v.x, sc.x, sh.x), 0.f);
    v.y = fmaxf(fmaf(v.y, sc.y, sh.y), 0.f);
    v.z = fmaxf(fmaf(v.z, sc.z, sh.z), 0.f);
    v.w = fmaxf(fmaf(v.w, sc.w, sh.w), 0.f);
    union { __half2 h[2]; uint2 u; } cv;
    cv.h[0] = __floats2half2_rn(v.x, v.y);
    cv.h[1] = __floats2half2_rn(v.z, v.w);
    *(uint2*)(g_H + e) = cv.u;
}

// ---------------- final: BN2 + ReLU + transpose (b,i,o) -> (b,o,i) ----------------
__global__ void out_kernel(float* __restrict__ out) {
    __shared__ float tile[32][33];
    int b = blockIdx.z, i0 = blockIdx.x * 32, o0 = blockIdx.y * 32;
    const float* src = g_Y2t + (size_t)b * NPTS * CH;
    for (int r = threadIdx.y; r < 32; r += 8)
        tile[r][threadIdx.x] = src[(size_t)(i0 + r) * CH + o0 + threadIdx.x];
    __syncthreads();
    float* dst = out + (size_t)b * CH * NPTS;
    for (int r = threadIdx.y; r < 32; r += 8) {
        int o = o0 + r;
        float v = fmaxf(fmaf(tile[threadIdx.x][r], g_scale2[o], g_shift2[o]), 0.f);
        dst[(size_t)o * NPTS + i0 + threadIdx.x] = v;
    }
}

// ---------------- launch ----------------
extern "C" void kernel_launch(void* const* d_in, const int* in_sizes, int n_in,
                              void* d_out, int out_size) {
    const float* unknown = (const float*)d_in[0];
    const float* known   = (const float*)d_in[1];
    const float* uf      = (const float*)d_in[2];
    const float* kf      = (const float*)d_in[3];
    const float* W1      = (const float*)d_in[4];
    const float* g1      = (const float*)d_in[5];
    const float* be1     = (const float*)d_in[6];
    const float* W2      = (const float*)d_in[7];
    const float* g2      = (const float*)d_in[8];
    const float* be2     = (const float*)d_in[9];
    float* out = (float*)d_out;

    cudaFuncSetAttribute(gemm_h<K1>, cudaFuncAttributeMaxDynamicSharedMemorySize, GEMM_SMEM);
    cudaFuncSetAttribute(gemm_h<CH>, cudaFuncAttributeMaxDynamicSharedMemorySize, GEMM_SMEM);

    __half *pXh, *pW1h, *pW2h, *pH;
    float *pY1, *pY2;
    float *ps1, *pq1, *ps2, *pq2, *psc1, *psh1, *psc2, *psh2;
    cudaGetSymbolAddress((void**)&pXh, g_Xh);
    cudaGetSymbolAddress((void**)&pW1h, g_W1h);
    cudaGetSymbolAddress((void**)&pW2h, g_W2h);
    cudaGetSymbolAddress((void**)&pH, g_H);
    cudaGetSymbolAddress((void**)&pY1, g_Y1t);
    cudaGetSymbolAddress((void**)&pY2, g_Y2t);
    cudaGetSymbolAddress((void**)&ps1, g_sum1);
    cudaGetSymbolAddress((void**)&pq1, g_sq1);
    cudaGetSymbolAddress((void**)&ps2, g_sum2);
    cudaGetSymbolAddress((void**)&pq2, g_sq2);
    cudaGetSymbolAddress((void**)&psc1, g_scale1);
    cudaGetSymbolAddress((void**)&psh1, g_shift1);
    cudaGetSymbolAddress((void**)&psc2, g_scale2);
    cudaGetSymbolAddress((void**)&psh2, g_shift2);

    zero_kernel<<<1, 256>>>();
    nn_kernel<<<dim3(NPTS / 256, BB), 256>>>(unknown, known);
    kft_kernel<<<dim3(MPTS / 32, CH / 32, BB), dim3(32, 8)>>>(kf);
    gather_kernel<<<dim3(NPTS / 4, BB), 256>>>();
    uft_kernel<<<dim3(NPTS / 32, CH / 32, BB), dim3(32, 8)>>>(uf);
    wround_kernel<<<CH * K1 / 256, 256>>>(W1, pW1h);
    wround_kernel<<<CH * CH / 256, 256>>>(W2, pW2h);

    gemm_h<K1><<<dim3(NPTS / 128, CH / 128, BB), 256, GEMM_SMEM>>>(pXh, pW1h, pY1, ps1, pq1);
    finalize_kernel<<<1, 256>>>(g1, be1, ps1, pq1, psc1, psh1);
    bn1h_kernel<<<(int)(((size_t)BB * NPTS * CH / 4) / 256), 256>>>();

    gemm_h<CH><<<dim3(NPTS / 128, CH / 128, BB), 256, GEMM_SMEM>>>(pH, pW2h, pY2, ps2, pq2);
    finalize_kernel<<<1, 256>>>(g2, be2, ps2, pq2, psc2, psh2);

    out_kernel<<<dim3(NPTS / 32, CH / 32, BB), dim3(32, 8)>>>(out);
}

// round 5
// speedup vs baseline: 3.2529x; 1.0494x over previous
#include <cuda_runtime.h>
#include <cuda_fp16.h>
#include <cstdint>

#define BB   16
#define NPTS 4096
#define MPTS 1024
#define CH   256
#define K1   512
#define BN_EPS 1e-5f

// ---------------- scratch ----------------
__device__ __align__(16) float  g_kft[(size_t)BB * MPTS * CH];   // known_feats^T (b,m,c) f32
__device__ __align__(16) __half g_Xh[(size_t)BB * NPTS * K1];    // [interp | uf^T] (b,i,k) half
__device__ __align__(16) float  g_Y1t[(size_t)BB * NPTS * CH];   // conv1 raw out (b,i,o) f32
__device__ __align__(16) __half g_H  [(size_t)BB * NPTS * CH];   // relu(bn1(Y1)) half (b,i,o)
__device__ __align__(16) float  g_Y2t[(size_t)BB * NPTS * CH];   // conv2 raw out (b,i,o) f32
__device__ __align__(16) __half g_W1h[CH * K1];
__device__ __align__(16) __half g_W2h[CH * CH];
__device__ int   g_idx3[BB * NPTS * 3];
__device__ float g_w3[BB * NPTS * 3];
__device__ float g_sum1[CH], g_sq1[CH], g_sum2[CH], g_sq2[CH];
__device__ float g_scale1[CH], g_shift1[CH], g_scale2[CH], g_shift2[CH];

// ---------------- helpers ----------------
__device__ __forceinline__ void cp16(uint32_t saddr, const void* g) {
    asm volatile("cp.async.ca.shared.global [%0], [%1], 16;" :: "r"(saddr), "l"(g));
}
__device__ __forceinline__ uint32_t smem_u32(const void* p) {
    uint32_t a;
    asm("{ .reg .u64 t; cvta.to.shared.u64 t, %1; cvt.u32.u64 %0, t; }" : "=r"(a) : "l"(p));
    return a;
}
__device__ __forceinline__ void ldm_x4(uint32_t* r, uint32_t addr) {
    asm volatile("ldmatrix.sync.aligned.m8n8.x4.shared.b16 {%0,%1,%2,%3}, [%4];"
                 : "=r"(r[0]), "=r"(r[1]), "=r"(r[2]), "=r"(r[3]) : "r"(addr));
}
__device__ __forceinline__ void mma_f16(float* d, const uint32_t* a, const uint32_t* b) {
    asm volatile(
        "mma.sync.aligned.m16n8k16.row.col.f32.f16.f16.f32 "
        "{%0,%1,%2,%3}, {%4,%5,%6,%7}, {%8,%9}, {%0,%1,%2,%3};"
        : "+f"(d[0]), "+f"(d[1]), "+f"(d[2]), "+f"(d[3])
        : "r"(a[0]), "r"(a[1]), "r"(a[2]), "r"(a[3]), "r"(b[0]), "r"(b[1]));
}

// ---------------- kernel: 3-NN + weights ----------------
__global__ void nn_kernel(const float* __restrict__ unknown, const float* __restrict__ known) {
    __shared__ float skx[MPTS], sky[MPTS], skz[MPTS];
    int b = blockIdx.y;
    const float* kb = known + (size_t)b * MPTS * 3;
    for (int j = threadIdx.x; j < MPTS; j += blockDim.x) {
        skx[j] = kb[j * 3 + 0]; sky[j] = kb[j * 3 + 1]; skz[j] = kb[j * 3 + 2];
    }
    __syncthreads();
    int i = blockIdx.x * blockDim.x + threadIdx.x;
    const float* u = unknown + ((size_t)b * NPTS + i) * 3;
    float ux = u[0], uy = u[1], uz = u[2];
    float b0 = 3.4e38f, b1 = 3.4e38f, b2 = 3.4e38f;
    int i0 = 0, i1 = 0, i2 = 0;
    #pragma unroll 4
    for (int j = 0; j < MPTS; j++) {
        float dx = ux - skx[j], dy = uy - sky[j], dz = uz - skz[j];
        float d = dx * dx + dy * dy + dz * dz;
        if (d < b2) {
            if (d < b1) {
                if (d < b0) { b2 = b1; i2 = i1; b1 = b0; i1 = i0; b0 = d; i0 = j; }
                else        { b2 = b1; i2 = i1; b1 = d;  i1 = j; }
            } else          { b2 = d;  i2 = j; }
        }
    }
    float r0 = 1.0f / (b0 + 1e-8f), r1 = 1.0f / (b1 + 1e-8f), r2 = 1.0f / (b2 + 1e-8f);
    float inv = 1.0f / (r0 + r1 + r2);
    size_t base = ((size_t)b * NPTS + i) * 3;
    g_idx3[base] = i0; g_idx3[base + 1] = i1; g_idx3[base + 2] = i2;
    g_w3[base] = r0 * inv; g_w3[base + 1] = r1 * inv; g_w3[base + 2] = r2 * inv;
}

// ---------------- transpose known_feats (b,c,m)->(b,m,c) ----------------
__global__ void kft_kernel(const float* __restrict__ kf) {
    __shared__ float tile[32][33];
    int b = blockIdx.z, c0 = blockIdx.y * 32, j0 = blockIdx.x * 32;
    const float* src = kf + (size_t)b * CH * MPTS;
    for (int r = threadIdx.y; r < 32; r += 8)
        tile[r][threadIdx.x] = src[(size_t)(c0 + r) * MPTS + j0 + threadIdx.x];
    __syncthreads();
    float* dst = g_kft + (size_t)b * MPTS * CH;
    for (int r = threadIdx.y; r < 32; r += 8)
        dst[(size_t)(j0 + r) * CH + c0 + threadIdx.x] = tile[threadIdx.x][r];
}

// ---------------- gather -> Xh[:, :, 0:256] (half) ----------------
__global__ void gather_kernel() {
    int b = blockIdx.y;
    int i = blockIdx.x * 4 + (threadIdx.x >> 6);
    int c = (threadIdx.x & 63) * 4;
    size_t base = ((size_t)b * NPTS + i) * 3;
    int j0 = g_idx3[base], j1 = g_idx3[base + 1], j2 = g_idx3[base + 2];
    float w0 = g_w3[base], w1 = g_w3[base + 1], w2 = g_w3[base + 2];
    const float* kb = g_kft + (size_t)b * MPTS * CH;
    float4 a = *(const float4*)(kb + (size_t)j0 * CH + c);
    float4 d = *(const float4*)(kb + (size_t)j1 * CH + c);
    float4 e = *(const float4*)(kb + (size_t)j2 * CH + c);
    union { __half2 h[2]; uint2 u; } cv;
    cv.h[0] = __floats2half2_rn(w0 * a.x + w1 * d.x + w2 * e.x,
                                w0 * a.y + w1 * d.y + w2 * e.y);
    cv.h[1] = __floats2half2_rn(w0 * a.z + w1 * d.z + w2 * e.z,
                                w0 * a.w + w1 * d.w + w2 * e.w);
    *(uint2*)(g_Xh + ((size_t)b * NPTS + i) * K1 + c) = cv.u;
}

// ---------------- uf transpose -> Xh[:, :, 256:512] (half) ----------------
__global__ void uft_kernel(const float* __restrict__ uf) {
    __shared__ float tile[32][33];
    int b = blockIdx.z, c0 = blockIdx.y * 32, i0 = blockIdx.x * 32;
    const float* src = uf + (size_t)b * CH * NPTS;
    for (int r = threadIdx.y; r < 32; r += 8)
        tile[r][threadIdx.x] = src[(size_t)(c0 + r) * NPTS + i0 + threadIdx.x];
    __syncthreads();
    __half* dst = g_Xh + (size_t)b * NPTS * K1;
    for (int r = threadIdx.y; r < 32; r += 8)
        dst[(size_t)(i0 + r) * K1 + 256 + c0 + threadIdx.x] = __float2half_rn(tile[threadIdx.x][r]);
}

// ---------------- weight -> half ----------------
__global__ void wround_kernel(const float* __restrict__ w, __half* __restrict__ dst) {
    int i = blockIdx.x * 256 + threadIdx.x;
    dst[i] = __float2half_rn(w[i]);
}
__global__ void zero_kernel() {
    int o = threadIdx.x;
    g_sum1[o] = 0.f; g_sq1[o] = 0.f; g_sum2[o] = 0.f; g_sq2[o] = 0.f;
}

// ---------------- fp16 mma GEMM, 128x128 tile, TK=64, 2-stage, 2 blocks/SM ----------------
// D(b,i,o) = A(b,i,k) @ B(o,k)^T
#define HS      72               // smem row stride in halves (64 data + 8 pad)
#define ATILE_B (128 * HS * 2)   // 18432 bytes
#define STAGE_B (2 * ATILE_B)    // 36864 bytes (A + B)
#define GEMM_SMEM (2 * STAGE_B + 1024)

template<int KDIM>
__global__ void __launch_bounds__(256, 2) gemm_h(const __half* __restrict__ Ag,
                                                 const __half* __restrict__ Bg,
                                                 float* __restrict__ Dg,
                                                 float* __restrict__ sums,
                                                 float* __restrict__ sqs) {
    extern __shared__ char smc[];
    const uint32_t sbase = smem_u32(smc);
    float* ssum = (float*)(smc + 2 * STAGE_B);
    float* ssq  = ssum + 128;

    const int tid = threadIdx.x;
    const int wid = tid >> 5, l = tid & 31;
    const int wy = wid >> 2, wx = wid & 3;
    const int g = l >> 2, c4 = l & 3;
    const int lr = l & 7, sel = l >> 3;
    const int b = blockIdx.z;
    const int i0 = blockIdx.x * 128, o0 = blockIdx.y * 128;

    if (tid < 128) { ssum[tid] = 0.f; ssq[tid] = 0.f; }

    const __half* Abase = Ag + ((size_t)b * NPTS + i0) * KDIM;
    const __half* Bbase = Bg + (size_t)o0 * KDIM;

    float acc[4][4][4];
    #pragma unroll
    for (int mi = 0; mi < 4; mi++)
        #pragma unroll
        for (int ni = 0; ni < 4; ni++)
            #pragma unroll
            for (int t = 0; t < 4; t++) acc[mi][ni][t] = 0.f;

    const int rb = tid >> 3, qq = tid & 7;
    const int NC = KDIM / 64;

    auto load_chunk = [&](int c, int s) {
        int k0 = c * 64;
        uint32_t offA = sbase + s * STAGE_B;
        uint32_t offB = offA + ATILE_B;
        const __half* Ab = Abase + k0;
        const __half* Bb = Bbase + k0;
        #pragma unroll
        for (int it = 0; it < 4; it++) {
            int r = rb + it * 32;
            cp16(offA + r * (HS * 2) + qq * 16, Ab + (size_t)r * KDIM + qq * 8);
            cp16(offB + r * (HS * 2) + qq * 16, Bb + (size_t)r * KDIM + qq * 8);
        }
        asm volatile("cp.async.commit_group;" ::: "memory");
    };

    // lane-invariant fragment address offsets (halves)
    const uint32_t aLane = ((uint32_t)(wy * 64 + lr + ((sel & 1) << 3)) * HS + ((sel >> 1) << 3)) * 2;
    const uint32_t bLane = ((uint32_t)(wx * 32 + lr + ((sel >> 1) << 3)) * HS + ((sel & 1) << 3)) * 2;

    load_chunk(0, 0);
    if (NC > 1) load_chunk(1, 1);
    for (int c = 0; c < NC; c++) {
        if (c + 1 < NC) {
            asm volatile("cp.async.wait_group 1;" ::: "memory");
        } else {
            asm volatile("cp.async.wait_group 0;" ::: "memory");
        }
        __syncthreads();

        uint32_t sA = sbase + (c & 1) * STAGE_B;
        uint32_t sB = sA + ATILE_B;
        #pragma unroll
        for (int kk16 = 0; kk16 < 4; kk16++) {
            uint32_t koff = kk16 * 32;  // 16 halves * 2B
            uint32_t af[4][4], bf[4][2];
            #pragma unroll
            for (int mi = 0; mi < 4; mi++)
                ldm_x4(af[mi], sA + aLane + mi * (16 * HS * 2) + koff);
            #pragma unroll
            for (int nip = 0; nip < 2; nip++) {
                uint32_t r[4];
                ldm_x4(r, sB + bLane + nip * (16 * HS * 2) + koff);
                bf[2 * nip][0] = r[0]; bf[2 * nip][1] = r[1];
                bf[2 * nip + 1][0] = r[2]; bf[2 * nip + 1][1] = r[3];
            }
            #pragma unroll
            for (int mi = 0; mi < 4; mi++)
                #pragma unroll
                for (int ni = 0; ni < 4; ni++)
                    mma_f16(acc[mi][ni], af[mi], bf[ni]);
        }
        __syncthreads();
        if (c + 2 < NC) load_chunk(c + 2, (c + 2) & 1);
    }

    // ---- epilogue: store D(b,i,o) + per-column partial stats ----
    #pragma unroll
    for (int mi = 0; mi < 4; mi++) {
        int row0 = i0 + wy * 64 + mi * 16 + g;
        #pragma unroll
        for (int ni = 0; ni < 4; ni++) {
            int col = o0 + wx * 32 + ni * 8 + 2 * c4;
            *(float2*)(Dg + ((size_t)b * NPTS + row0) * CH + col) =
                make_float2(acc[mi][ni][0], acc[mi][ni][1]);
            *(float2*)(Dg + ((size_t)b * NPTS + row0 + 8) * CH + col) =
                make_float2(acc[mi][ni][2], acc[mi][ni][3]);
        }
    }
    #pragma unroll
    for (int ni = 0; ni < 4; ni++) {
        float s0 = 0.f, s1 = 0.f, q0 = 0.f, q1 = 0.f;
        #pragma unroll
        for (int mi = 0; mi < 4; mi++) {
            const float* a = acc[mi][ni];
            s0 += a[0] + a[2]; s1 += a[1] + a[3];
            q0 += a[0] * a[0] + a[2] * a[2];
            q1 += a[1] * a[1] + a[3] * a[3];
        }
        int lc = wx * 32 + ni * 8 + 2 * c4;
        atomicAdd(&ssum[lc], s0); atomicAdd(&ssum[lc + 1], s1);
        atomicAdd(&ssq[lc], q0);  atomicAdd(&ssq[lc + 1], q1);
    }
    __syncthreads();
    if (tid < 128) {
        atomicAdd(&sums[o0 + tid], ssum[tid]);
        atomicAdd(&sqs[o0 + tid], ssq[tid]);
    }
}

// ---------------- finalize BN params ----------------
__global__ void finalize_kernel(const float* __restrict__ ga, const float* __restrict__ be,
                                const float* __restrict__ sums, const float* __restrict__ sqs,
                                float* __restrict__ scale, float* __restrict__ shift) {
    int o = threadIdx.x;
    float inv = 1.0f / (float)(BB * NPTS);
    float mean = sums[o] * inv;
    float var = sqs[o] * inv - mean * mean;
    float sc = ga[o] * rsqrtf(var + BN_EPS);
    scale[o] = sc;
    shift[o] = be[o] - mean * sc;
}

// ---------------- BN1 + ReLU + half convert: Y1t -> H ----------------
__global__ void bn1h_kernel() {
    size_t q = (size_t)blockIdx.x * 256 + threadIdx.x;  // one float4 per thread
    size_t e = q * 4;
    int o = (int)(e & (CH - 1));
    float4 v = ((const float4*)g_Y1t)[q];
    float4 sc = *(const float4*)(g_scale1 + o);
    float4 sh = *(const float4*)(g_shift1 + o);
    v.x = fmaxf(fmaf(v.x, sc.x, sh.x), 0.f);
    v.y = fmaxf(fmaf(v.y, sc.y, sh.y), 0.f);
    v.z = fmaxf(fmaf(v.z, sc.z, sh.z), 0.f);
    v.w = fmaxf(fmaf(v.w, sc.w, sh.w), 0.f);
    union { __half2 h[2]; uint2 u; } cv;
    cv.h[0] = __floats2half2_rn(v.x, v.y);
    cv.h[1] = __floats2half2_rn(v.z, v.w);
    *(uint2*)(g_H + e) = cv.u;
}

// ---------------- final: BN2 + ReLU + transpose (b,i,o) -> (b,o,i) ----------------
__global__ void out_kernel(float* __restrict__ out) {
    __shared__ float tile[32][33];
    int b = blockIdx.z, i0 = blockIdx.x * 32, o0 = blockIdx.y * 32;
    const float* src = g_Y2t + (size_t)b * NPTS * CH;
    for (int r = threadIdx.y; r < 32; r += 8)
        tile[r][threadIdx.x] = src[(size_t)(i0 + r) * CH + o0 + threadIdx.x];
    __syncthreads();
    float* dst = out + (size_t)b * CH * NPTS;
    for (int r = threadIdx.y; r < 32; r += 8) {
        int o = o0 + r;
        float v = fmaxf(fmaf(tile[threadIdx.x][r], g_scale2[o], g_shift2[o]), 0.f);
        dst[(size_t)o * NPTS + i0 + threadIdx.x] = v;
    }
}

// ---------------- launch ----------------
extern "C" void kernel_launch(void* const* d_in, const int* in_sizes, int n_in,
                              void* d_out, int out_size) {
    const float* unknown = (const float*)d_in[0];
    const float* known   = (const float*)d_in[1];
    const float* uf      = (const float*)d_in[2];
    const float* kf      = (const float*)d_in[3];
    const float* W1      = (const float*)d_in[4];
    const float* g1      = (const float*)d_in[5];
    const float* be1     = (const float*)d_in[6];
    const float* W2      = (const float*)d_in[7];
    const float* g2      = (const float*)d_in[8];
    const float* be2     = (const float*)d_in[9];
    float* out = (float*)d_out;

    cudaFuncSetAttribute(gemm_h<K1>, cudaFuncAttributeMaxDynamicSharedMemorySize, GEMM_SMEM);
    cudaFuncSetAttribute(gemm_h<CH>, cudaFuncAttributeMaxDynamicSharedMemorySize, GEMM_SMEM);

    __half *pXh, *pW1h, *pW2h, *pH;
    float *pY1, *pY2;
    float *ps1, *pq1, *ps2, *pq2, *psc1, *psh1, *psc2, *psh2;
    cudaGetSymbolAddress((void**)&pXh, g_Xh);
    cudaGetSymbolAddress((void**)&pW1h, g_W1h);
    cudaGetSymbolAddress((void**)&pW2h, g_W2h);
    cudaGetSymbolAddress((void**)&pH, g_H);
    cudaGetSymbolAddress((void**)&pY1, g_Y1t);
    cudaGetSymbolAddress((void**)&pY2, g_Y2t);
    cudaGetSymbolAddress((void**)&ps1, g_sum1);
    cudaGetSymbolAddress((void**)&pq1, g_sq1);
    cudaGetSymbolAddress((void**)&ps2, g_sum2);
    cudaGetSymbolAddress((void**)&pq2, g_sq2);
    cudaGetSymbolAddress((void**)&psc1, g_scale1);
    cudaGetSymbolAddress((void**)&psh1, g_shift1);
    cudaGetSymbolAddress((void**)&psc2, g_scale2);
    cudaGetSymbolAddress((void**)&psh2, g_shift2);

    zero_kernel<<<1, 256>>>();
    nn_kernel<<<dim3(NPTS / 256, BB), 256>>>(unknown, known);
    kft_kernel<<<dim3(MPTS / 32, CH / 32, BB), dim3(32, 8)>>>(kf);
    gather_kernel<<<dim3(NPTS / 4, BB), 256>>>();
    uft_kernel<<<dim3(NPTS / 32, CH / 32, BB), dim3(32, 8)>>>(uf);
    wround_kernel<<<CH * K1 / 256, 256>>>(W1, pW1h);
    wround_kernel<<<CH * CH / 256, 256>>>(W2, pW2h);

    gemm_h<K1><<<dim3(NPTS / 128, CH / 128, BB), 256, GEMM_SMEM>>>(pXh, pW1h, pY1, ps1, pq1);
    finalize_kernel<<<1, 256>>>(g1, be1, ps1, pq1, psc1, psh1);
    bn1h_kernel<<<(int)(((size_t)BB * NPTS * CH / 4) / 256), 256>>>();

    gemm_h<CH><<<dim3(NPTS / 128, CH / 128, BB), 256, GEMM_SMEM>>>(pH, pW2h, pY2, ps2, pq2);
    finalize_kernel<<<1, 256>>>(g2, be2, ps2, pq2, psc2, psh2);

    out_kernel<<<dim3(NPTS / 32, CH / 32, BB), dim3(32, 8)>>>(out);
}

// round 6
// speedup vs baseline: 3.5033x; 1.0770x over previous
#include <cuda_runtime.h>
#include <cuda_fp16.h>
#include <cstdint>

#define BB   16
#define NPTS 4096
#define MPTS 1024
#define CH   256
#define K1   512
#define BN_EPS 1e-5f

// ---------------- scratch ----------------
__device__ __align__(16) __half g_kft[(size_t)BB * MPTS * CH];   // known_feats^T (b,m,c) half
__device__ __align__(16) __half g_Xh[(size_t)BB * NPTS * K1];    // [interp | uf^T] (b,i,k) half
__device__ __align__(16) __half g_Hh[(size_t)BB * NPTS * CH];    // conv1 raw out (b,i,o) half
__device__ __align__(16) __half g_Y2h[(size_t)BB * NPTS * CH];   // conv2 raw out (b,i,o) half
__device__ __align__(16) __half g_W1h[CH * K1];
__device__ __align__(16) __half g_W2h[CH * CH];
__device__ int   g_idx3[BB * NPTS * 3];
__device__ float g_w3[BB * NPTS * 3];
__device__ float g_sum1[CH], g_sq1[CH], g_sum2[CH], g_sq2[CH];
__device__ float g_scale2[CH], g_shift2[CH];
__device__ __align__(16) __half g_sc1h[CH], g_sh1h[CH];
__device__ __align__(16) __half g_sc2h[CH], g_sh2h[CH];   // scratch (unused by out)

// ---------------- helpers ----------------
__device__ __forceinline__ void cp16(uint32_t saddr, const void* g) {
    asm volatile("cp.async.ca.shared.global [%0], [%1], 16;" :: "r"(saddr), "l"(g));
}
__device__ __forceinline__ uint32_t smem_u32(const void* p) {
    uint32_t a;
    asm("{ .reg .u64 t; cvta.to.shared.u64 t, %1; cvt.u32.u64 %0, t; }" : "=r"(a) : "l"(p));
    return a;
}
__device__ __forceinline__ void ldm_x4(uint32_t* r, uint32_t addr) {
    asm volatile("ldmatrix.sync.aligned.m8n8.x4.shared.b16 {%0,%1,%2,%3}, [%4];"
                 : "=r"(r[0]), "=r"(r[1]), "=r"(r[2]), "=r"(r[3]) : "r"(addr));
}
__device__ __forceinline__ void mma_f16(float* d, const uint32_t* a, const uint32_t* b) {
    asm volatile(
        "mma.sync.aligned.m16n8k16.row.col.f32.f16.f16.f32 "
        "{%0,%1,%2,%3}, {%4,%5,%6,%7}, {%8,%9}, {%0,%1,%2,%3};"
        : "+f"(d[0]), "+f"(d[1]), "+f"(d[2]), "+f"(d[3])
        : "r"(a[0]), "r"(a[1]), "r"(a[2]), "r"(a[3]), "r"(b[0]), "r"(b[1]));
}

// ---------------- kernel: 3-NN + weights ----------------
__global__ void nn_kernel(const float* __restrict__ unknown, const float* __restrict__ known) {
    __shared__ float4 sk[MPTS];
    int b = blockIdx.y;
    const float* kb = known + (size_t)b * MPTS * 3;
    for (int j = threadIdx.x; j < MPTS; j += blockDim.x)
        sk[j] = make_float4(kb[j * 3 + 0], kb[j * 3 + 1], kb[j * 3 + 2], 0.f);
    __syncthreads();
    int i = blockIdx.x * blockDim.x + threadIdx.x;
    const float* u = unknown + ((size_t)b * NPTS + i) * 3;
    float ux = u[0], uy = u[1], uz = u[2];
    float b0 = 3.4e38f, b1 = 3.4e38f, b2 = 3.4e38f;
    int i0 = 0, i1 = 0, i2 = 0;
    #pragma unroll 4
    for (int j = 0; j < MPTS; j++) {
        float4 k4 = sk[j];
        float dx = ux - k4.x, dy = uy - k4.y, dz = uz - k4.z;
        float d = dx * dx + dy * dy + dz * dz;
        if (d < b2) {
            if (d < b1) {
                if (d < b0) { b2 = b1; i2 = i1; b1 = b0; i1 = i0; b0 = d; i0 = j; }
                else        { b2 = b1; i2 = i1; b1 = d;  i1 = j; }
            } else          { b2 = d;  i2 = j; }
        }
    }
    float r0 = 1.0f / (b0 + 1e-8f), r1 = 1.0f / (b1 + 1e-8f), r2 = 1.0f / (b2 + 1e-8f);
    float inv = 1.0f / (r0 + r1 + r2);
    size_t base = ((size_t)b * NPTS + i) * 3;
    g_idx3[base] = i0; g_idx3[base + 1] = i1; g_idx3[base + 2] = i2;
    g_w3[base] = r0 * inv; g_w3[base + 1] = r1 * inv; g_w3[base + 2] = r2 * inv;
}

// ---------------- transpose known_feats (b,c,m)->(b,m,c) half ----------------
__global__ void kft_kernel(const float* __restrict__ kf) {
    __shared__ float tile[32][33];
    int b = blockIdx.z, c0 = blockIdx.y * 32, j0 = blockIdx.x * 32;
    const float* src = kf + (size_t)b * CH * MPTS;
    for (int r = threadIdx.y; r < 32; r += 8)
        tile[r][threadIdx.x] = src[(size_t)(c0 + r) * MPTS + j0 + threadIdx.x];
    __syncthreads();
    __half* dst = g_kft + (size_t)b * MPTS * CH;
    for (int r = threadIdx.y; r < 32; r += 8)
        dst[(size_t)(j0 + r) * CH + c0 + threadIdx.x] = __float2half_rn(tile[threadIdx.x][r]);
}

// ---------------- gather -> Xh[:, :, 0:256] (half) ----------------
__global__ void gather_kernel() {
    int b = blockIdx.y;
    int i = blockIdx.x * 4 + (threadIdx.x >> 6);
    int c = (threadIdx.x & 63) * 4;
    size_t base = ((size_t)b * NPTS + i) * 3;
    int j0 = g_idx3[base], j1 = g_idx3[base + 1], j2 = g_idx3[base + 2];
    float w0 = g_w3[base], w1 = g_w3[base + 1], w2 = g_w3[base + 2];
    const __half* kb = g_kft + (size_t)b * MPTS * CH;
    union { uint2 u; __half2 h[2]; } a, d, e;
    a.u = *(const uint2*)(kb + (size_t)j0 * CH + c);
    d.u = *(const uint2*)(kb + (size_t)j1 * CH + c);
    e.u = *(const uint2*)(kb + (size_t)j2 * CH + c);
    float2 a0 = __half22float2(a.h[0]), a1 = __half22float2(a.h[1]);
    float2 d0 = __half22float2(d.h[0]), d1 = __half22float2(d.h[1]);
    float2 e0 = __half22float2(e.h[0]), e1 = __half22float2(e.h[1]);
    union { __half2 h[2]; uint2 u; } cv;
    cv.h[0] = __floats2half2_rn(w0 * a0.x + w1 * d0.x + w2 * e0.x,
                                w0 * a0.y + w1 * d0.y + w2 * e0.y);
    cv.h[1] = __floats2half2_rn(w0 * a1.x + w1 * d1.x + w2 * e1.x,
                                w0 * a1.y + w1 * d1.y + w2 * e1.y);
    *(uint2*)(g_Xh + ((size_t)b * NPTS + i) * K1 + c) = cv.u;
}

// ---------------- uf transpose -> Xh[:, :, 256:512] (half) ----------------
__global__ void uft_kernel(const float* __restrict__ uf) {
    __shared__ float tile[32][33];
    int b = blockIdx.z, c0 = blockIdx.y * 32, i0 = blockIdx.x * 32;
    const float* src = uf + (size_t)b * CH * NPTS;
    for (int r = threadIdx.y; r < 32; r += 8)
        tile[r][threadIdx.x] = src[(size_t)(c0 + r) * NPTS + i0 + threadIdx.x];
    __syncthreads();
    __half* dst = g_Xh + (size_t)b * NPTS * K1;
    for (int r = threadIdx.y; r < 32; r += 8)
        dst[(size_t)(i0 + r) * K1 + 256 + c0 + threadIdx.x] = __float2half_rn(tile[threadIdx.x][r]);
}

// ---------------- weight -> half ----------------
__global__ void wround_kernel(const float* __restrict__ w, __half* __restrict__ dst) {
    int i = blockIdx.x * 256 + threadIdx.x;
    dst[i] = __float2half_rn(w[i]);
}
__global__ void zero_kernel() {
    int o = threadIdx.x;
    g_sum1[o] = 0.f; g_sq1[o] = 0.f; g_sum2[o] = 0.f; g_sq2[o] = 0.f;
}

// ---------------- fp16 mma GEMM, 128x128 tile, TK=64, 2-stage, 2 blocks/SM ----------------
// D(b,i,o) = A(b,i,k) @ B(o,k)^T ; output raw half + fused column stats.
// FUSE: A-loader applies half2 BN1+ReLU (scale/shift from g_sc1h/g_sh1h).
#define HS      72               // smem row stride in halves (64 data + 8 pad)
#define ATILE_B (128 * HS * 2)   // 18432 bytes
#define STAGE_B (2 * ATILE_B)    // 36864 bytes (A + B)
#define GEMM_SMEM (2 * STAGE_B + 1024)

template<int KDIM, bool FUSE>
__global__ void __launch_bounds__(256, 2) gemm_h(const __half* __restrict__ Ag,
                                                 const __half* __restrict__ Bg,
                                                 __half* __restrict__ Dg,
                                                 float* __restrict__ sums,
                                                 float* __restrict__ sqs) {
    extern __shared__ char smc[];
    const uint32_t sbase = smem_u32(smc);
    float* ssum = (float*)(smc + 2 * STAGE_B);
    float* ssq  = ssum + 128;

    const int tid = threadIdx.x;
    const int wid = tid >> 5, l = tid & 31;
    const int wy = wid >> 2, wx = wid & 3;
    const int g = l >> 2, c4 = l & 3;
    const int lr = l & 7, sel = l >> 3;
    const int b = blockIdx.z;
    const int i0 = blockIdx.x * 128, o0 = blockIdx.y * 128;

    if (tid < 128) { ssum[tid] = 0.f; ssq[tid] = 0.f; }

    const __half* Abase = Ag + ((size_t)b * NPTS + i0) * KDIM;
    const __half* Bbase = Bg + (size_t)o0 * KDIM;

    float acc[4][4][4];
    #pragma unroll
    for (int mi = 0; mi < 4; mi++)
        #pragma unroll
        for (int ni = 0; ni < 4; ni++)
            #pragma unroll
            for (int t = 0; t < 4; t++) acc[mi][ni][t] = 0.f;

    const int rb = tid >> 3, qq = tid & 7;
    const int NC = KDIM / 64;

    uint4 areg[4], screg, shreg;

    auto loadB = [&](int c, int s) {
        int k0 = c * 64;
        uint32_t offB = sbase + s * STAGE_B + ATILE_B;
        const __half* Bb = Bbase + k0;
        #pragma unroll
        for (int it = 0; it < 4; it++) {
            int r = rb + it * 32;
            cp16(offB + r * (HS * 2) + qq * 16, Bb + (size_t)r * KDIM + qq * 8);
        }
        asm volatile("cp.async.commit_group;" ::: "memory");
    };
    auto loadA_cp = [&](int c, int s) {   // non-FUSE: A via cp.async (same group as B)
        int k0 = c * 64;
        uint32_t offA = sbase + s * STAGE_B;
        const __half* Ab = Abase + k0;
        #pragma unroll
        for (int it = 0; it < 4; it++) {
            int r = rb + it * 32;
            cp16(offA + r * (HS * 2) + qq * 16, Ab + (size_t)r * KDIM + qq * 8);
        }
    };
    auto ldgA = [&](int c) {              // FUSE: A + scales to regs
        int k0 = c * 64;
        #pragma unroll
        for (int it = 0; it < 4; it++)
            areg[it] = *(const uint4*)(Abase + (size_t)(rb + it * 32) * KDIM + k0 + qq * 8);
        screg = *(const uint4*)(g_sc1h + k0 + qq * 8);
        shreg = *(const uint4*)(g_sh1h + k0 + qq * 8);
    };
    auto stsA = [&](int s) {              // FUSE: transform + STS
        const __half2 z2 = __float2half2_rn(0.f);
        union { uint4 u; __half2 h[4]; } sc, sh;
        sc.u = screg; sh.u = shreg;
        #pragma unroll
        for (int it = 0; it < 4; it++) {
            int r = rb + it * 32;
            union { uint4 u; __half2 h[4]; } v;
            v.u = areg[it];
            #pragma unroll
            for (int j = 0; j < 4; j++)
                v.h[j] = __hmax2(__hfma2(v.h[j], sc.h[j], sh.h[j]), z2);
            *(uint4*)(smc + s * STAGE_B + r * (HS * 2) + qq * 16) = v.u;
        }
    };

    // lane-invariant fragment address offsets (halves)
    const uint32_t aLane = ((uint32_t)(wy * 64 + lr + ((sel & 1) << 3)) * HS + ((sel >> 1) << 3)) * 2;
    const uint32_t bLane = ((uint32_t)(wx * 32 + lr + ((sel >> 1) << 3)) * HS + ((sel & 1) << 3)) * 2;

    // prologue
    if (FUSE) { ldgA(0); stsA(0); } else { loadA_cp(0, 0); }
    loadB(0, 0);
    if (NC > 1) {
        if (FUSE) { ldgA(1); stsA(1); } else { loadA_cp(1, 1); }
        loadB(1, 1);
    }

    for (int c = 0; c < NC; c++) {
        if (c + 1 < NC) {
            asm volatile("cp.async.wait_group 1;" ::: "memory");
        } else {
            asm volatile("cp.async.wait_group 0;" ::: "memory");
        }
        __syncthreads();

        if (FUSE && c + 2 < NC) ldgA(c + 2);

        uint32_t sA = sbase + (c & 1) * STAGE_B;
        uint32_t sB = sA + ATILE_B;
        #pragma unroll
        for (int kk16 = 0; kk16 < 4; kk16++) {
            uint32_t koff = kk16 * 32;  // 16 halves * 2B
            uint32_t af[4][4], bf[4][2];
            #pragma unroll
            for (int mi = 0; mi < 4; mi++)
                ldm_x4(af[mi], sA + aLane + mi * (16 * HS * 2) + koff);
            #pragma unroll
            for (int nip = 0; nip < 2; nip++) {
                uint32_t r[4];
                ldm_x4(r, sB + bLane + nip * (16 * HS * 2) + koff);
                bf[2 * nip][0] = r[0]; bf[2 * nip][1] = r[1];
                bf[2 * nip + 1][0] = r[2]; bf[2 * nip + 1][1] = r[3];
            }
            #pragma unroll
            for (int mi = 0; mi < 4; mi++)
                #pragma unroll
                for (int ni = 0; ni < 4; ni++)
                    mma_f16(acc[mi][ni], af[mi], bf[ni]);
        }
        __syncthreads();
        if (c + 2 < NC) {
            int s = (c + 2) & 1;
            if (FUSE) stsA(s); else loadA_cp(c + 2, s);
            loadB(c + 2, s);
        }
    }

    // ---- epilogue: store raw half D(b,i,o) + per-column partial stats ----
    #pragma unroll
    for (int mi = 0; mi < 4; mi++) {
        int row0 = i0 + wy * 64 + mi * 16 + g;
        #pragma unroll
        for (int ni = 0; ni < 4; ni++) {
            int col = o0 + wx * 32 + ni * 8 + 2 * c4;
            *(__half2*)(Dg + ((size_t)b * NPTS + row0) * CH + col) =
                __floats2half2_rn(acc[mi][ni][0], acc[mi][ni][1]);
            *(__half2*)(Dg + ((size_t)b * NPTS + row0 + 8) * CH + col) =
                __floats2half2_rn(acc[mi][ni][2], acc[mi][ni][3]);
        }
    }
    #pragma unroll
    for (int ni = 0; ni < 4; ni++) {
        float s0 = 0.f, s1 = 0.f, q0 = 0.f, q1 = 0.f;
        #pragma unroll
        for (int mi = 0; mi < 4; mi++) {
            const float* a = acc[mi][ni];
            s0 += a[0] + a[2]; s1 += a[1] + a[3];
            q0 += a[0] * a[0] + a[2] * a[2];
            q1 += a[1] * a[1] + a[3] * a[3];
        }
        int lc = wx * 32 + ni * 8 + 2 * c4;
        atomicAdd(&ssum[lc], s0); atomicAdd(&ssum[lc + 1], s1);
        atomicAdd(&ssq[lc], q0);  atomicAdd(&ssq[lc + 1], q1);
    }
    __syncthreads();
    if (tid < 128) {
        atomicAdd(&sums[o0 + tid], ssum[tid]);
        atomicAdd(&sqs[o0 + tid], ssq[tid]);
    }
}

// ---------------- finalize BN params (f32 + half copies) ----------------
__global__ void finalize_kernel(const float* __restrict__ ga, const float* __restrict__ be,
                                const float* __restrict__ sums, const float* __restrict__ sqs,
                                float* __restrict__ scale, float* __restrict__ shift,
                                __half* __restrict__ sch, __half* __restrict__ shh) {
    int o = threadIdx.x;
    float inv = 1.0f / (float)(BB * NPTS);
    float mean = sums[o] * inv;
    float var = sqs[o] * inv - mean * mean;
    float sc = ga[o] * rsqrtf(var + BN_EPS);
    float sh = be[o] - mean * sc;
    scale[o] = sc; shift[o] = sh;
    sch[o] = __float2half_rn(sc);
    shh[o] = __float2half_rn(sh);
}
__device__ float g_scale1_f[CH], g_shift1_f[CH];  // f32 BN1 (unused downstream, kept for finalize signature)

// ---------------- final: BN2 + ReLU + transpose half(b,i,o) -> f32 (b,o,i) ----------------
__global__ void out_kernel(float* __restrict__ out) {
    __shared__ float tile[32][33];
    int b = blockIdx.z, i0 = blockIdx.x * 32, o0 = blockIdx.y * 32;
    const __half* src = g_Y2h + (size_t)b * NPTS * CH;
    for (int r = threadIdx.y; r < 32; r += 8)
        tile[r][threadIdx.x] = __half2float(src[(size_t)(i0 + r) * CH + o0 + threadIdx.x]);
    __syncthreads();
    float* dst = out + (size_t)b * CH * NPTS;
    for (int r = threadIdx.y; r < 32; r += 8) {
        int o = o0 + r;
        float v = fmaxf(fmaf(tile[threadIdx.x][r], g_scale2[o], g_shift2[o]), 0.f);
        dst[(size_t)o * NPTS + i0 + threadIdx.x] = v;
    }
}

// ---------------- launch ----------------
extern "C" void kernel_launch(void* const* d_in, const int* in_sizes, int n_in,
                              void* d_out, int out_size) {
    const float* unknown = (const float*)d_in[0];
    const float* known   = (const float*)d_in[1];
    const float* uf      = (const float*)d_in[2];
    const float* kf      = (const float*)d_in[3];
    const float* W1      = (const float*)d_in[4];
    const float* g1      = (const float*)d_in[5];
    const float* be1     = (const float*)d_in[6];
    const float* W2      = (const float*)d_in[7];
    const float* g2      = (const float*)d_in[8];
    const float* be2     = (const float*)d_in[9];
    float* out = (float*)d_out;

    cudaFuncSetAttribute((gemm_h<K1, false>), cudaFuncAttributeMaxDynamicSharedMemorySize, GEMM_SMEM);
    cudaFuncSetAttribute((gemm_h<CH, true>),  cudaFuncAttributeMaxDynamicSharedMemorySize, GEMM_SMEM);

    __half *pXh, *pW1h, *pW2h, *pHh, *pY2h, *psc1h, *psh1h, *psc2h, *psh2h;
    float *ps1, *pq1, *ps2, *pq2, *psc2, *psh2, *psc1f, *psh1f;
    cudaGetSymbolAddress((void**)&pXh, g_Xh);
    cudaGetSymbolAddress((void**)&pW1h, g_W1h);
    cudaGetSymbolAddress((void**)&pW2h, g_W2h);
    cudaGetSymbolAddress((void**)&pHh, g_Hh);
    cudaGetSymbolAddress((void**)&pY2h, g_Y2h);
    cudaGetSymbolAddress((void**)&ps1, g_sum1);
    cudaGetSymbolAddress((void**)&pq1, g_sq1);
    cudaGetSymbolAddress((void**)&ps2, g_sum2);
    cudaGetSymbolAddress((void**)&pq2, g_sq2);
    cudaGetSymbolAddress((void**)&psc2, g_scale2);
    cudaGetSymbolAddress((void**)&psh2, g_shift2);
    cudaGetSymbolAddress((void**)&psc1f, g_scale1_f);
    cudaGetSymbolAddress((void**)&psh1f, g_shift1_f);
    cudaGetSymbolAddress((void**)&psc1h, g_sc1h);
    cudaGetSymbolAddress((void**)&psh1h, g_sh1h);
    cudaGetSymbolAddress((void**)&psc2h, g_sc2h);
    cudaGetSymbolAddress((void**)&psh2h, g_sh2h);

    zero_kernel<<<1, 256>>>();
    nn_kernel<<<dim3(NPTS / 256, BB), 256>>>(unknown, known);
    kft_kernel<<<dim3(MPTS / 32, CH / 32, BB), dim3(32, 8)>>>(kf);
    gather_kernel<<<dim3(NPTS / 4, BB), 256>>>();
    uft_kernel<<<dim3(NPTS / 32, CH / 32, BB), dim3(32, 8)>>>(uf);
    wround_kernel<<<CH * K1 / 256, 256>>>(W1, pW1h);
    wround_kernel<<<CH * CH / 256, 256>>>(W2, pW2h);

    gemm_h<K1, false><<<dim3(NPTS / 128, CH / 128, BB), 256, GEMM_SMEM>>>(pXh, pW1h, pHh, ps1, pq1);
    finalize_kernel<<<1, 256>>>(g1, be1, ps1, pq1, psc1f, psh1f, psc1h, psh1h);

    gemm_h<CH, true><<<dim3(NPTS / 128, CH / 128, BB), 256, GEMM_SMEM>>>(pHh, pW2h, pY2h, ps2, pq2);
    finalize_kernel<<<1, 256>>>(g2, be2, ps2, pq2, psc2, psh2, psc2h, psh2h);

    out_kernel<<<dim3(NPTS / 32, CH / 32, BB), dim3(32, 8)>>>(out);
}

// round 7
// speedup vs baseline: 3.5080x; 1.0013x over previous
#include <cuda_runtime.h>
#include <cuda_fp16.h>
#include <cstdint>

#define BB   16
#define NPTS 4096
#define MPTS 1024
#define CH   256
#define K1   512
#define BN_EPS 1e-5f

// ---------------- scratch ----------------
__device__ __align__(16) __half g_kft[(size_t)BB * MPTS * CH];   // known_feats^T (b,m,c) half
__device__ __align__(16) __half g_Xh[(size_t)BB * NPTS * K1];    // [interp | uf^T] (b,i,k) half
__device__ __align__(16) __half g_Hh[(size_t)BB * NPTS * CH];    // conv1 raw out (b,i,o) half
__device__ __align__(16) __half g_Y2h[(size_t)BB * NPTS * CH];   // conv2 raw out (b,i,o) half
__device__ __align__(16) __half g_W1h[CH * K1];
__device__ __align__(16) __half g_W2h[CH * CH];
__device__ int   g_idx3[BB * NPTS * 3];
__device__ float g_w3[BB * NPTS * 3];
__device__ float g_sum1[CH], g_sq1[CH], g_sum2[CH], g_sq2[CH];
__device__ float g_scale2[CH], g_shift2[CH];
__device__ float g_scale1_f[CH], g_shift1_f[CH];
__device__ __align__(16) __half g_sc1h[CH], g_sh1h[CH];
__device__ __align__(16) __half g_sc2h[CH], g_sh2h[CH];

// ---------------- helpers ----------------
__device__ __forceinline__ void cp16(uint32_t saddr, const void* g) {
    asm volatile("cp.async.ca.shared.global [%0], [%1], 16;" :: "r"(saddr), "l"(g));
}
__device__ __forceinline__ uint32_t smem_u32(const void* p) {
    uint32_t a;
    asm("{ .reg .u64 t; cvta.to.shared.u64 t, %1; cvt.u32.u64 %0, t; }" : "=r"(a) : "l"(p));
    return a;
}
__device__ __forceinline__ void ldm_x4(uint32_t* r, uint32_t addr) {
    asm volatile("ldmatrix.sync.aligned.m8n8.x4.shared.b16 {%0,%1,%2,%3}, [%4];"
                 : "=r"(r[0]), "=r"(r[1]), "=r"(r[2]), "=r"(r[3]) : "r"(addr));
}
__device__ __forceinline__ void mma_f16(float* d, const uint32_t* a, const uint32_t* b) {
    asm volatile(
        "mma.sync.aligned.m16n8k16.row.col.f32.f16.f16.f32 "
        "{%0,%1,%2,%3}, {%4,%5,%6,%7}, {%8,%9}, {%0,%1,%2,%3};"
        : "+f"(d[0]), "+f"(d[1]), "+f"(d[2]), "+f"(d[3])
        : "r"(a[0]), "r"(a[1]), "r"(a[2]), "r"(a[3]), "r"(b[0]), "r"(b[1]));
}

// ---------------- prep: weight->half conversions + stats zero (one launch) ----------------
__global__ void prep_kernel(const float* __restrict__ W1, const float* __restrict__ W2) {
    int blk = blockIdx.x;
    int t = threadIdx.x;
    if (blk < CH * K1 / 256) {
        int i = blk * 256 + t;
        g_W1h[i] = __float2half_rn(W1[i]);
    } else if (blk < CH * K1 / 256 + CH * CH / 256) {
        int i = (blk - CH * K1 / 256) * 256 + t;
        g_W2h[i] = __float2half_rn(W2[i]);
    } else {
        g_sum1[t] = 0.f; g_sq1[t] = 0.f; g_sum2[t] = 0.f; g_sq2[t] = 0.f;
    }
}

// ---------------- kernel: 3-NN + weights ----------------
__global__ void nn_kernel(const float* __restrict__ unknown, const float* __restrict__ known) {
    __shared__ float4 sk[MPTS];
    int b = blockIdx.y;
    const float* kb = known + (size_t)b * MPTS * 3;
    for (int j = threadIdx.x; j < MPTS; j += blockDim.x)
        sk[j] = make_float4(kb[j * 3 + 0], kb[j * 3 + 1], kb[j * 3 + 2], 0.f);
    __syncthreads();
    int i = blockIdx.x * blockDim.x + threadIdx.x;
    const float* u = unknown + ((size_t)b * NPTS + i) * 3;
    float ux = u[0], uy = u[1], uz = u[2];
    float b0 = 3.4e38f, b1 = 3.4e38f, b2 = 3.4e38f;
    int i0 = 0, i1 = 0, i2 = 0;
    #pragma unroll 4
    for (int j = 0; j < MPTS; j++) {
        float4 k4 = sk[j];
        float dx = ux - k4.x, dy = uy - k4.y, dz = uz - k4.z;
        float d = dx * dx + dy * dy + dz * dz;
        if (d < b2) {
            if (d < b1) {
                if (d < b0) { b2 = b1; i2 = i1; b1 = b0; i1 = i0; b0 = d; i0 = j; }
                else        { b2 = b1; i2 = i1; b1 = d;  i1 = j; }
            } else          { b2 = d;  i2 = j; }
        }
    }
    float r0 = 1.0f / (b0 + 1e-8f), r1 = 1.0f / (b1 + 1e-8f), r2 = 1.0f / (b2 + 1e-8f);
    float inv = 1.0f / (r0 + r1 + r2);
    size_t base = ((size_t)b * NPTS + i) * 3;
    g_idx3[base] = i0; g_idx3[base + 1] = i1; g_idx3[base + 2] = i2;
    g_w3[base] = r0 * inv; g_w3[base + 1] = r1 * inv; g_w3[base + 2] = r2 * inv;
}

// ---------------- transpose known_feats (b,c,m)->(b,m,c) half ----------------
__global__ void kft_kernel(const float* __restrict__ kf) {
    __shared__ float tile[32][33];
    int b = blockIdx.z, c0 = blockIdx.y * 32, j0 = blockIdx.x * 32;
    const float* src = kf + (size_t)b * CH * MPTS;
    for (int r = threadIdx.y; r < 32; r += 8)
        tile[r][threadIdx.x] = src[(size_t)(c0 + r) * MPTS + j0 + threadIdx.x];
    __syncthreads();
    __half* dst = g_kft + (size_t)b * MPTS * CH;
    for (int r = threadIdx.y; r < 32; r += 8)
        dst[(size_t)(j0 + r) * CH + c0 + threadIdx.x] = __float2half_rn(tile[threadIdx.x][r]);
}

// ---------------- gather -> Xh[:, :, 0:256] (half) ----------------
__global__ void gather_kernel() {
    int b = blockIdx.y;
    int i = blockIdx.x * 4 + (threadIdx.x >> 6);
    int c = (threadIdx.x & 63) * 4;
    size_t base = ((size_t)b * NPTS + i) * 3;
    int j0 = g_idx3[base], j1 = g_idx3[base + 1], j2 = g_idx3[base + 2];
    float w0 = g_w3[base], w1 = g_w3[base + 1], w2 = g_w3[base + 2];
    const __half* kb = g_kft + (size_t)b * MPTS * CH;
    union { uint2 u; __half2 h[2]; } a, d, e;
    a.u = *(const uint2*)(kb + (size_t)j0 * CH + c);
    d.u = *(const uint2*)(kb + (size_t)j1 * CH + c);
    e.u = *(const uint2*)(kb + (size_t)j2 * CH + c);
    float2 a0 = __half22float2(a.h[0]), a1 = __half22float2(a.h[1]);
    float2 d0 = __half22float2(d.h[0]), d1 = __half22float2(d.h[1]);
    float2 e0 = __half22float2(e.h[0]), e1 = __half22float2(e.h[1]);
    union { __half2 h[2]; uint2 u; } cv;
    cv.h[0] = __floats2half2_rn(w0 * a0.x + w1 * d0.x + w2 * e0.x,
                                w0 * a0.y + w1 * d0.y + w2 * e0.y);
    cv.h[1] = __floats2half2_rn(w0 * a1.x + w1 * d1.x + w2 * e1.x,
                                w0 * a1.y + w1 * d1.y + w2 * e1.y);
    *(uint2*)(g_Xh + ((size_t)b * NPTS + i) * K1 + c) = cv.u;
}

// ---------------- uf transpose -> Xh[:, :, 256:512] (half) ----------------
__global__ void uft_kernel(const float* __restrict__ uf) {
    __shared__ float tile[32][33];
    int b = blockIdx.z, c0 = blockIdx.y * 32, i0 = blockIdx.x * 32;
    const float* src = uf + (size_t)b * CH * NPTS;
    for (int r = threadIdx.y; r < 32; r += 8)
        tile[r][threadIdx.x] = src[(size_t)(c0 + r) * NPTS + i0 + threadIdx.x];
    __syncthreads();
    __half* dst = g_Xh + (size_t)b * NPTS * K1;
    for (int r = threadIdx.y; r < 32; r += 8)
        dst[(size_t)(i0 + r) * K1 + 256 + c0 + threadIdx.x] = __float2half_rn(tile[threadIdx.x][r]);
}

// ---------------- fp16 mma GEMM, 128x128 tile, TK=64, 2-stage, 2 blocks/SM ----------------
#define HS      72               // smem row stride in halves (64 data + 8 pad)
#define ATILE_B (128 * HS * 2)   // 18432 bytes
#define STAGE_B (2 * ATILE_B)    // 36864 bytes (A + B)
#define GEMM_SMEM (2 * STAGE_B + 1024)

template<int KDIM, bool FUSE>
__global__ void __launch_bounds__(256, 2) gemm_h(const __half* __restrict__ Ag,
                                                 const __half* __restrict__ Bg,
                                                 __half* __restrict__ Dg,
                                                 float* __restrict__ sums,
                                                 float* __restrict__ sqs) {
    extern __shared__ char smc[];
    const uint32_t sbase = smem_u32(smc);
    float* ssum = (float*)(smc + 2 * STAGE_B);
    float* ssq  = ssum + 128;

    const int tid = threadIdx.x;
    const int wid = tid >> 5, l = tid & 31;
    const int wy = wid >> 2, wx = wid & 3;
    const int g = l >> 2, c4 = l & 3;
    const int lr = l & 7, sel = l >> 3;
    const int b = blockIdx.z;
    const int i0 = blockIdx.x * 128, o0 = blockIdx.y * 128;

    if (tid < 128) { ssum[tid] = 0.f; ssq[tid] = 0.f; }

    const __half* Abase = Ag + ((size_t)b * NPTS + i0) * KDIM;
    const __half* Bbase = Bg + (size_t)o0 * KDIM;

    float acc[4][4][4];
    #pragma unroll
    for (int mi = 0; mi < 4; mi++)
        #pragma unroll
        for (int ni = 0; ni < 4; ni++)
            #pragma unroll
            for (int t = 0; t < 4; t++) acc[mi][ni][t] = 0.f;

    const int rb = tid >> 3, qq = tid & 7;
    const int NC = KDIM / 64;

    uint4 areg[4], screg, shreg;

    auto loadB = [&](int c, int s) {
        int k0 = c * 64;
        uint32_t offB = sbase + s * STAGE_B + ATILE_B;
        const __half* Bb = Bbase + k0;
        #pragma unroll
        for (int it = 0; it < 4; it++) {
            int r = rb + it * 32;
            cp16(offB + r * (HS * 2) + qq * 16, Bb + (size_t)r * KDIM + qq * 8);
        }
        asm volatile("cp.async.commit_group;" ::: "memory");
    };
    auto loadA_cp = [&](int c, int s) {
        int k0 = c * 64;
        uint32_t offA = sbase + s * STAGE_B;
        const __half* Ab = Abase + k0;
        #pragma unroll
        for (int it = 0; it < 4; it++) {
            int r = rb + it * 32;
            cp16(offA + r * (HS * 2) + qq * 16, Ab + (size_t)r * KDIM + qq * 8);
        }
    };
    auto ldgA = [&](int c) {
        int k0 = c * 64;
        #pragma unroll
        for (int it = 0; it < 4; it++)
            areg[it] = *(const uint4*)(Abase + (size_t)(rb + it * 32) * KDIM + k0 + qq * 8);
        screg = *(const uint4*)(g_sc1h + k0 + qq * 8);
        shreg = *(const uint4*)(g_sh1h + k0 + qq * 8);
    };
    auto stsA = [&](int s) {
        const __half2 z2 = __float2half2_rn(0.f);
        union { uint4 u; __half2 h[4]; } sc, sh;
        sc.u = screg; sh.u = shreg;
        #pragma unroll
        for (int it = 0; it < 4; it++) {
            int r = rb + it * 32;
            union { uint4 u; __half2 h[4]; } v;
            v.u = areg[it];
            #pragma unroll
            for (int j = 0; j < 4; j++)
                v.h[j] = __hmax2(__hfma2(v.h[j], sc.h[j], sh.h[j]), z2);
            *(uint4*)(smc + s * STAGE_B + r * (HS * 2) + qq * 16) = v.u;
        }
    };

    const uint32_t aLane = ((uint32_t)(wy * 64 + lr + ((sel & 1) << 3)) * HS + ((sel >> 1) << 3)) * 2;
    const uint32_t bLane = ((uint32_t)(wx * 32 + lr + ((sel >> 1) << 3)) * HS + ((sel & 1) << 3)) * 2;

    if (FUSE) { ldgA(0); stsA(0); } else { loadA_cp(0, 0); }
    loadB(0, 0);
    if (NC > 1) {
        if (FUSE) { ldgA(1); stsA(1); } else { loadA_cp(1, 1); }
        loadB(1, 1);
    }

    for (int c = 0; c < NC; c++) {
        if (c + 1 < NC) {
            asm volatile("cp.async.wait_group 1;" ::: "memory");
        } else {
            asm volatile("cp.async.wait_group 0;" ::: "memory");
        }
        __syncthreads();

        if (FUSE && c + 2 < NC) ldgA(c + 2);

        uint32_t sA = sbase + (c & 1) * STAGE_B;
        uint32_t sB = sA + ATILE_B;
        #pragma unroll
        for (int kk16 = 0; kk16 < 4; kk16++) {
            uint32_t koff = kk16 * 32;
            uint32_t af[4][4], bf[4][2];
            #pragma unroll
            for (int mi = 0; mi < 4; mi++)
                ldm_x4(af[mi], sA + aLane + mi * (16 * HS * 2) + koff);
            #pragma unroll
            for (int nip = 0; nip < 2; nip++) {
                uint32_t r[4];
                ldm_x4(r, sB + bLane + nip * (16 * HS * 2) + koff);
                bf[2 * nip][0] = r[0]; bf[2 * nip][1] = r[1];
                bf[2 * nip + 1][0] = r[2]; bf[2 * nip + 1][1] = r[3];
            }
            #pragma unroll
            for (int mi = 0; mi < 4; mi++)
                #pragma unroll
                for (int ni = 0; ni < 4; ni++)
                    mma_f16(acc[mi][ni], af[mi], bf[ni]);
        }
        __syncthreads();
        if (c + 2 < NC) {
            int s = (c + 2) & 1;
            if (FUSE) stsA(s); else loadA_cp(c + 2, s);
            loadB(c + 2, s);
        }
    }

    #pragma unroll
    for (int mi = 0; mi < 4; mi++) {
        int row0 = i0 + wy * 64 + mi * 16 + g;
        #pragma unroll
        for (int ni = 0; ni < 4; ni++) {
            int col = o0 + wx * 32 + ni * 8 + 2 * c4;
            *(__half2*)(Dg + ((size_t)b * NPTS + row0) * CH + col) =
                __floats2half2_rn(acc[mi][ni][0], acc[mi][ni][1]);
            *(__half2*)(Dg + ((size_t)b * NPTS + row0 + 8) * CH + col) =
                __floats2half2_rn(acc[mi][ni][2], acc[mi][ni][3]);
        }
    }
    #pragma unroll
    for (int ni = 0; ni < 4; ni++) {
        float s0 = 0.f, s1 = 0.f, q0 = 0.f, q1 = 0.f;
        #pragma unroll
        for (int mi = 0; mi < 4; mi++) {
            const float* a = acc[mi][ni];
            s0 += a[0] + a[2]; s1 += a[1] + a[3];
            q0 += a[0] * a[0] + a[2] * a[2];
            q1 += a[1] * a[1] + a[3] * a[3];
        }
        int lc = wx * 32 + ni * 8 + 2 * c4;
        atomicAdd(&ssum[lc], s0); atomicAdd(&ssum[lc + 1], s1);
        atomicAdd(&ssq[lc], q0);  atomicAdd(&ssq[lc + 1], q1);
    }
    __syncthreads();
    if (tid < 128) {
        atomicAdd(&sums[o0 + tid], ssum[tid]);
        atomicAdd(&sqs[o0 + tid], ssq[tid]);
    }
}

// ---------------- finalize BN params ----------------
__global__ void finalize_kernel(const float* __restrict__ ga, const float* __restrict__ be,
                                const float* __restrict__ sums, const float* __restrict__ sqs,
                                float* __restrict__ scale, float* __restrict__ shift,
                                __half* __restrict__ sch, __half* __restrict__ shh) {
    int o = threadIdx.x;
    float inv = 1.0f / (float)(BB * NPTS);
    float mean = sums[o] * inv;
    float var = sqs[o] * inv - mean * mean;
    float sc = ga[o] * rsqrtf(var + BN_EPS);
    float sh = be[o] - mean * sc;
    scale[o] = sc; shift[o] = sh;
    sch[o] = __float2half_rn(sc);
    shh[o] = __float2half_rn(sh);
}

// ---------------- final: BN2 + ReLU + transpose half(b,i,o) -> f32 (b,o,i) ----------------
__global__ void out_kernel(float* __restrict__ out) {
    __shared__ float tile[32][33];
    int b = blockIdx.z, i0 = blockIdx.x * 32, o0 = blockIdx.y * 32;
    const __half* src = g_Y2h + (size_t)b * NPTS * CH;
    for (int r = threadIdx.y; r < 32; r += 8)
        tile[r][threadIdx.x] = __half2float(src[(size_t)(i0 + r) * CH + o0 + threadIdx.x]);
    __syncthreads();
    float* dst = out + (size_t)b * CH * NPTS;
    for (int r = threadIdx.y; r < 32; r += 8) {
        int o = o0 + r;
        float v = fmaxf(fmaf(tile[threadIdx.x][r], g_scale2[o], g_shift2[o]), 0.f);
        dst[(size_t)o * NPTS + i0 + threadIdx.x] = v;
    }
}

// ---------------- launch ----------------
extern "C" void kernel_launch(void* const* d_in, const int* in_sizes, int n_in,
                              void* d_out, int out_size) {
    const float* unknown = (const float*)d_in[0];
    const float* known   = (const float*)d_in[1];
    const float* uf      = (const float*)d_in[2];
    const float* kf      = (const float*)d_in[3];
    const float* W1      = (const float*)d_in[4];
    const float* g1      = (const float*)d_in[5];
    const float* be1     = (const float*)d_in[6];
    const float* W2      = (const float*)d_in[7];
    const float* g2      = (const float*)d_in[8];
    const float* be2     = (const float*)d_in[9];
    float* out = (float*)d_out;

    cudaFuncSetAttribute((gemm_h<K1, false>), cudaFuncAttributeMaxDynamicSharedMemorySize, GEMM_SMEM);
    cudaFuncSetAttribute((gemm_h<CH, true>),  cudaFuncAttributeMaxDynamicSharedMemorySize, GEMM_SMEM);

    __half *pXh, *pW1h, *pW2h, *pHh, *pY2h, *psc1h, *psh1h, *psc2h, *psh2h;
    float *ps1, *pq1, *ps2, *pq2, *psc2, *psh2, *psc1f, *psh1f;
    cudaGetSymbolAddress((void**)&pXh, g_Xh);
    cudaGetSymbolAddress((void**)&pW1h, g_W1h);
    cudaGetSymbolAddress((void**)&pW2h, g_W2h);
    cudaGetSymbolAddress((void**)&pHh, g_Hh);
    cudaGetSymbolAddress((void**)&pY2h, g_Y2h);
    cudaGetSymbolAddress((void**)&ps1, g_sum1);
    cudaGetSymbolAddress((void**)&pq1, g_sq1);
    cudaGetSymbolAddress((void**)&ps2, g_sum2);
    cudaGetSymbolAddress((void**)&pq2, g_sq2);
    cudaGetSymbolAddress((void**)&psc2, g_scale2);
    cudaGetSymbolAddress((void**)&psh2, g_shift2);
    cudaGetSymbolAddress((void**)&psc1f, g_scale1_f);
    cudaGetSymbolAddress((void**)&psh1f, g_shift1_f);
    cudaGetSymbolAddress((void**)&psc1h, g_sc1h);
    cudaGetSymbolAddress((void**)&psh1h, g_sh1h);
    cudaGetSymbolAddress((void**)&psc2h, g_sc2h);
    cudaGetSymbolAddress((void**)&psh2h, g_sh2h);

    // Launch order chosen so launch #6 (ncu -s 5 -c 1) is gemm1.
    prep_kernel<<<CH * K1 / 256 + CH * CH / 256 + 1, 256>>>(W1, W2);            // 1
    nn_kernel<<<dim3(NPTS / 256, BB), 256>>>(unknown, known);                    // 2
    kft_kernel<<<dim3(MPTS / 32, CH / 32, BB), dim3(32, 8)>>>(kf);               // 3
    gather_kernel<<<dim3(NPTS / 4, BB), 256>>>();                                // 4
    uft_kernel<<<dim3(NPTS / 32, CH / 32, BB), dim3(32, 8)>>>(uf);               // 5
    gemm_h<K1, false><<<dim3(NPTS / 128, CH / 128, BB), 256, GEMM_SMEM>>>(       // 6 <- profiled
        pXh, pW1h, pHh, ps1, pq1);
    finalize_kernel<<<1, 256>>>(g1, be1, ps1, pq1, psc1f, psh1f, psc1h, psh1h);  // 7
    gemm_h<CH, true><<<dim3(NPTS / 128, CH / 128, BB), 256, GEMM_SMEM>>>(        // 8
        pHh, pW2h, pY2h, ps2, pq2);
    finalize_kernel<<<1, 256>>>(g2, be2, ps2, pq2, psc2, psh2, psc2h, psh2h);    // 9
    out_kernel<<<dim3(NPTS / 32, CH / 32, BB), dim3(32, 8)>>>(out);              // 10
}

// round 8
// speedup vs baseline: 3.5647x; 1.0162x over previous
#include <cuda_runtime.h>
#include <cuda_fp16.h>
#include <cstdint>

#define BB   16
#define NPTS 4096
#define MPTS 1024
#define CH   256
#define K1   512
#define BN_EPS 1e-5f

// ---------------- scratch ----------------
__device__ __align__(16) __half g_kft[(size_t)BB * MPTS * CH];   // known_feats^T (b,m,c) half
__device__ __align__(16) __half g_Xu[(size_t)BB * NPTS * CH];    // uf^T (b,i,c) half (stride 256)
__device__ __align__(16) __half g_Hh[(size_t)BB * NPTS * CH];    // conv1 raw out (b,i,o) half
__device__ __align__(16) __half g_Y2h[(size_t)BB * NPTS * CH];   // conv2 raw out (b,i,o) half
__device__ __align__(16) __half g_W1h[CH * K1];
__device__ __align__(16) __half g_W2h[CH * CH];
__device__ int   g_idx3[BB * NPTS * 3];
__device__ float g_w3[BB * NPTS * 3];
__device__ float g_sum1[CH], g_sq1[CH], g_sum2[CH], g_sq2[CH];
__device__ float g_scale2[CH], g_shift2[CH];
__device__ float g_scale1_f[CH], g_shift1_f[CH];
__device__ __align__(16) __half g_sc1h[CH], g_sh1h[CH];
__device__ __align__(16) __half g_sc2h[CH], g_sh2h[CH];

// ---------------- helpers ----------------
__device__ __forceinline__ void cp16(uint32_t saddr, const void* g) {
    asm volatile("cp.async.ca.shared.global [%0], [%1], 16;" :: "r"(saddr), "l"(g));
}
__device__ __forceinline__ uint32_t smem_u32(const void* p) {
    uint32_t a;
    asm("{ .reg .u64 t; cvta.to.shared.u64 t, %1; cvt.u32.u64 %0, t; }" : "=r"(a) : "l"(p));
    return a;
}
__device__ __forceinline__ void ldm_x4(uint32_t* r, uint32_t addr) {
    asm volatile("ldmatrix.sync.aligned.m8n8.x4.shared.b16 {%0,%1,%2,%3}, [%4];"
                 : "=r"(r[0]), "=r"(r[1]), "=r"(r[2]), "=r"(r[3]) : "r"(addr));
}
__device__ __forceinline__ void mma_f16(float* d, const uint32_t* a, const uint32_t* b) {
    asm volatile(
        "mma.sync.aligned.m16n8k16.row.col.f32.f16.f16.f32 "
        "{%0,%1,%2,%3}, {%4,%5,%6,%7}, {%8,%9}, {%0,%1,%2,%3};"
        : "+f"(d[0]), "+f"(d[1]), "+f"(d[2]), "+f"(d[3])
        : "r"(a[0]), "r"(a[1]), "r"(a[2]), "r"(a[3]), "r"(b[0]), "r"(b[1]));
}

// ---------------- prep: weight->half + stats zero ----------------
__global__ void prep_kernel(const float* __restrict__ W1, const float* __restrict__ W2) {
    int blk = blockIdx.x;
    int t = threadIdx.x;
    if (blk < CH * K1 / 256) {
        int i = blk * 256 + t;
        g_W1h[i] = __float2half_rn(W1[i]);
    } else if (blk < CH * K1 / 256 + CH * CH / 256) {
        int i = (blk - CH * K1 / 256) * 256 + t;
        g_W2h[i] = __float2half_rn(W2[i]);
    } else {
        g_sum1[t] = 0.f; g_sq1[t] = 0.f; g_sum2[t] = 0.f; g_sq2[t] = 0.f;
    }
}

// ---------------- 3-NN + weights ----------------
__global__ void nn_kernel(const float* __restrict__ unknown, const float* __restrict__ known) {
    __shared__ float4 sk[MPTS];
    int b = blockIdx.y;
    const float* kb = known + (size_t)b * MPTS * 3;
    for (int j = threadIdx.x; j < MPTS; j += blockDim.x)
        sk[j] = make_float4(kb[j * 3 + 0], kb[j * 3 + 1], kb[j * 3 + 2], 0.f);
    __syncthreads();
    int i = blockIdx.x * blockDim.x + threadIdx.x;
    const float* u = unknown + ((size_t)b * NPTS + i) * 3;
    float ux = u[0], uy = u[1], uz = u[2];
    float b0 = 3.4e38f, b1 = 3.4e38f, b2 = 3.4e38f;
    int i0 = 0, i1 = 0, i2 = 0;
    #pragma unroll 4
    for (int j = 0; j < MPTS; j++) {
        float4 k4 = sk[j];
        float dx = ux - k4.x, dy = uy - k4.y, dz = uz - k4.z;
        float d = dx * dx + dy * dy + dz * dz;
        if (d < b2) {
            if (d < b1) {
                if (d < b0) { b2 = b1; i2 = i1; b1 = b0; i1 = i0; b0 = d; i0 = j; }
                else        { b2 = b1; i2 = i1; b1 = d;  i1 = j; }
            } else          { b2 = d;  i2 = j; }
        }
    }
    float r0 = 1.0f / (b0 + 1e-8f), r1 = 1.0f / (b1 + 1e-8f), r2 = 1.0f / (b2 + 1e-8f);
    float inv = 1.0f / (r0 + r1 + r2);
    size_t base = ((size_t)b * NPTS + i) * 3;
    g_idx3[base] = i0; g_idx3[base + 1] = i1; g_idx3[base + 2] = i2;
    g_w3[base] = r0 * inv; g_w3[base + 1] = r1 * inv; g_w3[base + 2] = r2 * inv;
}

// ---------------- transpose known_feats (b,c,m)->(b,m,c) half ----------------
__global__ void kft_kernel(const float* __restrict__ kf) {
    __shared__ float tile[32][33];
    int b = blockIdx.z, c0 = blockIdx.y * 32, j0 = blockIdx.x * 32;
    const float* src = kf + (size_t)b * CH * MPTS;
    for (int r = threadIdx.y; r < 32; r += 8)
        tile[r][threadIdx.x] = src[(size_t)(c0 + r) * MPTS + j0 + threadIdx.x];
    __syncthreads();
    __half* dst = g_kft + (size_t)b * MPTS * CH;
    for (int r = threadIdx.y; r < 32; r += 8)
        dst[(size_t)(j0 + r) * CH + c0 + threadIdx.x] = __float2half_rn(tile[threadIdx.x][r]);
}

// ---------------- uf transpose -> Xu (b,i,c) half, stride 256 ----------------
__global__ void uft_kernel(const float* __restrict__ uf) {
    __shared__ float tile[32][33];
    int b = blockIdx.z, c0 = blockIdx.y * 32, i0 = blockIdx.x * 32;
    const float* src = uf + (size_t)b * CH * NPTS;
    for (int r = threadIdx.y; r < 32; r += 8)
        tile[r][threadIdx.x] = src[(size_t)(c0 + r) * NPTS + i0 + threadIdx.x];
    __syncthreads();
    __half* dst = g_Xu + (size_t)b * NPTS * CH;
    for (int r = threadIdx.y; r < 32; r += 8)
        dst[(size_t)(i0 + r) * CH + c0 + threadIdx.x] = __float2half_rn(tile[threadIdx.x][r]);
}

// ---------------- shared GEMM geometry ----------------
#define HS      72               // smem row stride in halves (64 data + 8 pad)
#define ATILE_B (128 * HS * 2)   // 18432 bytes
#define STAGE_B (2 * ATILE_B)    // 36864 bytes (A + B)
#define GEMM_SMEM  (2 * STAGE_B + 1024)
#define GEMM1_SMEM (2 * STAGE_B + 1024 + 4096)

// ---------------- GEMM1: A = [3NN-interp(kft) | Xu], B = W1h; D = Hh + stats ----------------
__global__ void __launch_bounds__(256, 2) gemm1_f(__half* __restrict__ Dg,
                                                  float* __restrict__ sums,
                                                  float* __restrict__ sqs) {
    extern __shared__ char smc[];
    const uint32_t sbase = smem_u32(smc);
    float* ssum = (float*)(smc + 2 * STAGE_B);
    float* ssq  = ssum + 128;
    int*   sidx = (int*)(smc + 2 * STAGE_B + 1024);
    float* sw   = (float*)(smc + 2 * STAGE_B + 1024 + 2048);

    const int tid = threadIdx.x;
    const int wid = tid >> 5, l = tid & 31;
    const int wy = wid >> 2, wx = wid & 3;
    const int g = l >> 2, c4 = l & 3;
    const int lr = l & 7, sel = l >> 3;
    const int b = blockIdx.z;
    const int i0 = blockIdx.x * 128, o0 = blockIdx.y * 128;

    if (tid < 128) {
        ssum[tid] = 0.f; ssq[tid] = 0.f;
        size_t base = ((size_t)b * NPTS + i0 + tid) * 3;
        sidx[4 * tid] = g_idx3[base]; sidx[4 * tid + 1] = g_idx3[base + 1];
        sidx[4 * tid + 2] = g_idx3[base + 2];
        sw[4 * tid] = g_w3[base]; sw[4 * tid + 1] = g_w3[base + 1];
        sw[4 * tid + 2] = g_w3[base + 2];
    }
    __syncthreads();

    const __half* Xu = g_Xu + ((size_t)b * NPTS + i0) * CH;
    const __half* Bbase = g_W1h + (size_t)o0 * K1;
    const __half* kftb = g_kft + (size_t)b * MPTS * CH;

    float acc[4][4][4];
    #pragma unroll
    for (int mi = 0; mi < 4; mi++)
        #pragma unroll
        for (int ni = 0; ni < 4; ni++)
            #pragma unroll
            for (int t = 0; t < 4; t++) acc[mi][ni][t] = 0.f;

    const int rb = tid >> 3, qq = tid & 7;
    const int NC = K1 / 64;   // 8: chunks 0-3 interp, 4-7 uf

    uint4 areg[4];

    auto loadB = [&](int c, int s) {
        int k0 = c * 64;
        uint32_t offB = sbase + s * STAGE_B + ATILE_B;
        const __half* Bb = Bbase + k0;
        #pragma unroll
        for (int it = 0; it < 4; it++) {
            int r = rb + it * 32;
            cp16(offB + r * (HS * 2) + qq * 16, Bb + (size_t)r * K1 + qq * 8);
        }
        asm volatile("cp.async.commit_group;" ::: "memory");
    };
    auto ldgA = [&](int c) {
        if (c < 4) {
            int k0 = c * 64 + qq * 8;
            #pragma unroll
            for (int it = 0; it < 4; it++) {
                int r = rb + it * 32;
                int4 jj = *(const int4*)&sidx[4 * r];
                float4 ww = *(const float4*)&sw[4 * r];
                union { uint4 u; __half2 h[4]; } A0, A1, A2, R;
                A0.u = *(const uint4*)(kftb + (size_t)jj.x * CH + k0);
                A1.u = *(const uint4*)(kftb + (size_t)jj.y * CH + k0);
                A2.u = *(const uint4*)(kftb + (size_t)jj.z * CH + k0);
                #pragma unroll
                for (int j = 0; j < 4; j++) {
                    float2 a = __half22float2(A0.h[j]);
                    float2 d = __half22float2(A1.h[j]);
                    float2 e = __half22float2(A2.h[j]);
                    R.h[j] = __floats2half2_rn(ww.x * a.x + ww.y * d.x + ww.z * e.x,
                                               ww.x * a.y + ww.y * d.y + ww.z * e.y);
                }
                areg[it] = R.u;
            }
        } else {
            int k0 = (c - 4) * 64 + qq * 8;
            #pragma unroll
            for (int it = 0; it < 4; it++)
                areg[it] = *(const uint4*)(Xu + (size_t)(rb + it * 32) * CH + k0);
        }
    };
    auto stsA = [&](int s) {
        #pragma unroll
        for (int it = 0; it < 4; it++)
            *(uint4*)(smc + s * STAGE_B + (rb + it * 32) * (HS * 2) + qq * 16) = areg[it];
    };

    const uint32_t aLane = ((uint32_t)(wy * 64 + lr + ((sel & 1) << 3)) * HS + ((sel >> 1) << 3)) * 2;
    const uint32_t bLane = ((uint32_t)(wx * 32 + lr + ((sel >> 1) << 3)) * HS + ((sel & 1) << 3)) * 2;

    ldgA(0); stsA(0); loadB(0, 0);
    ldgA(1); stsA(1); loadB(1, 1);

    for (int c = 0; c < NC; c++) {
        if (c + 1 < NC) {
            asm volatile("cp.async.wait_group 1;" ::: "memory");
        } else {
            asm volatile("cp.async.wait_group 0;" ::: "memory");
        }
        __syncthreads();

        if (c + 2 < NC) ldgA(c + 2);

        uint32_t sA = sbase + (c & 1) * STAGE_B;
        uint32_t sB = sA + ATILE_B;
        #pragma unroll
        for (int kk16 = 0; kk16 < 4; kk16++) {
            uint32_t koff = kk16 * 32;
            uint32_t af[4][4], bf[4][2];
            #pragma unroll
            for (int mi = 0; mi < 4; mi++)
                ldm_x4(af[mi], sA + aLane + mi * (16 * HS * 2) + koff);
            #pragma unroll
            for (int nip = 0; nip < 2; nip++) {
                uint32_t r[4];
                ldm_x4(r, sB + bLane + nip * (16 * HS * 2) + koff);
                bf[2 * nip][0] = r[0]; bf[2 * nip][1] = r[1];
                bf[2 * nip + 1][0] = r[2]; bf[2 * nip + 1][1] = r[3];
            }
            #pragma unroll
            for (int mi = 0; mi < 4; mi++)
                #pragma unroll
                for (int ni = 0; ni < 4; ni++)
                    mma_f16(acc[mi][ni], af[mi], bf[ni]);
        }
        __syncthreads();
        if (c + 2 < NC) {
            int s = (c + 2) & 1;
            stsA(s);
            loadB(c + 2, s);
        }
    }

    #pragma unroll
    for (int mi = 0; mi < 4; mi++) {
        int row0 = i0 + wy * 64 + mi * 16 + g;
        #pragma unroll
        for (int ni = 0; ni < 4; ni++) {
            int col = o0 + wx * 32 + ni * 8 + 2 * c4;
            *(__half2*)(Dg + ((size_t)b * NPTS + row0) * CH + col) =
                __floats2half2_rn(acc[mi][ni][0], acc[mi][ni][1]);
            *(__half2*)(Dg + ((size_t)b * NPTS + row0 + 8) * CH + col) =
                __floats2half2_rn(acc[mi][ni][2], acc[mi][ni][3]);
        }
    }
    #pragma unroll
    for (int ni = 0; ni < 4; ni++) {
        float s0 = 0.f, s1 = 0.f, q0 = 0.f, q1 = 0.f;
        #pragma unroll
        for (int mi = 0; mi < 4; mi++) {
            const float* a = acc[mi][ni];
            s0 += a[0] + a[2]; s1 += a[1] + a[3];
            q0 += a[0] * a[0] + a[2] * a[2];
            q1 += a[1] * a[1] + a[3] * a[3];
        }
        int lc = wx * 32 + ni * 8 + 2 * c4;
        atomicAdd(&ssum[lc], s0); atomicAdd(&ssum[lc + 1], s1);
        atomicAdd(&ssq[lc], q0);  atomicAdd(&ssq[lc + 1], q1);
    }
    __syncthreads();
    if (tid < 128) {
        atomicAdd(&sums[o0 + tid], ssum[tid]);
        atomicAdd(&sqs[o0 + tid], ssq[tid]);
    }
}

// ---------------- GEMM2 (FUSE BN1+ReLU in A-loader), as before ----------------
template<int KDIM>
__global__ void __launch_bounds__(256, 2) gemm_h(const __half* __restrict__ Ag,
                                                 const __half* __restrict__ Bg,
                                                 __half* __restrict__ Dg,
                                                 float* __restrict__ sums,
                                                 float* __restrict__ sqs) {
    extern __shared__ char smc[];
    const uint32_t sbase = smem_u32(smc);
    float* ssum = (float*)(smc + 2 * STAGE_B);
    float* ssq  = ssum + 128;

    const int tid = threadIdx.x;
    const int wid = tid >> 5, l = tid & 31;
    const int wy = wid >> 2, wx = wid & 3;
    const int g = l >> 2, c4 = l & 3;
    const int lr = l & 7, sel = l >> 3;
    const int b = blockIdx.z;
    const int i0 = blockIdx.x * 128, o0 = blockIdx.y * 128;

    if (tid < 128) { ssum[tid] = 0.f; ssq[tid] = 0.f; }

    const __half* Abase = Ag + ((size_t)b * NPTS + i0) * KDIM;
    const __half* Bbase = Bg + (size_t)o0 * KDIM;

    float acc[4][4][4];
    #pragma unroll
    for (int mi = 0; mi < 4; mi++)
        #pragma unroll
        for (int ni = 0; ni < 4; ni++)
            #pragma unroll
            for (int t = 0; t < 4; t++) acc[mi][ni][t] = 0.f;

    const int rb = tid >> 3, qq = tid & 7;
    const int NC = KDIM / 64;

    uint4 areg[4], screg, shreg;

    auto loadB = [&](int c, int s) {
        int k0 = c * 64;
        uint32_t offB = sbase + s * STAGE_B + ATILE_B;
        const __half* Bb = Bbase + k0;
        #pragma unroll
        for (int it = 0; it < 4; it++) {
            int r = rb + it * 32;
            cp16(offB + r * (HS * 2) + qq * 16, Bb + (size_t)r * KDIM + qq * 8);
        }
        asm volatile("cp.async.commit_group;" ::: "memory");
    };
    auto ldgA = [&](int c) {
        int k0 = c * 64;
        #pragma unroll
        for (int it = 0; it < 4; it++)
            areg[it] = *(const uint4*)(Abase + (size_t)(rb + it * 32) * KDIM + k0 + qq * 8);
        screg = *(const uint4*)(g_sc1h + k0 + qq * 8);
        shreg = *(const uint4*)(g_sh1h + k0 + qq * 8);
    };
    auto stsA = [&](int s) {
        const __half2 z2 = __float2half2_rn(0.f);
        union { uint4 u; __half2 h[4]; } sc, sh;
        sc.u = screg; sh.u = shreg;
        #pragma unroll
        for (int it = 0; it < 4; it++) {
            int r = rb + it * 32;
            union { uint4 u; __half2 h[4]; } v;
            v.u = areg[it];
            #pragma unroll
            for (int j = 0; j < 4; j++)
                v.h[j] = __hmax2(__hfma2(v.h[j], sc.h[j], sh.h[j]), z2);
            *(uint4*)(smc + s * STAGE_B + r * (HS * 2) + qq * 16) = v.u;
        }
    };

    const uint32_t aLane = ((uint32_t)(wy * 64 + lr + ((sel & 1) << 3)) * HS + ((sel >> 1) << 3)) * 2;
    const uint32_t bLane = ((uint32_t)(wx * 32 + lr + ((sel >> 1) << 3)) * HS + ((sel & 1) << 3)) * 2;

    ldgA(0); stsA(0); loadB(0, 0);
    ldgA(1); stsA(1); loadB(1, 1);

    for (int c = 0; c < NC; c++) {
        if (c + 1 < NC) {
            asm volatile("cp.async.wait_group 1;" ::: "memory");
        } else {
            asm volatile("cp.async.wait_group 0;" ::: "memory");
        }
        __syncthreads();

        if (c + 2 < NC) ldgA(c + 2);

        uint32_t sA = sbase + (c & 1) * STAGE_B;
        uint32_t sB = sA + ATILE_B;
        #pragma unroll
        for (int kk16 = 0; kk16 < 4; kk16++) {
            uint32_t koff = kk16 * 32;
            uint32_t af[4][4], bf[4][2];
            #pragma unroll
            for (int mi = 0; mi < 4; mi++)
                ldm_x4(af[mi], sA + aLane + mi * (16 * HS * 2) + koff);
            #pragma unroll
            for (int nip = 0; nip < 2; nip++) {
                uint32_t r[4];
                ldm_x4(r, sB + bLane + nip * (16 * HS * 2) + koff);
                bf[2 * nip][0] = r[0]; bf[2 * nip][1] = r[1];
                bf[2 * nip + 1][0] = r[2]; bf[2 * nip + 1][1] = r[3];
            }
            #pragma unroll
            for (int mi = 0; mi < 4; mi++)
                #pragma unroll
                for (int ni = 0; ni < 4; ni++)
                    mma_f16(acc[mi][ni], af[mi], bf[ni]);
        }
        __syncthreads();
        if (c + 2 < NC) {
            int s = (c + 2) & 1;
            stsA(s);
            loadB(c + 2, s);
        }
    }

    #pragma unroll
    for (int mi = 0; mi < 4; mi++) {
        int row0 = i0 + wy * 64 + mi * 16 + g;
        #pragma unroll
        for (int ni = 0; ni < 4; ni++) {
            int col = o0 + wx * 32 + ni * 8 + 2 * c4;
            *(__half2*)(Dg + ((size_t)b * NPTS + row0) * CH + col) =
                __floats2half2_rn(acc[mi][ni][0], acc[mi][ni][1]);
            *(__half2*)(Dg + ((size_t)b * NPTS + row0 + 8) * CH + col) =
                __floats2half2_rn(acc[mi][ni][2], acc[mi][ni][3]);
        }
    }
    #pragma unroll
    for (int ni = 0; ni < 4; ni++) {
        float s0 = 0.f, s1 = 0.f, q0 = 0.f, q1 = 0.f;
        #pragma unroll
        for (int mi = 0; mi < 4; mi++) {
            const float* a = acc[mi][ni];
            s0 += a[0] + a[2]; s1 += a[1] + a[3];
            q0 += a[0] * a[0] + a[2] * a[2];
            q1 += a[1] * a[1] + a[3] * a[3];
        }
        int lc = wx * 32 + ni * 8 + 2 * c4;
        atomicAdd(&ssum[lc], s0); atomicAdd(&ssum[lc + 1], s1);
        atomicAdd(&ssq[lc], q0);  atomicAdd(&ssq[lc + 1], q1);
    }
    __syncthreads();
    if (tid < 128) {
        atomicAdd(&sums[o0 + tid], ssum[tid]);
        atomicAdd(&sqs[o0 + tid], ssq[tid]);
    }
}

// ---------------- finalize BN params ----------------
__global__ void finalize_kernel(const float* __restrict__ ga, const float* __restrict__ be,
                                const float* __restrict__ sums, const float* __restrict__ sqs,
                                float* __restrict__ scale, float* __restrict__ shift,
                                __half* __restrict__ sch, __half* __restrict__ shh) {
    int o = threadIdx.x;
    float inv = 1.0f / (float)(BB * NPTS);
    float mean = sums[o] * inv;
    float var = sqs[o] * inv - mean * mean;
    float sc = ga[o] * rsqrtf(var + BN_EPS);
    float sh = be[o] - mean * sc;
    scale[o] = sc; shift[o] = sh;
    sch[o] = __float2half_rn(sc);
    shh[o] = __float2half_rn(sh);
}

// ---------------- final: BN2 + ReLU + transpose half(b,i,o) -> f32 (b,o,i) ----------------
__global__ void out_kernel(float* __restrict__ out) {
    __shared__ float tile[32][33];
    int b = blockIdx.z, i0 = blockIdx.x * 32, o0 = blockIdx.y * 32;
    const __half* src = g_Y2h + (size_t)b * NPTS * CH;
    for (int r = threadIdx.y; r < 32; r += 8)
        tile[r][threadIdx.x] = __half2float(src[(size_t)(i0 + r) * CH + o0 + threadIdx.x]);
    __syncthreads();
    float* dst = out + (size_t)b * CH * NPTS;
    for (int r = threadIdx.y; r < 32; r += 8) {
        int o = o0 + r;
        float v = fmaxf(fmaf(tile[threadIdx.x][r], g_scale2[o], g_shift2[o]), 0.f);
        dst[(size_t)o * NPTS + i0 + threadIdx.x] = v;
    }
}

// ---------------- launch ----------------
extern "C" void kernel_launch(void* const* d_in, const int* in_sizes, int n_in,
                              void* d_out, int out_size) {
    const float* unknown = (const float*)d_in[0];
    const float* known   = (const float*)d_in[1];
    const float* uf      = (const float*)d_in[2];
    const float* kf      = (const float*)d_in[3];
    const float* W1      = (const float*)d_in[4];
    const float* g1      = (const float*)d_in[5];
    const float* be1     = (const float*)d_in[6];
    const float* W2      = (const float*)d_in[7];
    const float* g2      = (const float*)d_in[8];
    const float* be2     = (const float*)d_in[9];
    float* out = (float*)d_out;

    cudaFuncSetAttribute(gemm1_f, cudaFuncAttributeMaxDynamicSharedMemorySize, GEMM1_SMEM);
    cudaFuncSetAttribute(gemm_h<CH>, cudaFuncAttributeMaxDynamicSharedMemorySize, GEMM_SMEM);

    __half *pHh, *pY2h, *pW2h, *psc1h, *psh1h, *psc2h, *psh2h;
    float *ps1, *pq1, *ps2, *pq2, *psc2, *psh2, *psc1f, *psh1f;
    cudaGetSymbolAddress((void**)&pHh, g_Hh);
    cudaGetSymbolAddress((void**)&pY2h, g_Y2h);
    cudaGetSymbolAddress((void**)&pW2h, g_W2h);
    cudaGetSymbolAddress((void**)&ps1, g_sum1);
    cudaGetSymbolAddress((void**)&pq1, g_sq1);
    cudaGetSymbolAddress((void**)&ps2, g_sum2);
    cudaGetSymbolAddress((void**)&pq2, g_sq2);
    cudaGetSymbolAddress((void**)&psc2, g_scale2);
    cudaGetSymbolAddress((void**)&psh2, g_shift2);
    cudaGetSymbolAddress((void**)&psc1f, g_scale1_f);
    cudaGetSymbolAddress((void**)&psh1f, g_shift1_f);
    cudaGetSymbolAddress((void**)&psc1h, g_sc1h);
    cudaGetSymbolAddress((void**)&psh1h, g_sh1h);
    cudaGetSymbolAddress((void**)&psc2h, g_sc2h);
    cudaGetSymbolAddress((void**)&psh2h, g_sh2h);

    prep_kernel<<<CH * K1 / 256 + CH * CH / 256 + 1, 256>>>(W1, W2);
    nn_kernel<<<dim3(NPTS / 256, BB), 256>>>(unknown, known);
    kft_kernel<<<dim3(MPTS / 32, CH / 32, BB), dim3(32, 8)>>>(kf);
    uft_kernel<<<dim3(NPTS / 32, CH / 32, BB), dim3(32, 8)>>>(uf);
    gemm1_f<<<dim3(NPTS / 128, CH / 128, BB), 256, GEMM1_SMEM>>>(pHh, ps1, pq1);
    finalize_kernel<<<1, 256>>>(g1, be1, ps1, pq1, psc1f, psh1f, psc1h, psh1h);
    gemm_h<CH><<<dim3(NPTS / 128, CH / 128, BB), 256, GEMM_SMEM>>>(pHh, pW2h, pY2h, ps2, pq2);
    finalize_kernel<<<1, 256>>>(g2, be2, ps2, pq2, psc2, psh2, psc2h, psh2h);
    out_kernel<<<dim3(NPTS / 32, CH / 32, BB), dim3(32, 8)>>>(out);
}

// round 9
// speedup vs baseline: 3.8996x; 1.0940x over previous
#include <cuda_runtime.h>
#include <cuda_fp16.h>
#include <cstdint>

#define BB   16
#define NPTS 4096
#define MPTS 1024
#define CH   256
#define K1   512
#define BN_EPS 1e-5f

// ---------------- scratch ----------------
__device__ __align__(16) __half g_kft[(size_t)BB * MPTS * CH];   // known_feats^T (b,m,c) half
__device__ __align__(16) __half g_Xc[(size_t)BB * CH * NPTS];    // uf (b,c,i) half (same layout as input)
__device__ __align__(16) __half g_Hh[(size_t)BB * NPTS * CH];    // conv1 raw out (b,i,o) half
__device__ __align__(16) __half g_Y2h[(size_t)BB * NPTS * CH];   // conv2 raw out (b,i,o) half
__device__ __align__(16) __half g_W1h[CH * K1];
__device__ __align__(16) __half g_W2h[CH * CH];
__device__ int   g_idx3[BB * NPTS * 3];
__device__ float g_w3[BB * NPTS * 3];
__device__ float g_sum1[CH], g_sq1[CH], g_sum2[CH], g_sq2[CH];
__device__ float g_scale2[CH], g_shift2[CH];
__device__ float g_scale1_f[CH], g_shift1_f[CH];
__device__ __align__(16) __half g_sc1h[CH], g_sh1h[CH];
__device__ __align__(16) __half g_sc2h[CH], g_sh2h[CH];

// ---------------- helpers ----------------
__device__ __forceinline__ void cp16(uint32_t saddr, const void* g) {
    asm volatile("cp.async.ca.shared.global [%0], [%1], 16;" :: "r"(saddr), "l"(g));
}
__device__ __forceinline__ uint32_t smem_u32(const void* p) {
    uint32_t a;
    asm("{ .reg .u64 t; cvta.to.shared.u64 t, %1; cvt.u32.u64 %0, t; }" : "=r"(a) : "l"(p));
    return a;
}
__device__ __forceinline__ void ldm_x4(uint32_t* r, uint32_t addr) {
    asm volatile("ldmatrix.sync.aligned.m8n8.x4.shared.b16 {%0,%1,%2,%3}, [%4];"
                 : "=r"(r[0]), "=r"(r[1]), "=r"(r[2]), "=r"(r[3]) : "r"(addr));
}
__device__ __forceinline__ void ldm_x4t(uint32_t* r, uint32_t addr) {
    asm volatile("ldmatrix.sync.aligned.m8n8.x4.trans.shared.b16 {%0,%1,%2,%3}, [%4];"
                 : "=r"(r[0]), "=r"(r[1]), "=r"(r[2]), "=r"(r[3]) : "r"(addr));
}
__device__ __forceinline__ void mma_f16(float* d, const uint32_t* a, const uint32_t* b) {
    asm volatile(
        "mma.sync.aligned.m16n8k16.row.col.f32.f16.f16.f32 "
        "{%0,%1,%2,%3}, {%4,%5,%6,%7}, {%8,%9}, {%0,%1,%2,%3};"
        : "+f"(d[0]), "+f"(d[1]), "+f"(d[2]), "+f"(d[3])
        : "r"(a[0]), "r"(a[1]), "r"(a[2]), "r"(a[3]), "r"(b[0]), "r"(b[1]));
}

// ---------------- prep: weight->half + stats zero ----------------
__global__ void prep_kernel(const float* __restrict__ W1, const float* __restrict__ W2) {
    int blk = blockIdx.x;
    int t = threadIdx.x;
    if (blk < CH * K1 / 256) {
        int i = blk * 256 + t;
        g_W1h[i] = __float2half_rn(W1[i]);
    } else if (blk < CH * K1 / 256 + CH * CH / 256) {
        int i = (blk - CH * K1 / 256) * 256 + t;
        g_W2h[i] = __float2half_rn(W2[i]);
    } else {
        g_sum1[t] = 0.f; g_sq1[t] = 0.f; g_sum2[t] = 0.f; g_sq2[t] = 0.f;
    }
}

// ---------------- elementwise uf f32 -> half (layout preserved) ----------------
__global__ void cvt_kernel(const float* __restrict__ uf) {
    size_t q = (size_t)blockIdx.x * 256 + threadIdx.x;   // one float4
    float4 v = ((const float4*)uf)[q];
    union { __half2 h[2]; uint2 u; } cv;
    cv.h[0] = __floats2half2_rn(v.x, v.y);
    cv.h[1] = __floats2half2_rn(v.z, v.w);
    *(uint2*)(g_Xc + q * 4) = cv.u;
}

// ---------------- 3-NN + weights ----------------
__global__ void nn_kernel(const float* __restrict__ unknown, const float* __restrict__ known) {
    __shared__ float4 sk[MPTS];
    int b = blockIdx.y;
    const float* kb = known + (size_t)b * MPTS * 3;
    for (int j = threadIdx.x; j < MPTS; j += blockDim.x)
        sk[j] = make_float4(kb[j * 3 + 0], kb[j * 3 + 1], kb[j * 3 + 2], 0.f);
    __syncthreads();
    int i = blockIdx.x * blockDim.x + threadIdx.x;
    const float* u = unknown + ((size_t)b * NPTS + i) * 3;
    float ux = u[0], uy = u[1], uz = u[2];
    float b0 = 3.4e38f, b1 = 3.4e38f, b2 = 3.4e38f;
    int i0 = 0, i1 = 0, i2 = 0;
    #pragma unroll 4
    for (int j = 0; j < MPTS; j++) {
        float4 k4 = sk[j];
        float dx = ux - k4.x, dy = uy - k4.y, dz = uz - k4.z;
        float d = dx * dx + dy * dy + dz * dz;
        if (d < b2) {
            if (d < b1) {
                if (d < b0) { b2 = b1; i2 = i1; b1 = b0; i1 = i0; b0 = d; i0 = j; }
                else        { b2 = b1; i2 = i1; b1 = d;  i1 = j; }
            } else          { b2 = d;  i2 = j; }
        }
    }
    float r0 = 1.0f / (b0 + 1e-8f), r1 = 1.0f / (b1 + 1e-8f), r2 = 1.0f / (b2 + 1e-8f);
    float inv = 1.0f / (r0 + r1 + r2);
    size_t base = ((size_t)b * NPTS + i) * 3;
    g_idx3[base] = i0; g_idx3[base + 1] = i1; g_idx3[base + 2] = i2;
    g_w3[base] = r0 * inv; g_w3[base + 1] = r1 * inv; g_w3[base + 2] = r2 * inv;
}

// ---------------- transpose known_feats (b,c,m)->(b,m,c) half ----------------
__global__ void kft_kernel(const float* __restrict__ kf) {
    __shared__ float tile[32][33];
    int b = blockIdx.z, c0 = blockIdx.y * 32, j0 = blockIdx.x * 32;
    const float* src = kf + (size_t)b * CH * MPTS;
    for (int r = threadIdx.y; r < 32; r += 8)
        tile[r][threadIdx.x] = src[(size_t)(c0 + r) * MPTS + j0 + threadIdx.x];
    __syncthreads();
    __half* dst = g_kft + (size_t)b * MPTS * CH;
    for (int r = threadIdx.y; r < 32; r += 8)
        dst[(size_t)(j0 + r) * CH + c0 + threadIdx.x] = __float2half_rn(tile[threadIdx.x][r]);
}

// ---------------- shared GEMM geometry ----------------
#define HS      72               // [i][k] row stride in halves (64 data + 8 pad)
#define RS2H    136              // [k][i] row stride in halves (128 data + 8 pad)
#define ATILE_B (128 * HS * 2)   // 18432 bytes (>= 64*RS2H*2 = 17408)
#define STAGE_B (2 * ATILE_B)
#define GEMM_SMEM  (2 * STAGE_B + 1024)
#define GEMM1_SMEM (2 * STAGE_B + 1024 + 4096)

// ---------------- GEMM1: A = [3NN-interp(kft) | uf-trans], B = W1h; D = Hh + stats ----------------
__global__ void __launch_bounds__(256, 2) gemm1_f(__half* __restrict__ Dg,
                                                  float* __restrict__ sums,
                                                  float* __restrict__ sqs) {
    extern __shared__ char smc[];
    const uint32_t sbase = smem_u32(smc);
    float* ssum = (float*)(smc + 2 * STAGE_B);
    float* ssq  = ssum + 128;
    int*   sidx = (int*)(smc + 2 * STAGE_B + 1024);
    float* sw   = (float*)(smc + 2 * STAGE_B + 1024 + 2048);

    const int tid = threadIdx.x;
    const int wid = tid >> 5, l = tid & 31;
    const int wy = wid >> 2, wx = wid & 3;
    const int g = l >> 2, c4 = l & 3;
    const int lr = l & 7, sel = l >> 3;
    const int b = blockIdx.z;
    const int i0 = blockIdx.x * 128, o0 = blockIdx.y * 128;

    if (tid < 128) {
        ssum[tid] = 0.f; ssq[tid] = 0.f;
        size_t base = ((size_t)b * NPTS + i0 + tid) * 3;
        sidx[4 * tid] = g_idx3[base]; sidx[4 * tid + 1] = g_idx3[base + 1];
        sidx[4 * tid + 2] = g_idx3[base + 2];
        sw[4 * tid] = g_w3[base]; sw[4 * tid + 1] = g_w3[base + 1];
        sw[4 * tid + 2] = g_w3[base + 2];
    }
    __syncthreads();

    const __half* Xc = g_Xc + (size_t)b * CH * NPTS;          // (c, i) half
    const __half* Bbase = g_W1h + (size_t)o0 * K1;
    const __half* kftb = g_kft + (size_t)b * MPTS * CH;

    float acc[4][4][4];
    #pragma unroll
    for (int mi = 0; mi < 4; mi++)
        #pragma unroll
        for (int ni = 0; ni < 4; ni++)
            #pragma unroll
            for (int t = 0; t < 4; t++) acc[mi][ni][t] = 0.f;

    const int rb = tid >> 3, qq = tid & 7;
    const int NC = K1 / 64;   // 8: chunks 0-3 interp, 4-7 uf (direct [k][i])

    uint4 areg[4];

    auto loadB = [&](int c, int s) {
        int k0 = c * 64;
        uint32_t offB = sbase + s * STAGE_B + ATILE_B;
        const __half* Bb = Bbase + k0;
        #pragma unroll
        for (int it = 0; it < 4; it++) {
            int r = rb + it * 32;
            cp16(offB + r * (HS * 2) + qq * 16, Bb + (size_t)r * K1 + qq * 8);
        }
        asm volatile("cp.async.commit_group;" ::: "memory");
    };
    auto ldgA = [&](int c) {   // interp chunks only (c<4)
        int k0 = c * 64 + qq * 8;
        #pragma unroll
        for (int it = 0; it < 4; it++) {
            int r = rb + it * 32;
            int4 jj = *(const int4*)&sidx[4 * r];
            float4 ww = *(const float4*)&sw[4 * r];
            union { uint4 u; __half2 h[4]; } A0, A1, A2, R;
            A0.u = *(const uint4*)(kftb + (size_t)jj.x * CH + k0);
            A1.u = *(const uint4*)(kftb + (size_t)jj.y * CH + k0);
            A2.u = *(const uint4*)(kftb + (size_t)jj.z * CH + k0);
            #pragma unroll
            for (int j = 0; j < 4; j++) {
                float2 a = __half22float2(A0.h[j]);
                float2 d = __half22float2(A1.h[j]);
                float2 e = __half22float2(A2.h[j]);
                R.h[j] = __floats2half2_rn(ww.x * a.x + ww.y * d.x + ww.z * e.x,
                                           ww.x * a.y + ww.y * d.y + ww.z * e.y);
            }
            areg[it] = R.u;
        }
    };
    auto stsA = [&](int s) {
        #pragma unroll
        for (int it = 0; it < 4; it++)
            *(uint4*)(smc + s * STAGE_B + (rb + it * 32) * (HS * 2) + qq * 16) = areg[it];
    };
    auto loadAuf = [&](int c, int s) {  // uf chunks: cp.async [k=64][i=128] half tile
        int chb = (c - 4) * 64;
        uint32_t offA = sbase + s * STAGE_B;
        #pragma unroll
        for (int it = 0; it < 4; it++) {
            int idx = tid + it * 256;         // 0..1023
            int row = idx >> 4;               // 0..63 (k)
            int off = idx & 15;               // 16B unit along i
            cp16(offA + row * (RS2H * 2) + off * 16,
                 Xc + (size_t)(chb + row) * NPTS + i0 + off * 8);
        }
        // commit happens in loadB (same group)
    };

    const uint32_t aLane = ((uint32_t)(wy * 64 + lr + ((sel & 1) << 3)) * HS + ((sel >> 1) << 3)) * 2;
    const uint32_t bLane = ((uint32_t)(wx * 32 + lr + ((sel >> 1) << 3)) * HS + ((sel & 1) << 3)) * 2;
    // trans A fragment lanes: mat0=(k0-7,m0-7) mat1=(k0-7,m8-15) mat2=(k8-15,m0-7) mat3=(k8-15,m8-15)
    const uint32_t aLaneT = ((uint32_t)(lr + ((sel >> 1) << 3)) * RS2H + (wy * 64 + ((sel & 1) << 3))) * 2;

    ldgA(0); stsA(0); loadB(0, 0);
    ldgA(1); stsA(1); loadB(1, 1);

    for (int c = 0; c < NC; c++) {
        if (c + 1 < NC) {
            asm volatile("cp.async.wait_group 1;" ::: "memory");
        } else {
            asm volatile("cp.async.wait_group 0;" ::: "memory");
        }
        __syncthreads();

        if (c + 2 < 4) ldgA(c + 2);

        uint32_t sA = sbase + (c & 1) * STAGE_B;
        uint32_t sB = sA + ATILE_B;
        if (c < 4) {
            #pragma unroll
            for (int kk16 = 0; kk16 < 4; kk16++) {
                uint32_t koff = kk16 * 32;
                uint32_t af[4][4], bf[4][2];
                #pragma unroll
                for (int mi = 0; mi < 4; mi++)
                    ldm_x4(af[mi], sA + aLane + mi * (16 * HS * 2) + koff);
                #pragma unroll
                for (int nip = 0; nip < 2; nip++) {
                    uint32_t r[4];
                    ldm_x4(r, sB + bLane + nip * (16 * HS * 2) + koff);
                    bf[2 * nip][0] = r[0]; bf[2 * nip][1] = r[1];
                    bf[2 * nip + 1][0] = r[2]; bf[2 * nip + 1][1] = r[3];
                }
                #pragma unroll
                for (int mi = 0; mi < 4; mi++)
                    #pragma unroll
                    for (int ni = 0; ni < 4; ni++)
                        mma_f16(acc[mi][ni], af[mi], bf[ni]);
            }
        } else {
            #pragma unroll
            for (int kk16 = 0; kk16 < 4; kk16++) {
                uint32_t krowoff = kk16 * 16 * (RS2H * 2);   // k advances along rows
                uint32_t koff = kk16 * 32;                   // B unchanged
                uint32_t af[4][4], bf[4][2];
                #pragma unroll
                for (int mi = 0; mi < 4; mi++)
                    ldm_x4t(af[mi], sA + aLaneT + krowoff + mi * 32);  // m advances along cols (16 halves)
                #pragma unroll
                for (int nip = 0; nip < 2; nip++) {
                    uint32_t r[4];
                    ldm_x4(r, sB + bLane + nip * (16 * HS * 2) + koff);
                    bf[2 * nip][0] = r[0]; bf[2 * nip][1] = r[1];
                    bf[2 * nip + 1][0] = r[2]; bf[2 * nip + 1][1] = r[3];
                }
                #pragma unroll
                for (int mi = 0; mi < 4; mi++)
                    #pragma unroll
                    for (int ni = 0; ni < 4; ni++)
                        mma_f16(acc[mi][ni], af[mi], bf[ni]);
            }
        }
        __syncthreads();
        if (c + 2 < NC) {
            int s = (c + 2) & 1;
            if (c + 2 < 4) { stsA(s); } else { loadAuf(c + 2, s); }
            loadB(c + 2, s);
        }
    }

    #pragma unroll
    for (int mi = 0; mi < 4; mi++) {
        int row0 = i0 + wy * 64 + mi * 16 + g;
        #pragma unroll
        for (int ni = 0; ni < 4; ni++) {
            int col = o0 + wx * 32 + ni * 8 + 2 * c4;
            *(__half2*)(Dg + ((size_t)b * NPTS + row0) * CH + col) =
                __floats2half2_rn(acc[mi][ni][0], acc[mi][ni][1]);
            *(__half2*)(Dg + ((size_t)b * NPTS + row0 + 8) * CH + col) =
                __floats2half2_rn(acc[mi][ni][2], acc[mi][ni][3]);
        }
    }
    #pragma unroll
    for (int ni = 0; ni < 4; ni++) {
        float s0 = 0.f, s1 = 0.f, q0 = 0.f, q1 = 0.f;
        #pragma unroll
        for (int mi = 0; mi < 4; mi++) {
            const float* a = acc[mi][ni];
            s0 += a[0] + a[2]; s1 += a[1] + a[3];
            q0 += a[0] * a[0] + a[2] * a[2];
            q1 += a[1] * a[1] + a[3] * a[3];
        }
        int lc = wx * 32 + ni * 8 + 2 * c4;
        atomicAdd(&ssum[lc], s0); atomicAdd(&ssum[lc + 1], s1);
        atomicAdd(&ssq[lc], q0);  atomicAdd(&ssq[lc + 1], q1);
    }
    __syncthreads();
    if (tid < 128) {
        atomicAdd(&sums[o0 + tid], ssum[tid]);
        atomicAdd(&sqs[o0 + tid], ssq[tid]);
    }
}

// ---------------- GEMM2 (FUSE BN1+ReLU in A-loader) ----------------
template<int KDIM>
__global__ void __launch_bounds__(256, 2) gemm_h(const __half* __restrict__ Ag,
                                                 const __half* __restrict__ Bg,
                                                 __half* __restrict__ Dg,
                                                 float* __restrict__ sums,
                                                 float* __restrict__ sqs) {
    extern __shared__ char smc[];
    const uint32_t sbase = smem_u32(smc);
    float* ssum = (float*)(smc + 2 * STAGE_B);
    float* ssq  = ssum + 128;

    const int tid = threadIdx.x;
    const int wid = tid >> 5, l = tid & 31;
    const int wy = wid >> 2, wx = wid & 3;
    const int g = l >> 2, c4 = l & 3;
    const int lr = l & 7, sel = l >> 3;
    const int b = blockIdx.z;
    const int i0 = blockIdx.x * 128, o0 = blockIdx.y * 128;

    if (tid < 128) { ssum[tid] = 0.f; ssq[tid] = 0.f; }

    const __half* Abase = Ag + ((size_t)b * NPTS + i0) * KDIM;
    const __half* Bbase = Bg + (size_t)o0 * KDIM;

    float acc[4][4][4];
    #pragma unroll
    for (int mi = 0; mi < 4; mi++)
        #pragma unroll
        for (int ni = 0; ni < 4; ni++)
            #pragma unroll
            for (int t = 0; t < 4; t++) acc[mi][ni][t] = 0.f;

    const int rb = tid >> 3, qq = tid & 7;
    const int NC = KDIM / 64;

    uint4 areg[4], screg, shreg;

    auto loadB = [&](int c, int s) {
        int k0 = c * 64;
        uint32_t offB = sbase + s * STAGE_B + ATILE_B;
        const __half* Bb = Bbase + k0;
        #pragma unroll
        for (int it = 0; it < 4; it++) {
            int r = rb + it * 32;
            cp16(offB + r * (HS * 2) + qq * 16, Bb + (size_t)r * KDIM + qq * 8);
        }
        asm volatile("cp.async.commit_group;" ::: "memory");
    };
    auto ldgA = [&](int c) {
        int k0 = c * 64;
        #pragma unroll
        for (int it = 0; it < 4; it++)
            areg[it] = *(const uint4*)(Abase + (size_t)(rb + it * 32) * KDIM + k0 + qq * 8);
        screg = *(const uint4*)(g_sc1h + k0 + qq * 8);
        shreg = *(const uint4*)(g_sh1h + k0 + qq * 8);
    };
    auto stsA = [&](int s) {
        const __half2 z2 = __float2half2_rn(0.f);
        union { uint4 u; __half2 h[4]; } sc, sh;
        sc.u = screg; sh.u = shreg;
        #pragma unroll
        for (int it = 0; it < 4; it++) {
            int r = rb + it * 32;
            union { uint4 u; __half2 h[4]; } v;
            v.u = areg[it];
            #pragma unroll
            for (int j = 0; j < 4; j++)
                v.h[j] = __hmax2(__hfma2(v.h[j], sc.h[j], sh.h[j]), z2);
            *(uint4*)(smc + s * STAGE_B + r * (HS * 2) + qq * 16) = v.u;
        }
    };

    const uint32_t aLane = ((uint32_t)(wy * 64 + lr + ((sel & 1) << 3)) * HS + ((sel >> 1) << 3)) * 2;
    const uint32_t bLane = ((uint32_t)(wx * 32 + lr + ((sel >> 1) << 3)) * HS + ((sel & 1) << 3)) * 2;

    ldgA(0); stsA(0); loadB(0, 0);
    ldgA(1); stsA(1); loadB(1, 1);

    for (int c = 0; c < NC; c++) {
        if (c + 1 < NC) {
            asm volatile("cp.async.wait_group 1;" ::: "memory");
        } else {
            asm volatile("cp.async.wait_group 0;" ::: "memory");
        }
        __syncthreads();

        if (c + 2 < NC) ldgA(c + 2);

        uint32_t sA = sbase + (c & 1) * STAGE_B;
        uint32_t sB = sA + ATILE_B;
        #pragma unroll
        for (int kk16 = 0; kk16 < 4; kk16++) {
            uint32_t koff = kk16 * 32;
            uint32_t af[4][4], bf[4][2];
            #pragma unroll
            for (int mi = 0; mi < 4; mi++)
                ldm_x4(af[mi], sA + aLane + mi * (16 * HS * 2) + koff);
            #pragma unroll
            for (int nip = 0; nip < 2; nip++) {
                uint32_t r[4];
                ldm_x4(r, sB + bLane + nip * (16 * HS * 2) + koff);
                bf[2 * nip][0] = r[0]; bf[2 * nip][1] = r[1];
                bf[2 * nip + 1][0] = r[2]; bf[2 * nip + 1][1] = r[3];
            }
            #pragma unroll
            for (int mi = 0; mi < 4; mi++)
                #pragma unroll
                for (int ni = 0; ni < 4; ni++)
                    mma_f16(acc[mi][ni], af[mi], bf[ni]);
        }
        __syncthreads();
        if (c + 2 < NC) {
            int s = (c + 2) & 1;
            stsA(s);
            loadB(c + 2, s);
        }
    }

    #pragma unroll
    for (int mi = 0; mi < 4; mi++) {
        int row0 = i0 + wy * 64 + mi * 16 + g;
        #pragma unroll
        for (int ni = 0; ni < 4; ni++) {
            int col = o0 + wx * 32 + ni * 8 + 2 * c4;
            *(__half2*)(Dg + ((size_t)b * NPTS + row0) * CH + col) =
                __floats2half2_rn(acc[mi][ni][0], acc[mi][ni][1]);
            *(__half2*)(Dg + ((size_t)b * NPTS + row0 + 8) * CH + col) =
                __floats2half2_rn(acc[mi][ni][2], acc[mi][ni][3]);
        }
    }
    #pragma unroll
    for (int ni = 0; ni < 4; ni++) {
        float s0 = 0.f, s1 = 0.f, q0 = 0.f, q1 = 0.f;
        #pragma unroll
        for (int mi = 0; mi < 4; mi++) {
            const float* a = acc[mi][ni];
            s0 += a[0] + a[2]; s1 += a[1] + a[3];
            q0 += a[0] * a[0] + a[2] * a[2];
            q1 += a[1] * a[1] + a[3] * a[3];
        }
        int lc = wx * 32 + ni * 8 + 2 * c4;
        atomicAdd(&ssum[lc], s0); atomicAdd(&ssum[lc + 1], s1);
        atomicAdd(&ssq[lc], q0);  atomicAdd(&ssq[lc + 1], q1);
    }
    __syncthreads();
    if (tid < 128) {
        atomicAdd(&sums[o0 + tid], ssum[tid]);
        atomicAdd(&sqs[o0 + tid], ssq[tid]);
    }
}

// ---------------- finalize BN params ----------------
__global__ void finalize_kernel(const float* __restrict__ ga, const float* __restrict__ be,
                                const float* __restrict__ sums, const float* __restrict__ sqs,
                                float* __restrict__ scale, float* __restrict__ shift,
                                __half* __restrict__ sch, __half* __restrict__ shh) {
    int o = threadIdx.x;
    float inv = 1.0f / (float)(BB * NPTS);
    float mean = sums[o] * inv;
    float var = sqs[o] * inv - mean * mean;
    float sc = ga[o] * rsqrtf(var + BN_EPS);
    float sh = be[o] - mean * sc;
    scale[o] = sc; shift[o] = sh;
    sch[o] = __float2half_rn(sc);
    shh[o] = __float2half_rn(sh);
}

// ---------------- final: BN2 + ReLU + transpose half(b,i,o) -> f32 (b,o,i) ----------------
__global__ void out_kernel(float* __restrict__ out) {
    __shared__ float tile[32][33];
    int b = blockIdx.z, i0 = blockIdx.x * 32, o0 = blockIdx.y * 32;
    const __half* src = g_Y2h + (size_t)b * NPTS * CH;
    for (int r = threadIdx.y; r < 32; r += 8)
        tile[r][threadIdx.x] = __half2float(src[(size_t)(i0 + r) * CH + o0 + threadIdx.x]);
    __syncthreads();
    float* dst = out + (size_t)b * CH * NPTS;
    for (int r = threadIdx.y; r < 32; r += 8) {
        int o = o0 + r;
        float v = fmaxf(fmaf(tile[threadIdx.x][r], g_scale2[o], g_shift2[o]), 0.f);
        dst[(size_t)o * NPTS + i0 + threadIdx.x] = v;
    }
}

// ---------------- launch ----------------
extern "C" void kernel_launch(void* const* d_in, const int* in_sizes, int n_in,
                              void* d_out, int out_size) {
    const float* unknown = (const float*)d_in[0];
    const float* known   = (const float*)d_in[1];
    const float* uf      = (const float*)d_in[2];
    const float* kf      = (const float*)d_in[3];
    const float* W1      = (const float*)d_in[4];
    const float* g1      = (const float*)d_in[5];
    const float* be1     = (const float*)d_in[6];
    const float* W2      = (const float*)d_in[7];
    const float* g2      = (const float*)d_in[8];
    const float* be2     = (const float*)d_in[9];
    float* out = (float*)d_out;

    cudaFuncSetAttribute(gemm1_f, cudaFuncAttributeMaxDynamicSharedMemorySize, GEMM1_SMEM);
    cudaFuncSetAttribute(gemm_h<CH>, cudaFuncAttributeMaxDynamicSharedMemorySize, GEMM_SMEM);

    __half *pHh, *pY2h, *pW2h, *psc1h, *psh1h, *psc2h, *psh2h;
    float *ps1, *pq1, *ps2, *pq2, *psc2, *psh2, *psc1f, *psh1f;
    cudaGetSymbolAddress((void**)&pHh, g_Hh);
    cudaGetSymbolAddress((void**)&pY2h, g_Y2h);
    cudaGetSymbolAddress((void**)&pW2h, g_W2h);
    cudaGetSymbolAddress((void**)&ps1, g_sum1);
    cudaGetSymbolAddress((void**)&pq1, g_sq1);
    cudaGetSymbolAddress((void**)&ps2, g_sum2);
    cudaGetSymbolAddress((void**)&pq2, g_sq2);
    cudaGetSymbolAddress((void**)&psc2, g_scale2);
    cudaGetSymbolAddress((void**)&psh2, g_shift2);
    cudaGetSymbolAddress((void**)&psc1f, g_scale1_f);
    cudaGetSymbolAddress((void**)&psh1f, g_shift1_f);
    cudaGetSymbolAddress((void**)&psc1h, g_sc1h);
    cudaGetSymbolAddress((void**)&psh1h, g_sh1h);
    cudaGetSymbolAddress((void**)&psc2h, g_sc2h);
    cudaGetSymbolAddress((void**)&psh2h, g_sh2h);

    prep_kernel<<<CH * K1 / 256 + CH * CH / 256 + 1, 256>>>(W1, W2);
    nn_kernel<<<dim3(NPTS / 256, BB), 256>>>(unknown, known);
    kft_kernel<<<dim3(MPTS / 32, CH / 32, BB), dim3(32, 8)>>>(kf);
    cvt_kernel<<<(int)(((size_t)BB * CH * NPTS / 4) / 256), 256>>>(uf);
    gemm1_f<<<dim3(NPTS / 128, CH / 128, BB), 256, GEMM1_SMEM>>>(pHh, ps1, pq1);
    finalize_kernel<<<1, 256>>>(g1, be1, ps1, pq1, psc1f, psh1f, psc1h, psh1h);
    gemm_h<CH><<<dim3(NPTS / 128, CH / 128, BB), 256, GEMM_SMEM>>>(pHh, pW2h, pY2h, ps2, pq2);
    finalize_kernel<<<1, 256>>>(g2, be2, ps2, pq2, psc2, psh2, psc2h, psh2h);
    out_kernel<<<dim3(NPTS / 32, CH / 32, BB), dim3(32, 8)>>>(out);
}

// round 10
// speedup vs baseline: 4.3726x; 1.1213x over previous
#include <cuda_runtime.h>
#include <cuda_fp16.h>
#include <cstdint>

#define BB   16
#define NPTS 4096
#define MPTS 1024
#define CH   256
#define K1   512
#define BN_EPS 1e-5f

// ---------------- scratch ----------------
__device__ __align__(16) __half g_kft[(size_t)BB * MPTS * CH];   // known_feats^T (b,m,c) half
__device__ __align__(16) __half g_Xc[(size_t)BB * CH * NPTS];    // uf (b,c,i) half
__device__ __align__(16) __half g_Hh[(size_t)BB * NPTS * CH];    // conv1 raw out (b,i,o) half
__device__ __align__(16) __half g_Y2h[(size_t)BB * NPTS * CH];   // conv2 raw out (b,i,o) half
__device__ __align__(16) __half g_W1h[CH * K1];
__device__ __align__(16) __half g_W2h[CH * CH];
__device__ int   g_idx3[BB * NPTS * 3];
__device__ float g_w3[BB * NPTS * 3];
__device__ float g_sum1[CH], g_sq1[CH], g_sum2[CH], g_sq2[CH];
__device__ float g_scale2[CH], g_shift2[CH];
__device__ float g_scale1_f[CH], g_shift1_f[CH];
__device__ __align__(16) __half g_sc1h[CH], g_sh1h[CH];
__device__ __align__(16) __half g_sc2h[CH], g_sh2h[CH];

// ---------------- helpers ----------------
__device__ __forceinline__ void cp16(uint32_t saddr, const void* g) {
    asm volatile("cp.async.ca.shared.global [%0], [%1], 16;" :: "r"(saddr), "l"(g));
}
__device__ __forceinline__ uint32_t smem_u32(const void* p) {
    uint32_t a;
    asm("{ .reg .u64 t; cvta.to.shared.u64 t, %1; cvt.u32.u64 %0, t; }" : "=r"(a) : "l"(p));
    return a;
}
__device__ __forceinline__ void ldm_x4(uint32_t* r, uint32_t addr) {
    asm volatile("ldmatrix.sync.aligned.m8n8.x4.shared.b16 {%0,%1,%2,%3}, [%4];"
                 : "=r"(r[0]), "=r"(r[1]), "=r"(r[2]), "=r"(r[3]) : "r"(addr));
}
__device__ __forceinline__ void ldm_x4t(uint32_t* r, uint32_t addr) {
    asm volatile("ldmatrix.sync.aligned.m8n8.x4.trans.shared.b16 {%0,%1,%2,%3}, [%4];"
                 : "=r"(r[0]), "=r"(r[1]), "=r"(r[2]), "=r"(r[3]) : "r"(addr));
}
__device__ __forceinline__ void mma_f16(float* d, const uint32_t* a, const uint32_t* b) {
    asm volatile(
        "mma.sync.aligned.m16n8k16.row.col.f32.f16.f16.f32 "
        "{%0,%1,%2,%3}, {%4,%5,%6,%7}, {%8,%9}, {%0,%1,%2,%3};"
        : "+f"(d[0]), "+f"(d[1]), "+f"(d[2]), "+f"(d[3])
        : "r"(a[0]), "r"(a[1]), "r"(a[2]), "r"(a[3]), "r"(b[0]), "r"(b[1]));
}

// ---------------- prep: weight->half + stats zero ----------------
__global__ void prep_kernel(const float* __restrict__ W1, const float* __restrict__ W2) {
    int blk = blockIdx.x;
    int t = threadIdx.x;
    if (blk < CH * K1 / 256) {
        int i = blk * 256 + t;
        g_W1h[i] = __float2half_rn(W1[i]);
    } else if (blk < CH * K1 / 256 + CH * CH / 256) {
        int i = (blk - CH * K1 / 256) * 256 + t;
        g_W2h[i] = __float2half_rn(W2[i]);
    } else {
        g_sum1[t] = 0.f; g_sq1[t] = 0.f; g_sum2[t] = 0.f; g_sq2[t] = 0.f;
    }
}

// ---------------- elementwise uf f32 -> half ----------------
__global__ void cvt_kernel(const float* __restrict__ uf) {
    size_t q = (size_t)blockIdx.x * 256 + threadIdx.x;
    float4 v = ((const float4*)uf)[q];
    union { __half2 h[2]; uint2 u; } cv;
    cv.h[0] = __floats2half2_rn(v.x, v.y);
    cv.h[1] = __floats2half2_rn(v.z, v.w);
    *(uint2*)(g_Xc + q * 4) = cv.u;
}

// ---------------- 3-NN + weights (score = |k|^2 - 2 u.k, 3 FMA inner loop) ----------------
__global__ void nn_kernel(const float* __restrict__ unknown, const float* __restrict__ known) {
    __shared__ float4 sk[MPTS];
    int b = blockIdx.y;
    const float* kb = known + (size_t)b * MPTS * 3;
    for (int j = threadIdx.x; j < MPTS; j += blockDim.x) {
        float kx = kb[j * 3 + 0], ky = kb[j * 3 + 1], kz = kb[j * 3 + 2];
        sk[j] = make_float4(kx, ky, kz, kx * kx + ky * ky + kz * kz);
    }
    __syncthreads();
    int i = blockIdx.x * blockDim.x + threadIdx.x;
    const float* u = unknown + ((size_t)b * NPTS + i) * 3;
    float ux = u[0], uy = u[1], uz = u[2];
    float ax = -2.f * ux, ay = -2.f * uy, az = -2.f * uz;
    float b0 = 3.4e38f, b1 = 3.4e38f, b2 = 3.4e38f;
    int i0 = 0, i1 = 0, i2 = 0;
    #pragma unroll 4
    for (int j = 0; j < MPTS; j++) {
        float4 k4 = sk[j];
        float s = fmaf(k4.x, ax, fmaf(k4.y, ay, fmaf(k4.z, az, k4.w)));
        if (s < b2) {
            if (s < b1) {
                if (s < b0) { b2 = b1; i2 = i1; b1 = b0; i1 = i0; b0 = s; i0 = j; }
                else        { b2 = b1; i2 = i1; b1 = s;  i1 = j; }
            } else          { b2 = s;  i2 = j; }
        }
    }
    // exact distances for the 3 winners (original formula -> accurate weights)
    float4 k0 = sk[i0], k1 = sk[i1], k2 = sk[i2];
    float d0 = (ux - k0.x) * (ux - k0.x) + (uy - k0.y) * (uy - k0.y) + (uz - k0.z) * (uz - k0.z);
    float d1 = (ux - k1.x) * (ux - k1.x) + (uy - k1.y) * (uy - k1.y) + (uz - k1.z) * (uz - k1.z);
    float d2 = (ux - k2.x) * (ux - k2.x) + (uy - k2.y) * (uy - k2.y) + (uz - k2.z) * (uz - k2.z);
    float r0 = 1.0f / (d0 + 1e-8f), r1 = 1.0f / (d1 + 1e-8f), r2 = 1.0f / (d2 + 1e-8f);
    float inv = 1.0f / (r0 + r1 + r2);
    size_t base = ((size_t)b * NPTS + i) * 3;
    g_idx3[base] = i0; g_idx3[base + 1] = i1; g_idx3[base + 2] = i2;
    g_w3[base] = r0 * inv; g_w3[base + 1] = r1 * inv; g_w3[base + 2] = r2 * inv;
}

// ---------------- transpose known_feats (b,c,m)->(b,m,c) half ----------------
__global__ void kft_kernel(const float* __restrict__ kf) {
    __shared__ float tile[32][33];
    int b = blockIdx.z, c0 = blockIdx.y * 32, j0 = blockIdx.x * 32;
    const float* src = kf + (size_t)b * CH * MPTS;
    for (int r = threadIdx.y; r < 32; r += 8)
        tile[r][threadIdx.x] = src[(size_t)(c0 + r) * MPTS + j0 + threadIdx.x];
    __syncthreads();
    __half* dst = g_kft + (size_t)b * MPTS * CH;
    for (int r = threadIdx.y; r < 32; r += 8)
        dst[(size_t)(j0 + r) * CH + c0 + threadIdx.x] = __float2half_rn(tile[threadIdx.x][r]);
}

// ---------------- shared GEMM geometry ----------------
#define HS      72
#define RS2H    136
#define ATILE_B (128 * HS * 2)
#define STAGE_B (2 * ATILE_B)
#define GEMM_SMEM  (2 * STAGE_B + 1024)
#define GEMM1_SMEM (2 * STAGE_B + 1024 + 4096)

// ---------------- GEMM1: A = [3NN-interp(kft) | uf-trans], B = W1h ----------------
__global__ void __launch_bounds__(256, 2) gemm1_f(__half* __restrict__ Dg,
                                                  float* __restrict__ sums,
                                                  float* __restrict__ sqs) {
    extern __shared__ char smc[];
    const uint32_t sbase = smem_u32(smc);
    float* ssum = (float*)(smc + 2 * STAGE_B);
    float* ssq  = ssum + 128;
    int*   sidx = (int*)(smc + 2 * STAGE_B + 1024);
    float* sw   = (float*)(smc + 2 * STAGE_B + 1024 + 2048);

    const int tid = threadIdx.x;
    const int wid = tid >> 5, l = tid & 31;
    const int wy = wid >> 2, wx = wid & 3;
    const int g = l >> 2, c4 = l & 3;
    const int lr = l & 7, sel = l >> 3;
    const int b = blockIdx.z;
    const int i0 = blockIdx.x * 128, o0 = blockIdx.y * 128;

    if (tid < 128) {
        ssum[tid] = 0.f; ssq[tid] = 0.f;
        size_t base = ((size_t)b * NPTS + i0 + tid) * 3;
        sidx[4 * tid] = g_idx3[base]; sidx[4 * tid + 1] = g_idx3[base + 1];
        sidx[4 * tid + 2] = g_idx3[base + 2];
        sw[4 * tid] = g_w3[base]; sw[4 * tid + 1] = g_w3[base + 1];
        sw[4 * tid + 2] = g_w3[base + 2];
    }
    __syncthreads();

    const __half* Xc = g_Xc + (size_t)b * CH * NPTS;
    const __half* Bbase = g_W1h + (size_t)o0 * K1;
    const __half* kftb = g_kft + (size_t)b * MPTS * CH;

    float acc[4][4][4];
    #pragma unroll
    for (int mi = 0; mi < 4; mi++)
        #pragma unroll
        for (int ni = 0; ni < 4; ni++)
            #pragma unroll
            for (int t = 0; t < 4; t++) acc[mi][ni][t] = 0.f;

    const int rb = tid >> 3, qq = tid & 7;
    const int NC = K1 / 64;

    uint4 areg[4];

    auto loadB = [&](int c, int s) {
        int k0 = c * 64;
        uint32_t offB = sbase + s * STAGE_B + ATILE_B;
        const __half* Bb = Bbase + k0;
        #pragma unroll
        for (int it = 0; it < 4; it++) {
            int r = rb + it * 32;
            cp16(offB + r * (HS * 2) + qq * 16, Bb + (size_t)r * K1 + qq * 8);
        }
        asm volatile("cp.async.commit_group;" ::: "memory");
    };
    auto ldgA = [&](int c) {
        int k0 = c * 64 + qq * 8;
        #pragma unroll
        for (int it = 0; it < 4; it++) {
            int r = rb + it * 32;
            int4 jj = *(const int4*)&sidx[4 * r];
            float4 ww = *(const float4*)&sw[4 * r];
            union { uint4 u; __half2 h[4]; } A0, A1, A2, R;
            A0.u = *(const uint4*)(kftb + (size_t)jj.x * CH + k0);
            A1.u = *(const uint4*)(kftb + (size_t)jj.y * CH + k0);
            A2.u = *(const uint4*)(kftb + (size_t)jj.z * CH + k0);
            #pragma unroll
            for (int j = 0; j < 4; j++) {
                float2 a = __half22float2(A0.h[j]);
                float2 d = __half22float2(A1.h[j]);
                float2 e = __half22float2(A2.h[j]);
                R.h[j] = __floats2half2_rn(ww.x * a.x + ww.y * d.x + ww.z * e.x,
                                           ww.x * a.y + ww.y * d.y + ww.z * e.y);
            }
            areg[it] = R.u;
        }
    };
    auto stsA = [&](int s) {
        #pragma unroll
        for (int it = 0; it < 4; it++)
            *(uint4*)(smc + s * STAGE_B + (rb + it * 32) * (HS * 2) + qq * 16) = areg[it];
    };
    auto loadAuf = [&](int c, int s) {
        int chb = (c - 4) * 64;
        uint32_t offA = sbase + s * STAGE_B;
        #pragma unroll
        for (int it = 0; it < 4; it++) {
            int idx = tid + it * 256;
            int row = idx >> 4;
            int off = idx & 15;
            cp16(offA + row * (RS2H * 2) + off * 16,
                 Xc + (size_t)(chb + row) * NPTS + i0 + off * 8);
        }
    };

    const uint32_t aLane = ((uint32_t)(wy * 64 + lr + ((sel & 1) << 3)) * HS + ((sel >> 1) << 3)) * 2;
    const uint32_t bLane = ((uint32_t)(wx * 32 + lr + ((sel >> 1) << 3)) * HS + ((sel & 1) << 3)) * 2;
    const uint32_t aLaneT = ((uint32_t)(lr + ((sel >> 1) << 3)) * RS2H + (wy * 64 + ((sel & 1) << 3))) * 2;

    ldgA(0); stsA(0); loadB(0, 0);
    ldgA(1); stsA(1); loadB(1, 1);

    for (int c = 0; c < NC; c++) {
        if (c + 1 < NC) {
            asm volatile("cp.async.wait_group 1;" ::: "memory");
        } else {
            asm volatile("cp.async.wait_group 0;" ::: "memory");
        }
        __syncthreads();

        if (c + 2 < 4) ldgA(c + 2);

        uint32_t sA = sbase + (c & 1) * STAGE_B;
        uint32_t sB = sA + ATILE_B;
        if (c < 4) {
            #pragma unroll
            for (int kk16 = 0; kk16 < 4; kk16++) {
                uint32_t koff = kk16 * 32;
                uint32_t af[4][4], bf[4][2];
                #pragma unroll
                for (int mi = 0; mi < 4; mi++)
                    ldm_x4(af[mi], sA + aLane + mi * (16 * HS * 2) + koff);
                #pragma unroll
                for (int nip = 0; nip < 2; nip++) {
                    uint32_t r[4];
                    ldm_x4(r, sB + bLane + nip * (16 * HS * 2) + koff);
                    bf[2 * nip][0] = r[0]; bf[2 * nip][1] = r[1];
                    bf[2 * nip + 1][0] = r[2]; bf[2 * nip + 1][1] = r[3];
                }
                #pragma unroll
                for (int mi = 0; mi < 4; mi++)
                    #pragma unroll
                    for (int ni = 0; ni < 4; ni++)
                        mma_f16(acc[mi][ni], af[mi], bf[ni]);
            }
        } else {
            #pragma unroll
            for (int kk16 = 0; kk16 < 4; kk16++) {
                uint32_t krowoff = kk16 * 16 * (RS2H * 2);
                uint32_t koff = kk16 * 32;
                uint32_t af[4][4], bf[4][2];
                #pragma unroll
                for (int mi = 0; mi < 4; mi++)
                    ldm_x4t(af[mi], sA + aLaneT + krowoff + mi * 32);
                #pragma unroll
                for (int nip = 0; nip < 2; nip++) {
                    uint32_t r[4];
                    ldm_x4(r, sB + bLane + nip * (16 * HS * 2) + koff);
                    bf[2 * nip][0] = r[0]; bf[2 * nip][1] = r[1];
                    bf[2 * nip + 1][0] = r[2]; bf[2 * nip + 1][1] = r[3];
                }
                #pragma unroll
                for (int mi = 0; mi < 4; mi++)
                    #pragma unroll
                    for (int ni = 0; ni < 4; ni++)
                        mma_f16(acc[mi][ni], af[mi], bf[ni]);
            }
        }
        __syncthreads();
        if (c + 2 < NC) {
            int s = (c + 2) & 1;
            if (c + 2 < 4) { stsA(s); } else { loadAuf(c + 2, s); }
            loadB(c + 2, s);
        }
    }

    #pragma unroll
    for (int mi = 0; mi < 4; mi++) {
        int row0 = i0 + wy * 64 + mi * 16 + g;
        #pragma unroll
        for (int ni = 0; ni < 4; ni++) {
            int col = o0 + wx * 32 + ni * 8 + 2 * c4;
            *(__half2*)(Dg + ((size_t)b * NPTS + row0) * CH + col) =
                __floats2half2_rn(acc[mi][ni][0], acc[mi][ni][1]);
            *(__half2*)(Dg + ((size_t)b * NPTS + row0 + 8) * CH + col) =
                __floats2half2_rn(acc[mi][ni][2], acc[mi][ni][3]);
        }
    }
    #pragma unroll
    for (int ni = 0; ni < 4; ni++) {
        float s0 = 0.f, s1 = 0.f, q0 = 0.f, q1 = 0.f;
        #pragma unroll
        for (int mi = 0; mi < 4; mi++) {
            const float* a = acc[mi][ni];
            s0 += a[0] + a[2]; s1 += a[1] + a[3];
            q0 += a[0] * a[0] + a[2] * a[2];
            q1 += a[1] * a[1] + a[3] * a[3];
        }
        int lc = wx * 32 + ni * 8 + 2 * c4;
        atomicAdd(&ssum[lc], s0); atomicAdd(&ssum[lc + 1], s1);
        atomicAdd(&ssq[lc], q0);  atomicAdd(&ssq[lc + 1], q1);
    }
    __syncthreads();
    if (tid < 128) {
        atomicAdd(&sums[o0 + tid], ssum[tid]);
        atomicAdd(&sqs[o0 + tid], ssq[tid]);
    }
}

// ---------------- GEMM2 (FUSE BN1+ReLU in A-loader) ----------------
template<int KDIM>
__global__ void __launch_bounds__(256, 2) gemm_h(const __half* __restrict__ Ag,
                                                 const __half* __restrict__ Bg,
                                                 __half* __restrict__ Dg,
                                                 float* __restrict__ sums,
                                                 float* __restrict__ sqs) {
    extern __shared__ char smc[];
    const uint32_t sbase = smem_u32(smc);
    float* ssum = (float*)(smc + 2 * STAGE_B);
    float* ssq  = ssum + 128;

    const int tid = threadIdx.x;
    const int wid = tid >> 5, l = tid & 31;
    const int wy = wid >> 2, wx = wid & 3;
    const int g = l >> 2, c4 = l & 3;
    const int lr = l & 7, sel = l >> 3;
    const int b = blockIdx.z;
    const int i0 = blockIdx.x * 128, o0 = blockIdx.y * 128;

    if (tid < 128) { ssum[tid] = 0.f; ssq[tid] = 0.f; }

    const __half* Abase = Ag + ((size_t)b * NPTS + i0) * KDIM;
    const __half* Bbase = Bg + (size_t)o0 * KDIM;

    float acc[4][4][4];
    #pragma unroll
    for (int mi = 0; mi < 4; mi++)
        #pragma unroll
        for (int ni = 0; ni < 4; ni++)
            #pragma unroll
            for (int t = 0; t < 4; t++) acc[mi][ni][t] = 0.f;

    const int rb = tid >> 3, qq = tid & 7;
    const int NC = KDIM / 64;

    uint4 areg[4], screg, shreg;

    auto loadB = [&](int c, int s) {
        int k0 = c * 64;
        uint32_t offB = sbase + s * STAGE_B + ATILE_B;
        const __half* Bb = Bbase + k0;
        #pragma unroll
        for (int it = 0; it < 4; it++) {
            int r = rb + it * 32;
            cp16(offB + r * (HS * 2) + qq * 16, Bb + (size_t)r * KDIM + qq * 8);
        }
        asm volatile("cp.async.commit_group;" ::: "memory");
    };
    auto ldgA = [&](int c) {
        int k0 = c * 64;
        #pragma unroll
        for (int it = 0; it < 4; it++)
            areg[it] = *(const uint4*)(Abase + (size_t)(rb + it * 32) * KDIM + k0 + qq * 8);
        screg = *(const uint4*)(g_sc1h + k0 + qq * 8);
        shreg = *(const uint4*)(g_sh1h + k0 + qq * 8);
    };
    auto stsA = [&](int s) {
        const __half2 z2 = __float2half2_rn(0.f);
        union { uint4 u; __half2 h[4]; } sc, sh;
        sc.u = screg; sh.u = shreg;
        #pragma unroll
        for (int it = 0; it < 4; it++) {
            int r = rb + it * 32;
            union { uint4 u; __half2 h[4]; } v;
            v.u = areg[it];
            #pragma unroll
            for (int j = 0; j < 4; j++)
                v.h[j] = __hmax2(__hfma2(v.h[j], sc.h[j], sh.h[j]), z2);
            *(uint4*)(smc + s * STAGE_B + r * (HS * 2) + qq * 16) = v.u;
        }
    };

    const uint32_t aLane = ((uint32_t)(wy * 64 + lr + ((sel & 1) << 3)) * HS + ((sel >> 1) << 3)) * 2;
    const uint32_t bLane = ((uint32_t)(wx * 32 + lr + ((sel >> 1) << 3)) * HS + ((sel & 1) << 3)) * 2;

    ldgA(0); stsA(0); loadB(0, 0);
    ldgA(1); stsA(1); loadB(1, 1);

    for (int c = 0; c < NC; c++) {
        if (c + 1 < NC) {
            asm volatile("cp.async.wait_group 1;" ::: "memory");
        } else {
            asm volatile("cp.async.wait_group 0;" ::: "memory");
        }
        __syncthreads();

        if (c + 2 < NC) ldgA(c + 2);

        uint32_t sA = sbase + (c & 1) * STAGE_B;
        uint32_t sB = sA + ATILE_B;
        #pragma unroll
        for (int kk16 = 0; kk16 < 4; kk16++) {
            uint32_t koff = kk16 * 32;
            uint32_t af[4][4], bf[4][2];
            #pragma unroll
            for (int mi = 0; mi < 4; mi++)
                ldm_x4(af[mi], sA + aLane + mi * (16 * HS * 2) + koff);
            #pragma unroll
            for (int nip = 0; nip < 2; nip++) {
                uint32_t r[4];
                ldm_x4(r, sB + bLane + nip * (16 * HS * 2) + koff);
                bf[2 * nip][0] = r[0]; bf[2 * nip][1] = r[1];
                bf[2 * nip + 1][0] = r[2]; bf[2 * nip + 1][1] = r[3];
            }
            #pragma unroll
            for (int mi = 0; mi < 4; mi++)
                #pragma unroll
                for (int ni = 0; ni < 4; ni++)
                    mma_f16(acc[mi][ni], af[mi], bf[ni]);
        }
        __syncthreads();
        if (c + 2 < NC) {
            int s = (c + 2) & 1;
            stsA(s);
            loadB(c + 2, s);
        }
    }

    #pragma unroll
    for (int mi = 0; mi < 4; mi++) {
        int row0 = i0 + wy * 64 + mi * 16 + g;
        #pragma unroll
        for (int ni = 0; ni < 4; ni++) {
            int col = o0 + wx * 32 + ni * 8 + 2 * c4;
            *(__half2*)(Dg + ((size_t)b * NPTS + row0) * CH + col) =
                __floats2half2_rn(acc[mi][ni][0], acc[mi][ni][1]);
            *(__half2*)(Dg + ((size_t)b * NPTS + row0 + 8) * CH + col) =
                __floats2half2_rn(acc[mi][ni][2], acc[mi][ni][3]);
        }
    }
    #pragma unroll
    for (int ni = 0; ni < 4; ni++) {
        float s0 = 0.f, s1 = 0.f, q0 = 0.f, q1 = 0.f;
        #pragma unroll
        for (int mi = 0; mi < 4; mi++) {
            const float* a = acc[mi][ni];
            s0 += a[0] + a[2]; s1 += a[1] + a[3];
            q0 += a[0] * a[0] + a[2] * a[2];
            q1 += a[1] * a[1] + a[3] * a[3];
        }
        int lc = wx * 32 + ni * 8 + 2 * c4;
        atomicAdd(&ssum[lc], s0); atomicAdd(&ssum[lc + 1], s1);
        atomicAdd(&ssq[lc], q0);  atomicAdd(&ssq[lc + 1], q1);
    }
    __syncthreads();
    if (tid < 128) {
        atomicAdd(&sums[o0 + tid], ssum[tid]);
        atomicAdd(&sqs[o0 + tid], ssq[tid]);
    }
}

// ---------------- finalize BN params ----------------
__global__ void finalize_kernel(const float* __restrict__ ga, const float* __restrict__ be,
                                const float* __restrict__ sums, const float* __restrict__ sqs,
                                float* __restrict__ scale, float* __restrict__ shift,
                                __half* __restrict__ sch, __half* __restrict__ shh) {
    int o = threadIdx.x;
    float inv = 1.0f / (float)(BB * NPTS);
    float mean = sums[o] * inv;
    float var = sqs[o] * inv - mean * mean;
    float sc = ga[o] * rsqrtf(var + BN_EPS);
    float sh = be[o] - mean * sc;
    scale[o] = sc; shift[o] = sh;
    sch[o] = __float2half_rn(sc);
    shh[o] = __float2half_rn(sh);
}

// ---------------- final: BN2 + ReLU + transpose half(b,i,o) -> f32 (b,o,i) ----------------
__global__ void out_kernel(float* __restrict__ out) {
    __shared__ float tile[32][33];
    int b = blockIdx.z, i0 = blockIdx.x * 32, o0 = blockIdx.y * 32;
    const __half* src = g_Y2h + (size_t)b * NPTS * CH;
    for (int r = threadIdx.y; r < 32; r += 8)
        tile[r][threadIdx.x] = __half2float(src[(size_t)(i0 + r) * CH + o0 + threadIdx.x]);
    __syncthreads();
    float* dst = out + (size_t)b * CH * NPTS;
    for (int r = threadIdx.y; r < 32; r += 8) {
        int o = o0 + r;
        float v = fmaxf(fmaf(tile[threadIdx.x][r], g_scale2[o], g_shift2[o]), 0.f);
        dst[(size_t)o * NPTS + i0 + threadIdx.x] = v;
    }
}

// ---------------- launch ----------------
extern "C" void kernel_launch(void* const* d_in, const int* in_sizes, int n_in,
                              void* d_out, int out_size) {
    const float* unknown = (const float*)d_in[0];
    const float* known   = (const float*)d_in[1];
    const float* uf      = (const float*)d_in[2];
    const float* kf      = (const float*)d_in[3];
    const float* W1      = (const float*)d_in[4];
    const float* g1      = (const float*)d_in[5];
    const float* be1     = (const float*)d_in[6];
    const float* W2      = (const float*)d_in[7];
    const float* g2      = (const float*)d_in[8];
    const float* be2     = (const float*)d_in[9];
    float* out = (float*)d_out;

    static cudaStream_t s1 = nullptr, s2 = nullptr;
    static cudaEvent_t ev0 = nullptr, ev1 = nullptr, ev2 = nullptr;
    if (!s1) {
        cudaStreamCreateWithFlags(&s1, cudaStreamNonBlocking);
        cudaStreamCreateWithFlags(&s2, cudaStreamNonBlocking);
        cudaEventCreateWithFlags(&ev0, cudaEventDisableTiming);
        cudaEventCreateWithFlags(&ev1, cudaEventDisableTiming);
        cudaEventCreateWithFlags(&ev2, cudaEventDisableTiming);
        cudaFuncSetAttribute(gemm1_f, cudaFuncAttributeMaxDynamicSharedMemorySize, GEMM1_SMEM);
        cudaFuncSetAttribute(gemm_h<CH>, cudaFuncAttributeMaxDynamicSharedMemorySize, GEMM_SMEM);
    }

    __half *pHh, *pY2h, *pW2h, *psc1h, *psh1h, *psc2h, *psh2h;
    float *ps1, *pq1, *ps2, *pq2, *psc2, *psh2, *psc1f, *psh1f;
    cudaGetSymbolAddress((void**)&pHh, g_Hh);
    cudaGetSymbolAddress((void**)&pY2h, g_Y2h);
    cudaGetSymbolAddress((void**)&pW2h, g_W2h);
    cudaGetSymbolAddress((void**)&ps1, g_sum1);
    cudaGetSymbolAddress((void**)&pq1, g_sq1);
    cudaGetSymbolAddress((void**)&ps2, g_sum2);
    cudaGetSymbolAddress((void**)&pq2, g_sq2);
    cudaGetSymbolAddress((void**)&psc2, g_scale2);
    cudaGetSymbolAddress((void**)&psh2, g_shift2);
    cudaGetSymbolAddress((void**)&psc1f, g_scale1_f);
    cudaGetSymbolAddress((void**)&psh1f, g_shift1_f);
    cudaGetSymbolAddress((void**)&psc1h, g_sc1h);
    cudaGetSymbolAddress((void**)&psh1h, g_sh1h);
    cudaGetSymbolAddress((void**)&psc2h, g_sc2h);
    cudaGetSymbolAddress((void**)&psh2h, g_sh2h);

    // fork: prep-phase kernels are mutually independent
    cudaEventRecord(ev0, 0);
    cudaStreamWaitEvent(s1, ev0, 0);
    cudaStreamWaitEvent(s2, ev0, 0);

    nn_kernel<<<dim3(NPTS / 256, BB), 256>>>(unknown, known);                       // main
    kft_kernel<<<dim3(MPTS / 32, CH / 32, BB), dim3(32, 8), 0, s1>>>(kf);           // s1
    prep_kernel<<<CH * K1 / 256 + CH * CH / 256 + 1, 256, 0, s2>>>(W1, W2);         // s2
    cvt_kernel<<<(int)(((size_t)BB * CH * NPTS / 4) / 256), 256, 0, s2>>>(uf);      // s2

    // join before gemm1
    cudaEventRecord(ev1, s1);
    cudaEventRecord(ev2, s2);
    cudaStreamWaitEvent(0, ev1, 0);
    cudaStreamWaitEvent(0, ev2, 0);

    gemm1_f<<<dim3(NPTS / 128, CH / 128, BB), 256, GEMM1_SMEM>>>(pHh, ps1, pq1);
    finalize_kernel<<<1, 256>>>(g1, be1, ps1, pq1, psc1f, psh1f, psc1h, psh1h);
    gemm_h<CH><<<dim3(NPTS / 128, CH / 128, BB), 256, GEMM_SMEM>>>(pHh, pW2h, pY2h, ps2, pq2);
    finalize_kernel<<<1, 256>>>(g2, be2, ps2, pq2, psc2, psh2, psc2h, psh2h);
    out_kernel<<<dim3(NPTS / 32, CH / 32, BB), dim3(32, 8)>>>(out);
}